// round 5
// baseline (speedup 1.0000x reference)
#include <cuda_runtime.h>
#include <math.h>
#include <stdint.h>

// Problem constants
#define Bq   2
#define Sq   2048
#define DM   1024
#define Hh   16
#define HD   64
#define MEMN 1000
#define KTOT 10

// ---------------- device scratch ----------------
__device__ float g_q[Bq * Hh * Sq * HD];
__device__ float g_k[Bq * Hh * Sq * HD];
__device__ float g_v[Bq * Hh * Sq * HD];
__device__ float g_att[Bq * Sq * DM];
__device__ float g_ret[Bq * KTOT * DM];
__device__ float g_sims[Bq * MEMN];
__device__ float g_wt[4 * DM * DM];    // transposed weights [N][K] x4

// ---------------- helpers ----------------
__device__ __forceinline__ uint32_t smem_u32(const void* p) {
    uint32_t a;
    asm("{ .reg .u64 t; cvta.to.shared.u64 t, %1; cvt.u32.u64 %0, t; }" : "=r"(a) : "l"(p));
    return a;
}
__device__ __forceinline__ float cf_tf32(float x) {
    uint32_t u;
    asm("cvt.rna.tf32.f32 %0, %1;" : "=r"(u) : "f"(x));
    return __uint_as_float(u);
}
__device__ __forceinline__ void mma8(float* c, const uint32_t* a, const uint32_t* b) {
    asm("mma.sync.aligned.m16n8k8.row.col.f32.tf32.tf32.f32 "
        "{%0,%1,%2,%3},{%4,%5,%6,%7},{%8,%9},{%0,%1,%2,%3};"
        : "+f"(c[0]), "+f"(c[1]), "+f"(c[2]), "+f"(c[3])
        : "r"(a[0]), "r"(a[1]), "r"(a[2]), "r"(a[3]), "r"(b[0]), "r"(b[1]));
}
__device__ __forceinline__ uint64_t pk2(float a, float b) {
    uint64_t r; asm("mov.b64 %0,{%1,%2};" : "=l"(r) : "f"(a), "f"(b)); return r;
}
__device__ __forceinline__ void upk2(float& a, float& b, uint64_t v) {
    asm("mov.b64 {%0,%1},%2;" : "=f"(a), "=f"(b) : "l"(v));
}
__device__ __forceinline__ void fma2(uint64_t& d, uint64_t a, uint64_t b) {
    asm("fma.rn.f32x2 %0,%1,%2,%0;" : "+l"(d) : "l"(a), "l"(b));
}
__device__ __forceinline__ void mul2(uint64_t& d, uint64_t a) {
    asm("mul.rn.f32x2 %0,%0,%1;" : "+l"(d) : "l"(a));
}
__device__ __forceinline__ void cpa16(uint32_t d, const void* g) {
    asm volatile("cp.async.cg.shared.global [%0], [%1], 16;" :: "r"(d), "l"(g) : "memory");
}
#define CP_COMMIT() asm volatile("cp.async.commit_group;" ::: "memory")

// ---------------- weight transpose: WT[z][n][k] = W_z[k][n] ----------------
__global__ __launch_bounds__(256) void transpose_w(const float* __restrict__ W0,
                                                   const float* __restrict__ W1,
                                                   const float* __restrict__ W2,
                                                   const float* __restrict__ W3,
                                                   float* __restrict__ WT)
{
    __shared__ float t[32][33];
    int z = blockIdx.z;
    const float* W = (z == 0) ? W0 : (z == 1) ? W1 : (z == 2) ? W2 : W3;
    float* D = WT + (size_t)z * DM * DM;
    int x = blockIdx.x * 32, y = blockIdx.y * 32;
    int tx = threadIdx.x & 31, ty = threadIdx.x >> 5;
    for (int r = ty; r < 32; r += 8)
        t[r][tx] = W[(size_t)(y + r) * DM + x + tx];
    __syncthreads();
    for (int r = ty; r < 32; r += 8)
        D[(size_t)(x + r) * DM + y + tx] = t[tx][r];
}

// ---------------- cp.async-pipelined tf32 mma.sync GEMM -------------------
#define GP      20
#define STGF    (128 * GP * 2)
#define NSTAGE  3
#define NIT     (DM / 16)
#define GSMEM_BYTES (NSTAGE * STGF * 4)

__global__ void __launch_bounds__(256, 2) gemm_cp(const float* __restrict__ A,
                                                  const float* __restrict__ WT,
                                                  float* __restrict__ C,
                                                  int headwrite)
{
    extern __shared__ float dsm[];
    uint32_t sbase = smem_u32(dsm);

    int tid = threadIdx.x, lane = tid & 31, wid = tid >> 5;
    int wm = wid & 3, wn = wid >> 2;
    int m0 = blockIdx.y * 128, n0 = blockIdx.x * 128;
    int r = lane >> 2, c = lane & 3;

    int srow = tid >> 1, shalf = tid & 1;
    const float* gA = A  + (size_t)(m0 + srow) * DM + shalf * 8;
    const float* gB = WT + (size_t)(n0 + srow) * DM + shalf * 8;
    uint32_t dA = sbase + (uint32_t)(srow * GP + shalf * 8) * 4u;
    uint32_t dB = dA + (uint32_t)(128 * GP) * 4u;

    float acc[2][8][4];
#pragma unroll
    for (int i = 0; i < 2; i++)
#pragma unroll
        for (int j = 0; j < 8; j++)
#pragma unroll
            for (int t = 0; t < 4; t++) acc[i][j][t] = 0.f;

#pragma unroll
    for (int s = 0; s < NSTAGE - 1; s++) {
        uint32_t so = (uint32_t)(s * STGF) * 4u;
        cpa16(dA + so,      gA + s * 16);
        cpa16(dA + so + 16, gA + s * 16 + 4);
        cpa16(dB + so,      gB + s * 16);
        cpa16(dB + so + 16, gB + s * 16 + 4);
        CP_COMMIT();
    }

    for (int it = 0; it < NIT; ++it) {
        if (it + NSTAGE - 1 < NIT) {
            int s = it + NSTAGE - 1;
            uint32_t so = (uint32_t)((s % NSTAGE) * STGF) * 4u;
            cpa16(dA + so,      gA + s * 16);
            cpa16(dA + so + 16, gA + s * 16 + 4);
            cpa16(dB + so,      gB + s * 16);
            cpa16(dB + so + 16, gB + s * 16 + 4);
            CP_COMMIT();
        }
        if (it <= NIT - 3)      asm volatile("cp.async.wait_group 2;" ::: "memory");
        else if (it == NIT - 2) asm volatile("cp.async.wait_group 1;" ::: "memory");
        else                    asm volatile("cp.async.wait_group 0;" ::: "memory");
        __syncthreads();

        const float* As = dsm + (it % NSTAGE) * STGF;
        const float* Bs = As + 128 * GP;

#pragma unroll
        for (int ks = 0; ks < 16; ks += 8) {
            uint32_t af[2][4];
#pragma unroll
            for (int i = 0; i < 2; i++) {
                int row = wm * 32 + i * 16 + r;
                af[i][0] = __float_as_uint(cf_tf32(As[row * GP + ks + c]));
                af[i][1] = __float_as_uint(cf_tf32(As[(row + 8) * GP + ks + c]));
                af[i][2] = __float_as_uint(cf_tf32(As[row * GP + ks + c + 4]));
                af[i][3] = __float_as_uint(cf_tf32(As[(row + 8) * GP + ks + c + 4]));
            }
            uint32_t bf[8][2];
#pragma unroll
            for (int j = 0; j < 8; j++) {
                int nr = wn * 64 + j * 8 + r;
                bf[j][0] = __float_as_uint(cf_tf32(Bs[nr * GP + ks + c]));
                bf[j][1] = __float_as_uint(cf_tf32(Bs[nr * GP + ks + c + 4]));
            }
#pragma unroll
            for (int i = 0; i < 2; i++)
#pragma unroll
                for (int j = 0; j < 8; j++) mma8(acc[i][j], af[i], bf[j]);
        }
        __syncthreads();
    }

    int c2 = (lane & 3) * 2;
#pragma unroll
    for (int i = 0; i < 2; i++) {
#pragma unroll
        for (int j = 0; j < 8; j++) {
            int row0 = m0 + wm * 32 + i * 16 + r;
            int col  = n0 + wn * 64 + j * 8 + c2;
            float2 lo = make_float2(acc[i][j][0], acc[i][j][1]);
            float2 hi = make_float2(acc[i][j][2], acc[i][j][3]);
            if (headwrite) {
                int b = row0 >> 11, h = col >> 6, hd = col & 63;
                int s0 = row0 & 2047;
                float* base = C + (((size_t)(b * Hh + h)) * Sq) * HD + hd;
                *(float2*)(base + (size_t)s0 * HD)       = lo;
                *(float2*)(base + (size_t)(s0 + 8) * HD) = hi;
            } else {
                *(float2*)&C[(size_t)row0 * DM + col]       = lo;
                *(float2*)&C[(size_t)(row0 + 8) * DM + col] = hi;
            }
        }
    }
}

// ---------------- retrieval: sims (warp per event) ------------------------
__global__ __launch_bounds__(256) void retrieve_sims(const float* __restrict__ kbuf,
                                                     const float* __restrict__ events,
                                                     float* __restrict__ sims)
{
    int b = blockIdx.y;
    int tid = threadIdx.x;
    int lane = tid & 31, wid = tid >> 5;
    __shared__ float qs[DM];
    __shared__ float qn_s;

    for (int d = tid; d < DM; d += 256) {
        int h = d >> 6, hd = d & 63;
        qs[d] = kbuf[(((size_t)(b * Hh + h)) * Sq + (Sq - 1)) * HD + hd];
    }
    __syncthreads();
    if (wid == 0) {
        float ps = 0.f;
        for (int d = lane * 4; d < DM; d += 128) {
            float4 t = *(const float4*)&qs[d];
            ps += t.x * t.x + t.y * t.y + t.z * t.z + t.w * t.w;
        }
#pragma unroll
        for (int off = 16; off > 0; off >>= 1) ps += __shfl_down_sync(0xffffffffu, ps, off);
        if (lane == 0) qn_s = sqrtf(ps) + 1e-8f;
    }
    __syncthreads();
    float qnorm = qn_s;

    int e = blockIdx.x * 8 + wid;
    if (e >= MEMN) return;
    const float* ep = events + (size_t)e * DM;
    float dot = 0.f, nn = 0.f;
    for (int d = lane * 4; d < DM; d += 128) {
        float4 ev = *(const float4*)(ep + d);
        float4 qv = *(const float4*)&qs[d];
        dot += qv.x * ev.x + qv.y * ev.y + qv.z * ev.z + qv.w * ev.w;
        nn  += ev.x * ev.x + ev.y * ev.y + ev.z * ev.z + ev.w * ev.w;
    }
#pragma unroll
    for (int off = 16; off > 0; off >>= 1) {
        dot += __shfl_down_sync(0xffffffffu, dot, off);
        nn  += __shfl_down_sync(0xffffffffu, nn, off);
    }
    if (lane == 0) sims[b * MEMN + e] = dot / (qnorm * (sqrtf(nn) + 1e-8f));
}

// ---------------- retrieval: parallel top-k + gather -----------------------
__global__ __launch_bounds__(256) void topk_gather(const float* __restrict__ sims,
                                                   const float* __restrict__ events,
                                                   float* __restrict__ ret)
{
    int b = blockIdx.x;
    int tid = threadIdx.x;
    int lane = tid & 31, wid = tid >> 5;
    __shared__ float sv[MEMN];
    __shared__ float wmax[8];
    __shared__ int   widx[8];
    __shared__ int   tidx[KTOT];

    for (int e = tid; e < MEMN; e += 256) sv[e] = sims[b * MEMN + e];
    __syncthreads();

    for (int kk = 0; kk < KTOT; kk++) {
        float bm = -1e30f; int bi = MEMN;
        for (int e = tid; e < MEMN; e += 256) {
            float v = sv[e];
            if (v > bm || (v == bm && e < bi)) { bm = v; bi = e; }
        }
#pragma unroll
        for (int off = 16; off > 0; off >>= 1) {
            float om = __shfl_down_sync(0xffffffffu, bm, off);
            int   oi = __shfl_down_sync(0xffffffffu, bi, off);
            if (om > bm || (om == bm && oi < bi)) { bm = om; bi = oi; }
        }
        if (lane == 0) { wmax[wid] = bm; widx[wid] = bi; }
        __syncthreads();
        if (tid == 0) {
            float gm = wmax[0]; int gi = widx[0];
            for (int w = 1; w < 8; w++) {
                if (wmax[w] > gm || (wmax[w] == gm && widx[w] < gi)) { gm = wmax[w]; gi = widx[w]; }
            }
            tidx[kk] = gi;
            sv[gi] = -1e30f;
        }
        __syncthreads();
    }

    for (int kk = 0; kk < KTOT; kk++) {
        int src = tidx[kk];
        for (int d = tid; d < DM; d += 256)
            ret[((size_t)b * KTOT + kk) * DM + d] = events[(size_t)src * DM + d];
    }
}

// ---------------- flash attention v2: tensor-core QK^T, scalar PV ----------
// CTA: 256 threads (8 warps), 128 query rows, key tiles of 64.
// Tile 0 = [10 memory tokens | first 54 keys]; tile t>=1 keys j0=t*64-10.
// SMEM floats: SQ(Q then P) 128*68 | Ks 64*68 | Vs 64*68 | mk 64 | rowc 128
#define FST    68
#define OFF_SQ 0
#define OFF_KS (128 * FST)
#define OFF_VS (OFF_KS + 64 * FST)
#define OFF_MK (OFF_VS + 64 * FST)
#define OFF_RC (OFF_MK + 64)
#define FSMEM_FLOATS (OFF_RC + 128)
#define FSMEM_BYTES  (FSMEM_FLOATS * 4)

__global__ void __launch_bounds__(256, 1) flash_mma(const float* __restrict__ amask,
                                                    const float* __restrict__ qbuf,
                                                    const float* __restrict__ kbuf,
                                                    const float* __restrict__ vbuf,
                                                    const float* __restrict__ ret,
                                                    float* __restrict__ att)
{
    extern __shared__ float fsm[];
    float* SQ = fsm + OFF_SQ;     // Q (tf32) then P
    float* Ks = fsm + OFF_KS;     // K tile (tf32)
    float* Vs = fsm + OFF_VS;     // V tile (fp32)
    float* mk = fsm + OFF_MK;
    float* rowc = fsm + OFF_RC;   // per-row corr (per tile), then l (at end)

    int qt = gridDim.x - 1 - blockIdx.x;   // heavy tiles first
    int h = blockIdx.y, b = blockIdx.z;
    int tid = threadIdx.x;
    int lane = tid & 31, w = tid >> 5;
    int r = lane >> 2, cc = lane & 3;
    int i0 = qt * 128;
    const float scale = 0.125f;
    float slope = exp2f(-0.5f * (float)(h + 1));

    const float* qbase = qbuf + ((size_t)(b * Hh + h)) * Sq * HD;
    const float* kbase = kbuf + ((size_t)(b * Hh + h)) * Sq * HD;
    const float* vbase = vbuf + ((size_t)(b * Hh + h)) * Sq * HD;

    // ---- stage Q (tf32) ----
    {
        int row = tid >> 1, h32 = (tid & 1) * 32;
        const float* qp = qbase + (size_t)(i0 + row) * HD + h32;
        float* dst = SQ + row * FST + h32;
#pragma unroll
        for (int i = 0; i < 8; i++) {
            float4 t = *(const float4*)(qp + i * 4);
            dst[i * 4]     = cf_tf32(t.x);
            dst[i * 4 + 1] = cf_tf32(t.y);
            dst[i * 4 + 2] = cf_tf32(t.z);
            dst[i * 4 + 3] = cf_tf32(t.w);
        }
    }
    __syncthreads();

    // ---- A fragments (Q) once per CTA ----
    int row_lo = w * 16 + r, row_hi = row_lo + 8;
    int ig_lo = i0 + row_lo, ig_hi = i0 + row_hi;
    uint32_t afr[8][4];
#pragma unroll
    for (int ks = 0; ks < 8; ks++) {
        afr[ks][0] = __float_as_uint(SQ[row_lo * FST + ks * 8 + cc]);
        afr[ks][1] = __float_as_uint(SQ[row_hi * FST + ks * 8 + cc]);
        afr[ks][2] = __float_as_uint(SQ[row_lo * FST + ks * 8 + cc + 4]);
        afr[ks][3] = __float_as_uint(SQ[row_hi * FST + ks * 8 + cc + 4]);
    }

    // PV mapping: 2 threads per row
    int prow = tid >> 1, phalf = (tid & 1) * 32;
    uint64_t acc2[16];
#pragma unroll
    for (int i = 0; i < 16; i++) acc2[i] = 0ull;

    float m_lo = -1e30f, m_hi = -1e30f, l_lo = 0.f, l_hi = 0.f;

    int ntiles = 2 * qt + 3;
    for (int t = 0; t < ntiles; ++t) {
        int j0 = t * 64 - 10;
        // ---- stage K (tf32) + V (fp32) tiles ----
        {
            int kk = tid >> 2, part = (tid & 3) * 16;
            const float *kp, *vp;
            if (t == 0 && kk < KTOT) {
                kp = ret + ((size_t)b * KTOT + kk) * DM + h * HD + part;
                vp = kp;
            } else {
                int jg = j0 + kk;
                if (jg > Sq - 1) jg = Sq - 1;
                kp = kbase + (size_t)jg * HD + part;
                vp = vbase + (size_t)jg * HD + part;
            }
            float* dk = Ks + kk * FST + part;
            float* dv = Vs + kk * FST + part;
#pragma unroll
            for (int i = 0; i < 4; i++) {
                float4 tk = *(const float4*)(kp + i * 4);
                float4 tv = *(const float4*)(vp + i * 4);
                dk[i * 4]     = cf_tf32(tk.x);
                dk[i * 4 + 1] = cf_tf32(tk.y);
                dk[i * 4 + 2] = cf_tf32(tk.z);
                dk[i * 4 + 3] = cf_tf32(tk.w);
                *(float4*)(dv + i * 4) = tv;
            }
            if (tid < 64) {
                int jg = j0 + tid;
                if (jg < 0) jg = 0;
                if (jg > Sq - 1) jg = Sq - 1;
                mk[tid] = (t == 0 && tid < KTOT) ? 1.0f : amask[b * Sq + jg];
            }
        }
        __syncthreads();

        // ---- S = Q K^T via mma.sync ----
        float sc[8][4];
#pragma unroll
        for (int f = 0; f < 8; f++)
#pragma unroll
            for (int e = 0; e < 4; e++) sc[f][e] = 0.f;
#pragma unroll
        for (int ks = 0; ks < 8; ks++) {
#pragma unroll
            for (int f = 0; f < 8; f++) {
                uint32_t bb[2];
                bb[0] = __float_as_uint(Ks[(f * 8 + r) * FST + ks * 8 + cc]);
                bb[1] = __float_as_uint(Ks[(f * 8 + r) * FST + ks * 8 + cc + 4]);
                mma8(sc[f], afr[ks], bb);
            }
        }

        // ---- bias + causal + mask, track tile max ----
        float tmax_lo = m_lo, tmax_hi = m_hi;
#pragma unroll
        for (int f = 0; f < 8; f++) {
            int col0 = f * 8 + 2 * cc;
            int col1 = col0 + 1;
            int jg0 = j0 + col0, jg1 = j0 + col1;
            bool mem0 = (t == 0) && (col0 < KTOT);
            bool mem1 = (t == 0) && (col1 < KTOT);
            float pen0 = (1.0f - mk[col0]) * (-1e9f);
            float pen1 = (1.0f - mk[col1]) * (-1e9f);
            float s;
            s = sc[f][0] * scale + (mem0 ? 0.f : slope * (float)(ig_lo - jg0) + pen0);
            if (!mem0 && jg0 > ig_lo) s = -1e30f;
            sc[f][0] = s; tmax_lo = fmaxf(tmax_lo, s);
            s = sc[f][1] * scale + (mem1 ? 0.f : slope * (float)(ig_lo - jg1) + pen1);
            if (!mem1 && jg1 > ig_lo) s = -1e30f;
            sc[f][1] = s; tmax_lo = fmaxf(tmax_lo, s);
            s = sc[f][2] * scale + (mem0 ? 0.f : slope * (float)(ig_hi - jg0) + pen0);
            if (!mem0 && jg0 > ig_hi) s = -1e30f;
            sc[f][2] = s; tmax_hi = fmaxf(tmax_hi, s);
            s = sc[f][3] * scale + (mem1 ? 0.f : slope * (float)(ig_hi - jg1) + pen1);
            if (!mem1 && jg1 > ig_hi) s = -1e30f;
            sc[f][3] = s; tmax_hi = fmaxf(tmax_hi, s);
        }
        // quad reduce max over the 4 lanes sharing each row
        tmax_lo = fmaxf(tmax_lo, __shfl_xor_sync(0xffffffffu, tmax_lo, 1));
        tmax_lo = fmaxf(tmax_lo, __shfl_xor_sync(0xffffffffu, tmax_lo, 2));
        tmax_hi = fmaxf(tmax_hi, __shfl_xor_sync(0xffffffffu, tmax_hi, 1));
        tmax_hi = fmaxf(tmax_hi, __shfl_xor_sync(0xffffffffu, tmax_hi, 2));

        float corr_lo = __expf(m_lo - tmax_lo);
        float corr_hi = __expf(m_hi - tmax_hi);
        l_lo *= corr_lo; l_hi *= corr_hi;
        m_lo = tmax_lo;  m_hi = tmax_hi;

        float sl = 0.f, sh = 0.f;
#pragma unroll
        for (int f = 0; f < 8; f++) {
            sc[f][0] = __expf(sc[f][0] - m_lo); sl += sc[f][0];
            sc[f][1] = __expf(sc[f][1] - m_lo); sl += sc[f][1];
            sc[f][2] = __expf(sc[f][2] - m_hi); sh += sc[f][2];
            sc[f][3] = __expf(sc[f][3] - m_hi); sh += sc[f][3];
        }
        sl += __shfl_xor_sync(0xffffffffu, sl, 1);
        sl += __shfl_xor_sync(0xffffffffu, sl, 2);
        sh += __shfl_xor_sync(0xffffffffu, sh, 1);
        sh += __shfl_xor_sync(0xffffffffu, sh, 2);
        l_lo += sl; l_hi += sh;

        // write P + per-row corr
#pragma unroll
        for (int f = 0; f < 8; f++) {
            int col0 = f * 8 + 2 * cc;
            *(float2*)&SQ[row_lo * FST + col0] = make_float2(sc[f][0], sc[f][1]);
            *(float2*)&SQ[row_hi * FST + col0] = make_float2(sc[f][2], sc[f][3]);
        }
        if (cc == 0) { rowc[row_lo] = corr_lo; rowc[row_hi] = corr_hi; }
        __syncthreads();

        // ---- PV: scalar fp32 f32x2, 2 threads per row ----
        {
            float corr = rowc[prow];
            uint64_t cd = pk2(corr, corr);
#pragma unroll
            for (int i = 0; i < 16; i++) mul2(acc2[i], cd);
            const float* pr = SQ + prow * FST;
            const float* vb = Vs + phalf;
#pragma unroll 4
            for (int j = 0; j < 64; ++j) {
                float p = pr[j];
                uint64_t pd = pk2(p, p);
                const ulonglong2* vrow = (const ulonglong2*)(vb + j * FST);
#pragma unroll
                for (int i = 0; i < 8; i++) {
                    ulonglong2 vv = vrow[i];
                    fma2(acc2[i * 2],     pd, vv.x);
                    fma2(acc2[i * 2 + 1], pd, vv.y);
                }
            }
        }
        __syncthreads();
    }

    // ---- finalize: publish l, divide, store ----
    if (cc == 0) { rowc[row_lo] = l_lo; rowc[row_hi] = l_hi; }
    __syncthreads();
    float inv = 1.0f / rowc[prow];
    float* op = att + ((size_t)(b * Sq + i0 + prow)) * DM + h * HD + phalf;
#pragma unroll
    for (int i = 0; i < 8; i++) {
        float x0, x1, x2, x3;
        upk2(x0, x1, acc2[i * 2]);
        upk2(x2, x3, acc2[i * 2 + 1]);
        *(float4*)(op + i * 4) = make_float4(x0 * inv, x1 * inv, x2 * inv, x3 * inv);
    }
}

// ---------------- launcher ----------------
extern "C" void kernel_launch(void* const* d_in, const int* in_sizes, int n_in,
                              void* d_out, int out_size)
{
    const float* inputs = (const float*)d_in[0];
    const float* amask  = (const float*)d_in[1];
    const float* Wq     = (const float*)d_in[2];
    const float* Wk     = (const float*)d_in[3];
    const float* Wv     = (const float*)d_in[4];
    const float* Wo     = (const float*)d_in[5];
    const float* events = (const float*)d_in[6];
    float* out = (float*)d_out;

    float *q, *k, *v, *att, *ret, *sims, *wt;
    cudaGetSymbolAddress((void**)&q,    g_q);
    cudaGetSymbolAddress((void**)&k,    g_k);
    cudaGetSymbolAddress((void**)&v,    g_v);
    cudaGetSymbolAddress((void**)&att,  g_att);
    cudaGetSymbolAddress((void**)&ret,  g_ret);
    cudaGetSymbolAddress((void**)&sims, g_sims);
    cudaGetSymbolAddress((void**)&wt,   g_wt);

    cudaFuncSetAttribute(gemm_cp,   cudaFuncAttributeMaxDynamicSharedMemorySize, GSMEM_BYTES);
    cudaFuncSetAttribute(flash_mma, cudaFuncAttributeMaxDynamicSharedMemorySize, FSMEM_BYTES);

    transpose_w<<<dim3(32, 32, 4), 256>>>(Wq, Wk, Wv, Wo, wt);

    dim3 gg(DM / 128, (Bq * Sq) / 128);   // (8, 32)
    gemm_cp<<<gg, 256, GSMEM_BYTES>>>(inputs, wt + 0 * DM * DM, q, 1);
    gemm_cp<<<gg, 256, GSMEM_BYTES>>>(inputs, wt + 1 * DM * DM, k, 1);
    gemm_cp<<<gg, 256, GSMEM_BYTES>>>(inputs, wt + 2 * DM * DM, v, 1);

    retrieve_sims<<<dim3(125, Bq), 256>>>(k, events, sims);
    topk_gather<<<Bq, 256>>>(sims, events, ret);

    flash_mma<<<dim3(Sq / 128, Hh, Bq), 256, FSMEM_BYTES>>>(amask, q, k, v, ret, att);

    gemm_cp<<<gg, 256, GSMEM_BYTES>>>(att, wt + 3 * DM * DM, out, 0);
}

// round 6
// speedup vs baseline: 1.8226x; 1.8226x over previous
#include <cuda_runtime.h>
#include <math.h>
#include <stdint.h>

// Problem constants
#define Bq   2
#define Sq   2048
#define DM   1024
#define Hh   16
#define HD   64
#define MEMN 1000
#define KTOT 10

// ---------------- device scratch ----------------
__device__ float g_q[Bq * Hh * Sq * HD];
__device__ float g_k[Bq * Hh * Sq * HD];
__device__ float g_v[Bq * Hh * Sq * HD];
__device__ float g_att[Bq * Sq * DM];
__device__ float g_ret[Bq * KTOT * DM];
__device__ float g_sims[Bq * MEMN];
__device__ float g_wt[4 * DM * DM];    // transposed weights [N][K] x4

// ---------------- helpers ----------------
__device__ __forceinline__ uint32_t smem_u32(const void* p) {
    uint32_t a;
    asm("{ .reg .u64 t; cvta.to.shared.u64 t, %1; cvt.u32.u64 %0, t; }" : "=r"(a) : "l"(p));
    return a;
}
__device__ __forceinline__ float cf_tf32(float x) {
    uint32_t u;
    asm("cvt.rna.tf32.f32 %0, %1;" : "=r"(u) : "f"(x));
    return __uint_as_float(u);
}
__device__ __forceinline__ void mma8(float* c, const uint32_t* a, const uint32_t* b) {
    asm("mma.sync.aligned.m16n8k8.row.col.f32.tf32.tf32.f32 "
        "{%0,%1,%2,%3},{%4,%5,%6,%7},{%8,%9},{%0,%1,%2,%3};"
        : "+f"(c[0]), "+f"(c[1]), "+f"(c[2]), "+f"(c[3])
        : "r"(a[0]), "r"(a[1]), "r"(a[2]), "r"(a[3]), "r"(b[0]), "r"(b[1]));
}
__device__ __forceinline__ void cpa16(uint32_t d, const void* g) {
    asm volatile("cp.async.cg.shared.global [%0], [%1], 16;" :: "r"(d), "l"(g) : "memory");
}
#define CP_COMMIT() asm volatile("cp.async.commit_group;" ::: "memory")

// ---------------- weight transpose: WT[z][n][k] = W_z[k][n] ----------------
__global__ __launch_bounds__(256) void transpose_w(const float* __restrict__ W0,
                                                   const float* __restrict__ W1,
                                                   const float* __restrict__ W2,
                                                   const float* __restrict__ W3,
                                                   float* __restrict__ WT)
{
    __shared__ float t[32][33];
    int z = blockIdx.z;
    const float* W = (z == 0) ? W0 : (z == 1) ? W1 : (z == 2) ? W2 : W3;
    float* D = WT + (size_t)z * DM * DM;
    int x = blockIdx.x * 32, y = blockIdx.y * 32;
    int tx = threadIdx.x & 31, ty = threadIdx.x >> 5;
    for (int r = ty; r < 32; r += 8)
        t[r][tx] = W[(size_t)(y + r) * DM + x + tx];
    __syncthreads();
    for (int r = ty; r < 32; r += 8)
        D[(size_t)(x + r) * DM + y + tx] = t[tx][r];
}

// ---------------- cp.async-pipelined tf32 mma.sync GEMM -------------------
#define GP      20
#define STGF    (128 * GP * 2)
#define NSTAGE  3
#define NIT     (DM / 16)
#define GSMEM_BYTES (NSTAGE * STGF * 4)

__global__ void __launch_bounds__(256, 2) gemm_cp(const float* __restrict__ A,
                                                  const float* __restrict__ WT,
                                                  float* __restrict__ C,
                                                  int headwrite)
{
    extern __shared__ float dsm[];
    uint32_t sbase = smem_u32(dsm);

    int tid = threadIdx.x, lane = tid & 31, wid = tid >> 5;
    int wm = wid & 3, wn = wid >> 2;
    int m0 = blockIdx.y * 128, n0 = blockIdx.x * 128;
    int r = lane >> 2, c = lane & 3;

    int srow = tid >> 1, shalf = tid & 1;
    const float* gA = A  + (size_t)(m0 + srow) * DM + shalf * 8;
    const float* gB = WT + (size_t)(n0 + srow) * DM + shalf * 8;
    uint32_t dA = sbase + (uint32_t)(srow * GP + shalf * 8) * 4u;
    uint32_t dB = dA + (uint32_t)(128 * GP) * 4u;

    float acc[2][8][4];
#pragma unroll
    for (int i = 0; i < 2; i++)
#pragma unroll
        for (int j = 0; j < 8; j++)
#pragma unroll
            for (int t = 0; t < 4; t++) acc[i][j][t] = 0.f;

#pragma unroll
    for (int s = 0; s < NSTAGE - 1; s++) {
        uint32_t so = (uint32_t)(s * STGF) * 4u;
        cpa16(dA + so,      gA + s * 16);
        cpa16(dA + so + 16, gA + s * 16 + 4);
        cpa16(dB + so,      gB + s * 16);
        cpa16(dB + so + 16, gB + s * 16 + 4);
        CP_COMMIT();
    }

    for (int it = 0; it < NIT; ++it) {
        if (it + NSTAGE - 1 < NIT) {
            int s = it + NSTAGE - 1;
            uint32_t so = (uint32_t)((s % NSTAGE) * STGF) * 4u;
            cpa16(dA + so,      gA + s * 16);
            cpa16(dA + so + 16, gA + s * 16 + 4);
            cpa16(dB + so,      gB + s * 16);
            cpa16(dB + so + 16, gB + s * 16 + 4);
            CP_COMMIT();
        }
        if (it <= NIT - 3)      asm volatile("cp.async.wait_group 2;" ::: "memory");
        else if (it == NIT - 2) asm volatile("cp.async.wait_group 1;" ::: "memory");
        else                    asm volatile("cp.async.wait_group 0;" ::: "memory");
        __syncthreads();

        const float* As = dsm + (it % NSTAGE) * STGF;
        const float* Bs = As + 128 * GP;

#pragma unroll
        for (int ks = 0; ks < 16; ks += 8) {
            uint32_t af[2][4];
#pragma unroll
            for (int i = 0; i < 2; i++) {
                int row = wm * 32 + i * 16 + r;
                af[i][0] = __float_as_uint(cf_tf32(As[row * GP + ks + c]));
                af[i][1] = __float_as_uint(cf_tf32(As[(row + 8) * GP + ks + c]));
                af[i][2] = __float_as_uint(cf_tf32(As[row * GP + ks + c + 4]));
                af[i][3] = __float_as_uint(cf_tf32(As[(row + 8) * GP + ks + c + 4]));
            }
            uint32_t bf[8][2];
#pragma unroll
            for (int j = 0; j < 8; j++) {
                int nr = wn * 64 + j * 8 + r;
                bf[j][0] = __float_as_uint(cf_tf32(Bs[nr * GP + ks + c]));
                bf[j][1] = __float_as_uint(cf_tf32(Bs[nr * GP + ks + c + 4]));
            }
#pragma unroll
            for (int i = 0; i < 2; i++)
#pragma unroll
                for (int j = 0; j < 8; j++) mma8(acc[i][j], af[i], bf[j]);
        }
        __syncthreads();
    }

    int c2 = (lane & 3) * 2;
#pragma unroll
    for (int i = 0; i < 2; i++) {
#pragma unroll
        for (int j = 0; j < 8; j++) {
            int row0 = m0 + wm * 32 + i * 16 + r;
            int col  = n0 + wn * 64 + j * 8 + c2;
            float2 lo = make_float2(acc[i][j][0], acc[i][j][1]);
            float2 hi = make_float2(acc[i][j][2], acc[i][j][3]);
            if (headwrite) {
                int b = row0 >> 11, h = col >> 6, hd = col & 63;
                int s0 = row0 & 2047;
                float* base = C + (((size_t)(b * Hh + h)) * Sq) * HD + hd;
                *(float2*)(base + (size_t)s0 * HD)       = lo;
                *(float2*)(base + (size_t)(s0 + 8) * HD) = hi;
            } else {
                *(float2*)&C[(size_t)row0 * DM + col]       = lo;
                *(float2*)&C[(size_t)(row0 + 8) * DM + col] = hi;
            }
        }
    }
}

// ---------------- retrieval: sims (warp per event) ------------------------
__global__ __launch_bounds__(256) void retrieve_sims(const float* __restrict__ kbuf,
                                                     const float* __restrict__ events,
                                                     float* __restrict__ sims)
{
    int b = blockIdx.y;
    int tid = threadIdx.x;
    int lane = tid & 31, wid = tid >> 5;
    __shared__ float qs[DM];
    __shared__ float qn_s;

    for (int d = tid; d < DM; d += 256) {
        int h = d >> 6, hd = d & 63;
        qs[d] = kbuf[(((size_t)(b * Hh + h)) * Sq + (Sq - 1)) * HD + hd];
    }
    __syncthreads();
    if (wid == 0) {
        float ps = 0.f;
        for (int d = lane * 4; d < DM; d += 128) {
            float4 t = *(const float4*)&qs[d];
            ps += t.x * t.x + t.y * t.y + t.z * t.z + t.w * t.w;
        }
#pragma unroll
        for (int off = 16; off > 0; off >>= 1) ps += __shfl_down_sync(0xffffffffu, ps, off);
        if (lane == 0) qn_s = sqrtf(ps) + 1e-8f;
    }
    __syncthreads();
    float qnorm = qn_s;

    int e = blockIdx.x * 8 + wid;
    if (e >= MEMN) return;
    const float* ep = events + (size_t)e * DM;
    float dot = 0.f, nn = 0.f;
    for (int d = lane * 4; d < DM; d += 128) {
        float4 ev = *(const float4*)(ep + d);
        float4 qv = *(const float4*)&qs[d];
        dot += qv.x * ev.x + qv.y * ev.y + qv.z * ev.z + qv.w * ev.w;
        nn  += ev.x * ev.x + ev.y * ev.y + ev.z * ev.z + ev.w * ev.w;
    }
#pragma unroll
    for (int off = 16; off > 0; off >>= 1) {
        dot += __shfl_down_sync(0xffffffffu, dot, off);
        nn  += __shfl_down_sync(0xffffffffu, nn, off);
    }
    if (lane == 0) sims[b * MEMN + e] = dot / (qnorm * (sqrtf(nn) + 1e-8f));
}

// ---------------- retrieval: parallel top-k + gather -----------------------
__global__ __launch_bounds__(256) void topk_gather(const float* __restrict__ sims,
                                                   const float* __restrict__ events,
                                                   float* __restrict__ ret)
{
    int b = blockIdx.x;
    int tid = threadIdx.x;
    int lane = tid & 31, wid = tid >> 5;
    __shared__ float sv[MEMN];
    __shared__ float wmax[8];
    __shared__ int   widx[8];
    __shared__ int   tidx[KTOT];

    for (int e = tid; e < MEMN; e += 256) sv[e] = sims[b * MEMN + e];
    __syncthreads();

    for (int kk = 0; kk < KTOT; kk++) {
        float bm = -1e30f; int bi = MEMN;
        for (int e = tid; e < MEMN; e += 256) {
            float v = sv[e];
            if (v > bm || (v == bm && e < bi)) { bm = v; bi = e; }
        }
#pragma unroll
        for (int off = 16; off > 0; off >>= 1) {
            float om = __shfl_down_sync(0xffffffffu, bm, off);
            int   oi = __shfl_down_sync(0xffffffffu, bi, off);
            if (om > bm || (om == bm && oi < bi)) { bm = om; bi = oi; }
        }
        if (lane == 0) { wmax[wid] = bm; widx[wid] = bi; }
        __syncthreads();
        if (tid == 0) {
            float gm = wmax[0]; int gi = widx[0];
            for (int w = 1; w < 8; w++) {
                if (wmax[w] > gm || (wmax[w] == gm && widx[w] < gi)) { gm = wmax[w]; gi = widx[w]; }
            }
            tidx[kk] = gi;
            sv[gi] = -1e30f;
        }
        __syncthreads();
    }

    for (int kk = 0; kk < KTOT; kk++) {
        int src = tidx[kk];
        for (int d = tid; d < DM; d += 256)
            ret[((size_t)b * KTOT + kk) * DM + d] = events[(size_t)src * DM + d];
    }
}

// ---------------- flash attention v3: MMA for QK^T AND PV ------------------
// CTA: 256 threads (8 warps), 128 query rows, key tiles of 64.
// Tile 0 = [10 memory tokens | first 54 keys]; tile t>=1 keys j0=t*64-10.
// SMEM floats: SQ(Q then P, tf32) 128*68 | Ks 64*68 | Vt 64*67 | mk 64
#define FST    68
#define VTST   67
#define OFF_SQ 0
#define OFF_KS (128 * FST)
#define OFF_VT (OFF_KS + 64 * FST)
#define OFF_MK (OFF_VT + 64 * VTST)
#define FSMEM_FLOATS (OFF_MK + 64)
#define FSMEM_BYTES  (FSMEM_FLOATS * 4)

__global__ void __launch_bounds__(256, 2) flash_mma(const float* __restrict__ amask,
                                                    const float* __restrict__ qbuf,
                                                    const float* __restrict__ kbuf,
                                                    const float* __restrict__ vbuf,
                                                    const float* __restrict__ ret,
                                                    float* __restrict__ att)
{
    extern __shared__ float fsm[];
    float* SQ = fsm + OFF_SQ;     // Q (tf32), later P (tf32)
    float* Ks = fsm + OFF_KS;     // K tile (tf32)
    float* Vt = fsm + OFF_VT;     // V tile transposed [col][key] (tf32)
    float* mk = fsm + OFF_MK;

    int qt = gridDim.x - 1 - blockIdx.x;   // heavy tiles first
    int h = blockIdx.y, b = blockIdx.z;
    int tid = threadIdx.x;
    int lane = tid & 31, w = tid >> 5;
    int r = lane >> 2, cc = lane & 3;
    int i0 = qt * 128;
    const float scale = 0.125f;
    float slope = exp2f(-0.5f * (float)(h + 1));

    const float* qbase = qbuf + ((size_t)(b * Hh + h)) * Sq * HD;
    const float* kbase = kbuf + ((size_t)(b * Hh + h)) * Sq * HD;
    const float* vbase = vbuf + ((size_t)(b * Hh + h)) * Sq * HD;

    // ---- stage Q (tf32) ----
    {
        int row = tid >> 1, h32 = (tid & 1) * 32;
        const float* qp = qbase + (size_t)(i0 + row) * HD + h32;
        float* dst = SQ + row * FST + h32;
#pragma unroll
        for (int i = 0; i < 8; i++) {
            float4 t = *(const float4*)(qp + i * 4);
            dst[i * 4]     = cf_tf32(t.x);
            dst[i * 4 + 1] = cf_tf32(t.y);
            dst[i * 4 + 2] = cf_tf32(t.z);
            dst[i * 4 + 3] = cf_tf32(t.w);
        }
    }
    __syncthreads();

    // ---- A fragments (Q) once per CTA (warp-exclusive rows) ----
    int row_lo = w * 16 + r, row_hi = row_lo + 8;
    int ig_lo = i0 + row_lo, ig_hi = i0 + row_hi;
    uint32_t afr[8][4];
#pragma unroll
    for (int ks = 0; ks < 8; ks++) {
        afr[ks][0] = __float_as_uint(SQ[row_lo * FST + ks * 8 + cc]);
        afr[ks][1] = __float_as_uint(SQ[row_hi * FST + ks * 8 + cc]);
        afr[ks][2] = __float_as_uint(SQ[row_lo * FST + ks * 8 + cc + 4]);
        afr[ks][3] = __float_as_uint(SQ[row_hi * FST + ks * 8 + cc + 4]);
    }

    float of[8][4];
#pragma unroll
    for (int f = 0; f < 8; f++)
#pragma unroll
        for (int e = 0; e < 4; e++) of[f][e] = 0.f;

    float m_lo = -1e30f, m_hi = -1e30f, l_lo = 0.f, l_hi = 0.f;

    int ntiles = 2 * qt + 3;
    for (int t = 0; t < ntiles; ++t) {
        int j0 = t * 64 - 10;
        // ---- stage K (tf32) and V transposed (tf32) ----
        {
            int kk = tid >> 2, part = (tid & 3) * 16;
            const float *kp, *vp;
            if (t == 0 && kk < KTOT) {
                kp = ret + ((size_t)b * KTOT + kk) * DM + h * HD + part;
                vp = kp;
            } else {
                int jg = j0 + kk;
                if (jg > Sq - 1) jg = Sq - 1;
                kp = kbase + (size_t)jg * HD + part;
                vp = vbase + (size_t)jg * HD + part;
            }
            float* dk = Ks + kk * FST + part;
#pragma unroll
            for (int i = 0; i < 4; i++) {
                float4 tk = *(const float4*)(kp + i * 4);
                dk[i * 4]     = cf_tf32(tk.x);
                dk[i * 4 + 1] = cf_tf32(tk.y);
                dk[i * 4 + 2] = cf_tf32(tk.z);
                dk[i * 4 + 3] = cf_tf32(tk.w);
            }
#pragma unroll
            for (int i = 0; i < 4; i++) {
                float4 tv = *(const float4*)(vp + i * 4);
                Vt[(part + i * 4 + 0) * VTST + kk] = cf_tf32(tv.x);
                Vt[(part + i * 4 + 1) * VTST + kk] = cf_tf32(tv.y);
                Vt[(part + i * 4 + 2) * VTST + kk] = cf_tf32(tv.z);
                Vt[(part + i * 4 + 3) * VTST + kk] = cf_tf32(tv.w);
            }
            if (tid < 64) {
                int jg = j0 + tid;
                if (jg < 0) jg = 0;
                if (jg > Sq - 1) jg = Sq - 1;
                mk[tid] = (t == 0 && tid < KTOT) ? 1.0f : amask[b * Sq + jg];
            }
        }
        __syncthreads();

        // ---- S = Q K^T via mma.sync ----
        float sc[8][4];
#pragma unroll
        for (int f = 0; f < 8; f++)
#pragma unroll
            for (int e = 0; e < 4; e++) sc[f][e] = 0.f;
#pragma unroll
        for (int ks = 0; ks < 8; ks++) {
#pragma unroll
            for (int f = 0; f < 8; f++) {
                uint32_t bb[2];
                bb[0] = __float_as_uint(Ks[(f * 8 + r) * FST + ks * 8 + cc]);
                bb[1] = __float_as_uint(Ks[(f * 8 + r) * FST + ks * 8 + cc + 4]);
                mma8(sc[f], afr[ks], bb);
            }
        }

        // ---- bias + causal + mask, tile max ----
        float tmax_lo = m_lo, tmax_hi = m_hi;
#pragma unroll
        for (int f = 0; f < 8; f++) {
            int col0 = f * 8 + 2 * cc;
            int col1 = col0 + 1;
            int jg0 = j0 + col0, jg1 = j0 + col1;
            bool mem0 = (t == 0) && (col0 < KTOT);
            bool mem1 = (t == 0) && (col1 < KTOT);
            float pen0 = (1.0f - mk[col0]) * (-1e9f);
            float pen1 = (1.0f - mk[col1]) * (-1e9f);
            float s;
            s = sc[f][0] * scale + (mem0 ? 0.f : slope * (float)(ig_lo - jg0) + pen0);
            if (!mem0 && jg0 > ig_lo) s = -1e30f;
            sc[f][0] = s; tmax_lo = fmaxf(tmax_lo, s);
            s = sc[f][1] * scale + (mem1 ? 0.f : slope * (float)(ig_lo - jg1) + pen1);
            if (!mem1 && jg1 > ig_lo) s = -1e30f;
            sc[f][1] = s; tmax_lo = fmaxf(tmax_lo, s);
            s = sc[f][2] * scale + (mem0 ? 0.f : slope * (float)(ig_hi - jg0) + pen0);
            if (!mem0 && jg0 > ig_hi) s = -1e30f;
            sc[f][2] = s; tmax_hi = fmaxf(tmax_hi, s);
            s = sc[f][3] * scale + (mem1 ? 0.f : slope * (float)(ig_hi - jg1) + pen1);
            if (!mem1 && jg1 > ig_hi) s = -1e30f;
            sc[f][3] = s; tmax_hi = fmaxf(tmax_hi, s);
        }
        tmax_lo = fmaxf(tmax_lo, __shfl_xor_sync(0xffffffffu, tmax_lo, 1));
        tmax_lo = fmaxf(tmax_lo, __shfl_xor_sync(0xffffffffu, tmax_lo, 2));
        tmax_hi = fmaxf(tmax_hi, __shfl_xor_sync(0xffffffffu, tmax_hi, 1));
        tmax_hi = fmaxf(tmax_hi, __shfl_xor_sync(0xffffffffu, tmax_hi, 2));

        float corr_lo = __expf(m_lo - tmax_lo);
        float corr_hi = __expf(m_hi - tmax_hi);
        l_lo *= corr_lo; l_hi *= corr_hi;
        m_lo = tmax_lo;  m_hi = tmax_hi;

        float sl = 0.f, sh = 0.f;
#pragma unroll
        for (int f = 0; f < 8; f++) {
            sc[f][0] = __expf(sc[f][0] - m_lo); sl += sc[f][0];
            sc[f][1] = __expf(sc[f][1] - m_lo); sl += sc[f][1];
            sc[f][2] = __expf(sc[f][2] - m_hi); sh += sc[f][2];
            sc[f][3] = __expf(sc[f][3] - m_hi); sh += sc[f][3];
        }
        sl += __shfl_xor_sync(0xffffffffu, sl, 1);
        sl += __shfl_xor_sync(0xffffffffu, sl, 2);
        sh += __shfl_xor_sync(0xffffffffu, sh, 1);
        sh += __shfl_xor_sync(0xffffffffu, sh, 2);
        l_lo += sl; l_hi += sh;

        // ---- rescale O fragments by corr ----
#pragma unroll
        for (int f = 0; f < 8; f++) {
            of[f][0] *= corr_lo; of[f][1] *= corr_lo;
            of[f][2] *= corr_hi; of[f][3] *= corr_hi;
        }

        // ---- write P (tf32) to warp-exclusive SQ rows ----
#pragma unroll
        for (int f = 0; f < 8; f++) {
            int col0 = f * 8 + 2 * cc;
            *(float2*)&SQ[row_lo * FST + col0] = make_float2(cf_tf32(sc[f][0]), cf_tf32(sc[f][1]));
            *(float2*)&SQ[row_hi * FST + col0] = make_float2(cf_tf32(sc[f][2]), cf_tf32(sc[f][3]));
        }
        __syncwarp();

        // ---- O += P V via mma.sync ----
#pragma unroll
        for (int ks = 0; ks < 8; ks++) {
            uint32_t ap[4];
            ap[0] = __float_as_uint(SQ[row_lo * FST + ks * 8 + cc]);
            ap[1] = __float_as_uint(SQ[row_hi * FST + ks * 8 + cc]);
            ap[2] = __float_as_uint(SQ[row_lo * FST + ks * 8 + cc + 4]);
            ap[3] = __float_as_uint(SQ[row_hi * FST + ks * 8 + cc + 4]);
#pragma unroll
            for (int f = 0; f < 8; f++) {
                uint32_t bv[2];
                bv[0] = __float_as_uint(Vt[(f * 8 + r) * VTST + ks * 8 + cc]);
                bv[1] = __float_as_uint(Vt[(f * 8 + r) * VTST + ks * 8 + cc + 4]);
                mma8(of[f], ap, bv);
            }
        }
        __syncthreads();
    }

    // ---- finalize: divide by l, store ----
    float inv_lo = 1.0f / l_lo, inv_hi = 1.0f / l_hi;
    float* olo = att + ((size_t)(b * Sq + ig_lo)) * DM + h * HD;
    float* ohi = att + ((size_t)(b * Sq + ig_hi)) * DM + h * HD;
#pragma unroll
    for (int f = 0; f < 8; f++) {
        int col0 = f * 8 + 2 * cc;
        *(float2*)(olo + col0) = make_float2(of[f][0] * inv_lo, of[f][1] * inv_lo);
        *(float2*)(ohi + col0) = make_float2(of[f][2] * inv_hi, of[f][3] * inv_hi);
    }
}

// ---------------- launcher ----------------
extern "C" void kernel_launch(void* const* d_in, const int* in_sizes, int n_in,
                              void* d_out, int out_size)
{
    const float* inputs = (const float*)d_in[0];
    const float* amask  = (const float*)d_in[1];
    const float* Wq     = (const float*)d_in[2];
    const float* Wk     = (const float*)d_in[3];
    const float* Wv     = (const float*)d_in[4];
    const float* Wo     = (const float*)d_in[5];
    const float* events = (const float*)d_in[6];
    float* out = (float*)d_out;

    float *q, *k, *v, *att, *ret, *sims, *wt;
    cudaGetSymbolAddress((void**)&q,    g_q);
    cudaGetSymbolAddress((void**)&k,    g_k);
    cudaGetSymbolAddress((void**)&v,    g_v);
    cudaGetSymbolAddress((void**)&att,  g_att);
    cudaGetSymbolAddress((void**)&ret,  g_ret);
    cudaGetSymbolAddress((void**)&sims, g_sims);
    cudaGetSymbolAddress((void**)&wt,   g_wt);

    cudaFuncSetAttribute(gemm_cp,   cudaFuncAttributeMaxDynamicSharedMemorySize, GSMEM_BYTES);
    cudaFuncSetAttribute(flash_mma, cudaFuncAttributeMaxDynamicSharedMemorySize, FSMEM_BYTES);

    transpose_w<<<dim3(32, 32, 4), 256>>>(Wq, Wk, Wv, Wo, wt);

    dim3 gg(DM / 128, (Bq * Sq) / 128);   // (8, 32)
    gemm_cp<<<gg, 256, GSMEM_BYTES>>>(inputs, wt + 0 * DM * DM, q, 1);
    gemm_cp<<<gg, 256, GSMEM_BYTES>>>(inputs, wt + 1 * DM * DM, k, 1);
    gemm_cp<<<gg, 256, GSMEM_BYTES>>>(inputs, wt + 2 * DM * DM, v, 1);

    retrieve_sims<<<dim3(125, Bq), 256>>>(k, events, sims);
    topk_gather<<<Bq, 256>>>(sims, events, ret);

    flash_mma<<<dim3(Sq / 128, Hh, Bq), 256, FSMEM_BYTES>>>(amask, q, k, v, ret, att);

    gemm_cp<<<gg, 256, GSMEM_BYTES>>>(att, wt + 3 * DM * DM, out, 0);
}

// round 7
// speedup vs baseline: 1.9238x; 1.0555x over previous
#include <cuda_runtime.h>
#include <math.h>
#include <stdint.h>

// Problem constants
#define Bq   2
#define Sq   2048
#define DM   1024
#define Hh   16
#define HD   64
#define MEMN 1000
#define KTOT 10

// ---------------- device scratch ----------------
__device__ float g_q[Bq * Hh * Sq * HD];
__device__ float g_k[Bq * Hh * Sq * HD];
__device__ float g_v[Bq * Hh * Sq * HD];
__device__ float g_att[Bq * Sq * DM];
__device__ float g_ret[Bq * KTOT * DM];
__device__ float g_sims[Bq * MEMN];
__device__ float g_wt[4 * DM * DM];    // transposed + tf32-rounded weights
__device__ float g_ai[Bq * Sq * DM];   // tf32-rounded inputs

// ---------------- helpers ----------------
__device__ __forceinline__ uint32_t smem_u32(const void* p) {
    uint32_t a;
    asm("{ .reg .u64 t; cvta.to.shared.u64 t, %1; cvt.u32.u64 %0, t; }" : "=r"(a) : "l"(p));
    return a;
}
__device__ __forceinline__ float cf_tf32(float x) {
    uint32_t u;
    asm("cvt.rna.tf32.f32 %0, %1;" : "=r"(u) : "f"(x));
    return __uint_as_float(u);
}
__device__ __forceinline__ void mma8(float* c, const uint32_t* a, const uint32_t* b) {
    asm("mma.sync.aligned.m16n8k8.row.col.f32.tf32.tf32.f32 "
        "{%0,%1,%2,%3},{%4,%5,%6,%7},{%8,%9},{%0,%1,%2,%3};"
        : "+f"(c[0]), "+f"(c[1]), "+f"(c[2]), "+f"(c[3])
        : "r"(a[0]), "r"(a[1]), "r"(a[2]), "r"(a[3]), "r"(b[0]), "r"(b[1]));
}
__device__ __forceinline__ void cpa16(uint32_t d, const void* g) {
    asm volatile("cp.async.cg.shared.global [%0], [%1], 16;" :: "r"(d), "l"(g) : "memory");
}
#define CP_COMMIT() asm volatile("cp.async.commit_group;" ::: "memory")

// ---------------- prep: round inputs to tf32 in global ---------------------
__global__ __launch_bounds__(256) void prep_a(const float* __restrict__ A,
                                              float* __restrict__ D)
{
    size_t i = ((size_t)blockIdx.x * 256 + threadIdx.x) * 4;
    float4 t = *(const float4*)(A + i);
    *(float4*)(D + i) = make_float4(cf_tf32(t.x), cf_tf32(t.y), cf_tf32(t.z), cf_tf32(t.w));
}

// ---------------- weight transpose + tf32 round ----------------------------
__global__ __launch_bounds__(256) void transpose_w(const float* __restrict__ W0,
                                                   const float* __restrict__ W1,
                                                   const float* __restrict__ W2,
                                                   const float* __restrict__ W3,
                                                   float* __restrict__ WT)
{
    __shared__ float t[32][33];
    int z = blockIdx.z;
    const float* W = (z == 0) ? W0 : (z == 1) ? W1 : (z == 2) ? W2 : W3;
    float* D = WT + (size_t)z * DM * DM;
    int x = blockIdx.x * 32, y = blockIdx.y * 32;
    int tx = threadIdx.x & 31, ty = threadIdx.x >> 5;
    for (int r = ty; r < 32; r += 8)
        t[r][tx] = W[(size_t)(y + r) * DM + x + tx];
    __syncthreads();
    for (int r = ty; r < 32; r += 8)
        D[(size_t)(x + r) * DM + y + tx] = cf_tf32(t[tx][r]);
}

// ---------------- cp.async-pipelined tf32 mma.sync GEMM -------------------
// Inputs are pre-rounded to tf32 in global; fragment loads are pure LDS.
#define GP      20
#define STGF    (128 * GP * 2)
#define NSTAGE  3
#define NIT     (DM / 16)
#define GSMEM_BYTES (NSTAGE * STGF * 4)

struct GemmOuts { float *c0, *c1, *c2; };

__device__ __forceinline__ void gemm_body(const float* __restrict__ A,
                                          const float* __restrict__ WT,
                                          float* __restrict__ C,
                                          int headwrite, float* dsm)
{
    uint32_t sbase = smem_u32(dsm);
    int tid = threadIdx.x, lane = tid & 31, wid = tid >> 5;
    int wm = wid & 3, wn = wid >> 2;
    int m0 = blockIdx.y * 128, n0 = blockIdx.x * 128;
    int r = lane >> 2, c = lane & 3;

    int srow = tid >> 1, shalf = tid & 1;
    const float* gA = A  + (size_t)(m0 + srow) * DM + shalf * 8;
    const float* gB = WT + (size_t)(n0 + srow) * DM + shalf * 8;
    uint32_t dA = sbase + (uint32_t)(srow * GP + shalf * 8) * 4u;
    uint32_t dB = dA + (uint32_t)(128 * GP) * 4u;

    float acc[2][8][4];
#pragma unroll
    for (int i = 0; i < 2; i++)
#pragma unroll
        for (int j = 0; j < 8; j++)
#pragma unroll
            for (int t = 0; t < 4; t++) acc[i][j][t] = 0.f;

#pragma unroll
    for (int s = 0; s < NSTAGE - 1; s++) {
        uint32_t so = (uint32_t)(s * STGF) * 4u;
        cpa16(dA + so,      gA + s * 16);
        cpa16(dA + so + 16, gA + s * 16 + 4);
        cpa16(dB + so,      gB + s * 16);
        cpa16(dB + so + 16, gB + s * 16 + 4);
        CP_COMMIT();
    }

    for (int it = 0; it < NIT; ++it) {
        if (it + NSTAGE - 1 < NIT) {
            int s = it + NSTAGE - 1;
            uint32_t so = (uint32_t)((s % NSTAGE) * STGF) * 4u;
            cpa16(dA + so,      gA + s * 16);
            cpa16(dA + so + 16, gA + s * 16 + 4);
            cpa16(dB + so,      gB + s * 16);
            cpa16(dB + so + 16, gB + s * 16 + 4);
            CP_COMMIT();
        }
        if (it <= NIT - 3)      asm volatile("cp.async.wait_group 2;" ::: "memory");
        else if (it == NIT - 2) asm volatile("cp.async.wait_group 1;" ::: "memory");
        else                    asm volatile("cp.async.wait_group 0;" ::: "memory");
        __syncthreads();

        const float* As = dsm + (it % NSTAGE) * STGF;
        const float* Bs = As + 128 * GP;

#pragma unroll
        for (int ks = 0; ks < 16; ks += 8) {
            uint32_t af[2][4];
#pragma unroll
            for (int i = 0; i < 2; i++) {
                int row = wm * 32 + i * 16 + r;
                af[i][0] = __float_as_uint(As[row * GP + ks + c]);
                af[i][1] = __float_as_uint(As[(row + 8) * GP + ks + c]);
                af[i][2] = __float_as_uint(As[row * GP + ks + c + 4]);
                af[i][3] = __float_as_uint(As[(row + 8) * GP + ks + c + 4]);
            }
            uint32_t bf[8][2];
#pragma unroll
            for (int j = 0; j < 8; j++) {
                int nr = wn * 64 + j * 8 + r;
                bf[j][0] = __float_as_uint(Bs[nr * GP + ks + c]);
                bf[j][1] = __float_as_uint(Bs[nr * GP + ks + c + 4]);
            }
#pragma unroll
            for (int i = 0; i < 2; i++)
#pragma unroll
                for (int j = 0; j < 8; j++) mma8(acc[i][j], af[i], bf[j]);
        }
        __syncthreads();
    }

    int c2 = (lane & 3) * 2;
#pragma unroll
    for (int i = 0; i < 2; i++) {
#pragma unroll
        for (int j = 0; j < 8; j++) {
            int row0 = m0 + wm * 32 + i * 16 + r;
            int col  = n0 + wn * 64 + j * 8 + c2;
            float2 lo = make_float2(acc[i][j][0], acc[i][j][1]);
            float2 hi = make_float2(acc[i][j][2], acc[i][j][3]);
            if (headwrite) {
                int b = row0 >> 11, h = col >> 6, hd = col & 63;
                int s0 = row0 & 2047;
                float* base = C + (((size_t)(b * Hh + h)) * Sq) * HD + hd;
                *(float2*)(base + (size_t)s0 * HD)       = lo;
                *(float2*)(base + (size_t)(s0 + 8) * HD) = hi;
            } else {
                *(float2*)&C[(size_t)row0 * DM + col]       = lo;
                *(float2*)&C[(size_t)(row0 + 8) * DM + col] = hi;
            }
        }
    }
}

__global__ void __launch_bounds__(256, 2) gemm_qkv(const float* __restrict__ A,
                                                   const float* __restrict__ WT,
                                                   float* q, float* k, float* v)
{
    extern __shared__ float dsm[];
    int z = blockIdx.z;
    float* C = (z == 0) ? q : (z == 1) ? k : v;
    gemm_body(A, WT + (size_t)z * DM * DM, C, 1, dsm);
}

__global__ void __launch_bounds__(256, 2) gemm_o(const float* __restrict__ A,
                                                 const float* __restrict__ WT,
                                                 float* __restrict__ C)
{
    extern __shared__ float dsm[];
    gemm_body(A, WT, C, 0, dsm);
}

// ---------------- retrieval: sims (warp per event) ------------------------
__global__ __launch_bounds__(256) void retrieve_sims(const float* __restrict__ kbuf,
                                                     const float* __restrict__ events,
                                                     float* __restrict__ sims)
{
    int b = blockIdx.y;
    int tid = threadIdx.x;
    int lane = tid & 31, wid = tid >> 5;
    __shared__ float qs[DM];
    __shared__ float qn_s;

    for (int d = tid; d < DM; d += 256) {
        int h = d >> 6, hd = d & 63;
        qs[d] = kbuf[(((size_t)(b * Hh + h)) * Sq + (Sq - 1)) * HD + hd];
    }
    __syncthreads();
    if (wid == 0) {
        float ps = 0.f;
        for (int d = lane * 4; d < DM; d += 128) {
            float4 t = *(const float4*)&qs[d];
            ps += t.x * t.x + t.y * t.y + t.z * t.z + t.w * t.w;
        }
#pragma unroll
        for (int off = 16; off > 0; off >>= 1) ps += __shfl_down_sync(0xffffffffu, ps, off);
        if (lane == 0) qn_s = sqrtf(ps) + 1e-8f;
    }
    __syncthreads();
    float qnorm = qn_s;

    int e = blockIdx.x * 8 + wid;
    if (e >= MEMN) return;
    const float* ep = events + (size_t)e * DM;
    float dot = 0.f, nn = 0.f;
    for (int d = lane * 4; d < DM; d += 128) {
        float4 ev = *(const float4*)(ep + d);
        float4 qv = *(const float4*)&qs[d];
        dot += qv.x * ev.x + qv.y * ev.y + qv.z * ev.z + qv.w * ev.w;
        nn  += ev.x * ev.x + ev.y * ev.y + ev.z * ev.z + ev.w * ev.w;
    }
#pragma unroll
    for (int off = 16; off > 0; off >>= 1) {
        dot += __shfl_down_sync(0xffffffffu, dot, off);
        nn  += __shfl_down_sync(0xffffffffu, nn, off);
    }
    if (lane == 0) sims[b * MEMN + e] = dot / (qnorm * (sqrtf(nn) + 1e-8f));
}

// ---------------- retrieval: parallel top-k + gather -----------------------
__global__ __launch_bounds__(256) void topk_gather(const float* __restrict__ sims,
                                                   const float* __restrict__ events,
                                                   float* __restrict__ ret)
{
    int b = blockIdx.x;
    int tid = threadIdx.x;
    int lane = tid & 31, wid = tid >> 5;
    __shared__ float sv[MEMN];
    __shared__ float wmax[8];
    __shared__ int   widx[8];
    __shared__ int   tidx[KTOT];

    for (int e = tid; e < MEMN; e += 256) sv[e] = sims[b * MEMN + e];
    __syncthreads();

    for (int kk = 0; kk < KTOT; kk++) {
        float bm = -1e30f; int bi = MEMN;
        for (int e = tid; e < MEMN; e += 256) {
            float v = sv[e];
            if (v > bm || (v == bm && e < bi)) { bm = v; bi = e; }
        }
#pragma unroll
        for (int off = 16; off > 0; off >>= 1) {
            float om = __shfl_down_sync(0xffffffffu, bm, off);
            int   oi = __shfl_down_sync(0xffffffffu, bi, off);
            if (om > bm || (om == bm && oi < bi)) { bm = om; bi = oi; }
        }
        if (lane == 0) { wmax[wid] = bm; widx[wid] = bi; }
        __syncthreads();
        if (tid == 0) {
            float gm = wmax[0]; int gi = widx[0];
            for (int w = 1; w < 8; w++) {
                if (wmax[w] > gm || (wmax[w] == gm && widx[w] < gi)) { gm = wmax[w]; gi = widx[w]; }
            }
            tidx[kk] = gi;
            sv[gi] = -1e30f;
        }
        __syncthreads();
    }

    for (int kk = 0; kk < KTOT; kk++) {
        int src = tidx[kk];
        for (int d = tid; d < DM; d += 256)
            ret[((size_t)b * KTOT + kk) * DM + d] = events[(size_t)src * DM + d];
    }
}

// ---------------- flash attention v4: MMA QK+PV, no reg spills -------------
// 256 threads / 8 warps, 128 q-rows per CTA, key tiles of 64.
// Q fragments re-loaded from SMEM each tile (frees 32 regs); P has its own buf.
#define FST    68
#define OFF_SQ 0
#define OFF_SP (128 * FST)
#define OFF_KS (OFF_SP + 128 * FST)
#define OFF_VT (OFF_KS + 64 * FST)
#define OFF_MK (OFF_VT + 64 * FST)
#define FSMEM_FLOATS (OFF_MK + 64)
#define FSMEM_BYTES  (FSMEM_FLOATS * 4)

__global__ void __launch_bounds__(256, 2) flash_mma(const float* __restrict__ amask,
                                                    const float* __restrict__ qbuf,
                                                    const float* __restrict__ kbuf,
                                                    const float* __restrict__ vbuf,
                                                    const float* __restrict__ ret,
                                                    float* __restrict__ att)
{
    extern __shared__ float fsm[];
    float* SQ = fsm + OFF_SQ;     // Q (tf32) — persistent
    float* SP = fsm + OFF_SP;     // P (tf32)
    float* Ks = fsm + OFF_KS;     // K tile (tf32)
    float* Vt = fsm + OFF_VT;     // V tile transposed [col][key] (tf32)
    float* mk = fsm + OFF_MK;

    int qt = gridDim.x - 1 - blockIdx.x;   // heavy tiles first
    int h = blockIdx.y, b = blockIdx.z;
    int tid = threadIdx.x;
    int lane = tid & 31, w = tid >> 5;
    int r = lane >> 2, cc = lane & 3;
    int i0 = qt * 128;
    const float scale = 0.125f;
    float slope = exp2f(-0.5f * (float)(h + 1));

    const float* qbase = qbuf + ((size_t)(b * Hh + h)) * Sq * HD;
    const float* kbase = kbuf + ((size_t)(b * Hh + h)) * Sq * HD;
    const float* vbase = vbuf + ((size_t)(b * Hh + h)) * Sq * HD;

    // ---- stage Q (tf32), persistent all loop ----
    {
        int row = tid >> 1, h32 = (tid & 1) * 32;
        const float* qp = qbase + (size_t)(i0 + row) * HD + h32;
        float* dst = SQ + row * FST + h32;
#pragma unroll
        for (int i = 0; i < 8; i++) {
            float4 t = *(const float4*)(qp + i * 4);
            dst[i * 4]     = cf_tf32(t.x);
            dst[i * 4 + 1] = cf_tf32(t.y);
            dst[i * 4 + 2] = cf_tf32(t.z);
            dst[i * 4 + 3] = cf_tf32(t.w);
        }
    }
    __syncthreads();

    int row_lo = w * 16 + r, row_hi = row_lo + 8;
    int ig_lo = i0 + row_lo, ig_hi = i0 + row_hi;

    float of[8][4];
#pragma unroll
    for (int f = 0; f < 8; f++)
#pragma unroll
        for (int e = 0; e < 4; e++) of[f][e] = 0.f;

    float m_lo = -1e30f, m_hi = -1e30f, l_lo = 0.f, l_hi = 0.f;

    int ntiles = 2 * qt + 3;
    for (int t = 0; t < ntiles; ++t) {
        int j0 = t * 64 - 10;
        // ---- stage K (tf32) and V transposed (tf32) ----
        {
            int kk = tid >> 2, part = (tid & 3) * 16;
            const float *kp, *vp;
            if (t == 0 && kk < KTOT) {
                kp = ret + ((size_t)b * KTOT + kk) * DM + h * HD + part;
                vp = kp;
            } else {
                int jg = j0 + kk;
                if (jg > Sq - 1) jg = Sq - 1;
                kp = kbase + (size_t)jg * HD + part;
                vp = vbase + (size_t)jg * HD + part;
            }
            float* dk = Ks + kk * FST + part;
#pragma unroll
            for (int i = 0; i < 4; i++) {
                float4 tk = *(const float4*)(kp + i * 4);
                dk[i * 4]     = cf_tf32(tk.x);
                dk[i * 4 + 1] = cf_tf32(tk.y);
                dk[i * 4 + 2] = cf_tf32(tk.z);
                dk[i * 4 + 3] = cf_tf32(tk.w);
            }
#pragma unroll
            for (int i = 0; i < 4; i++) {
                float4 tv = *(const float4*)(vp + i * 4);
                Vt[(part + i * 4 + 0) * FST + kk] = cf_tf32(tv.x);
                Vt[(part + i * 4 + 1) * FST + kk] = cf_tf32(tv.y);
                Vt[(part + i * 4 + 2) * FST + kk] = cf_tf32(tv.z);
                Vt[(part + i * 4 + 3) * FST + kk] = cf_tf32(tv.w);
            }
            if (tid < 64) {
                int jg = j0 + tid;
                if (jg < 0) jg = 0;
                if (jg > Sq - 1) jg = Sq - 1;
                mk[tid] = (t == 0 && tid < KTOT) ? 1.0f : amask[b * Sq + jg];
            }
        }
        __syncthreads();

        // ---- S = Q K^T via mma.sync (Q frags from SMEM each kstep) ----
        float sc[8][4];
#pragma unroll
        for (int f = 0; f < 8; f++)
#pragma unroll
            for (int e = 0; e < 4; e++) sc[f][e] = 0.f;
#pragma unroll
        for (int ks = 0; ks < 8; ks++) {
            uint32_t aq[4];
            aq[0] = __float_as_uint(SQ[row_lo * FST + ks * 8 + cc]);
            aq[1] = __float_as_uint(SQ[row_hi * FST + ks * 8 + cc]);
            aq[2] = __float_as_uint(SQ[row_lo * FST + ks * 8 + cc + 4]);
            aq[3] = __float_as_uint(SQ[row_hi * FST + ks * 8 + cc + 4]);
#pragma unroll
            for (int f = 0; f < 8; f++) {
                uint32_t bb[2];
                bb[0] = __float_as_uint(Ks[(f * 8 + r) * FST + ks * 8 + cc]);
                bb[1] = __float_as_uint(Ks[(f * 8 + r) * FST + ks * 8 + cc + 4]);
                mma8(sc[f], aq, bb);
            }
        }

        // ---- bias + causal + mask, tile max ----
        float tmax_lo = m_lo, tmax_hi = m_hi;
#pragma unroll
        for (int f = 0; f < 8; f++) {
            int col0 = f * 8 + 2 * cc;
            int col1 = col0 + 1;
            int jg0 = j0 + col0, jg1 = j0 + col1;
            bool mem0 = (t == 0) && (col0 < KTOT);
            bool mem1 = (t == 0) && (col1 < KTOT);
            float pen0 = (1.0f - mk[col0]) * (-1e9f);
            float pen1 = (1.0f - mk[col1]) * (-1e9f);
            float s;
            s = sc[f][0] * scale + (mem0 ? 0.f : slope * (float)(ig_lo - jg0) + pen0);
            if (!mem0 && jg0 > ig_lo) s = -1e30f;
            sc[f][0] = s; tmax_lo = fmaxf(tmax_lo, s);
            s = sc[f][1] * scale + (mem1 ? 0.f : slope * (float)(ig_lo - jg1) + pen1);
            if (!mem1 && jg1 > ig_lo) s = -1e30f;
            sc[f][1] = s; tmax_lo = fmaxf(tmax_lo, s);
            s = sc[f][2] * scale + (mem0 ? 0.f : slope * (float)(ig_hi - jg0) + pen0);
            if (!mem0 && jg0 > ig_hi) s = -1e30f;
            sc[f][2] = s; tmax_hi = fmaxf(tmax_hi, s);
            s = sc[f][3] * scale + (mem1 ? 0.f : slope * (float)(ig_hi - jg1) + pen1);
            if (!mem1 && jg1 > ig_hi) s = -1e30f;
            sc[f][3] = s; tmax_hi = fmaxf(tmax_hi, s);
        }
        tmax_lo = fmaxf(tmax_lo, __shfl_xor_sync(0xffffffffu, tmax_lo, 1));
        tmax_lo = fmaxf(tmax_lo, __shfl_xor_sync(0xffffffffu, tmax_lo, 2));
        tmax_hi = fmaxf(tmax_hi, __shfl_xor_sync(0xffffffffu, tmax_hi, 1));
        tmax_hi = fmaxf(tmax_hi, __shfl_xor_sync(0xffffffffu, tmax_hi, 2));

        float corr_lo = __expf(m_lo - tmax_lo);
        float corr_hi = __expf(m_hi - tmax_hi);
        l_lo *= corr_lo; l_hi *= corr_hi;
        m_lo = tmax_lo;  m_hi = tmax_hi;

        float sl = 0.f, sh = 0.f;
#pragma unroll
        for (int f = 0; f < 8; f++) {
            sc[f][0] = __expf(sc[f][0] - m_lo); sl += sc[f][0];
            sc[f][1] = __expf(sc[f][1] - m_lo); sl += sc[f][1];
            sc[f][2] = __expf(sc[f][2] - m_hi); sh += sc[f][2];
            sc[f][3] = __expf(sc[f][3] - m_hi); sh += sc[f][3];
        }
        sl += __shfl_xor_sync(0xffffffffu, sl, 1);
        sl += __shfl_xor_sync(0xffffffffu, sl, 2);
        sh += __shfl_xor_sync(0xffffffffu, sh, 1);
        sh += __shfl_xor_sync(0xffffffffu, sh, 2);
        l_lo += sl; l_hi += sh;

#pragma unroll
        for (int f = 0; f < 8; f++) {
            of[f][0] *= corr_lo; of[f][1] *= corr_lo;
            of[f][2] *= corr_hi; of[f][3] *= corr_hi;
        }

        // ---- write P (tf32) to warp-exclusive SP rows ----
#pragma unroll
        for (int f = 0; f < 8; f++) {
            int col0 = f * 8 + 2 * cc;
            *(float2*)&SP[row_lo * FST + col0] = make_float2(cf_tf32(sc[f][0]), cf_tf32(sc[f][1]));
            *(float2*)&SP[row_hi * FST + col0] = make_float2(cf_tf32(sc[f][2]), cf_tf32(sc[f][3]));
        }
        __syncwarp();

        // ---- O += P V via mma.sync ----
#pragma unroll
        for (int ks = 0; ks < 8; ks++) {
            uint32_t ap[4];
            ap[0] = __float_as_uint(SP[row_lo * FST + ks * 8 + cc]);
            ap[1] = __float_as_uint(SP[row_hi * FST + ks * 8 + cc]);
            ap[2] = __float_as_uint(SP[row_lo * FST + ks * 8 + cc + 4]);
            ap[3] = __float_as_uint(SP[row_hi * FST + ks * 8 + cc + 4]);
#pragma unroll
            for (int f = 0; f < 8; f++) {
                uint32_t bv[2];
                bv[0] = __float_as_uint(Vt[(f * 8 + r) * FST + ks * 8 + cc]);
                bv[1] = __float_as_uint(Vt[(f * 8 + r) * FST + ks * 8 + cc + 4]);
                mma8(of[f], ap, bv);
            }
        }
        __syncthreads();
    }

    // ---- finalize: divide by l, tf32-round (next GEMM input), store ----
    float inv_lo = 1.0f / l_lo, inv_hi = 1.0f / l_hi;
    float* olo = att + ((size_t)(b * Sq + ig_lo)) * DM + h * HD;
    float* ohi = att + ((size_t)(b * Sq + ig_hi)) * DM + h * HD;
#pragma unroll
    for (int f = 0; f < 8; f++) {
        int col0 = f * 8 + 2 * cc;
        *(float2*)(olo + col0) = make_float2(cf_tf32(of[f][0] * inv_lo), cf_tf32(of[f][1] * inv_lo));
        *(float2*)(ohi + col0) = make_float2(cf_tf32(of[f][2] * inv_hi), cf_tf32(of[f][3] * inv_hi));
    }
}

// ---------------- launcher ----------------
extern "C" void kernel_launch(void* const* d_in, const int* in_sizes, int n_in,
                              void* d_out, int out_size)
{
    const float* inputs = (const float*)d_in[0];
    const float* amask  = (const float*)d_in[1];
    const float* Wq     = (const float*)d_in[2];
    const float* Wk     = (const float*)d_in[3];
    const float* Wv     = (const float*)d_in[4];
    const float* Wo     = (const float*)d_in[5];
    const float* events = (const float*)d_in[6];
    float* out = (float*)d_out;

    float *q, *k, *v, *att, *ret, *sims, *wt, *ai;
    cudaGetSymbolAddress((void**)&q,    g_q);
    cudaGetSymbolAddress((void**)&k,    g_k);
    cudaGetSymbolAddress((void**)&v,    g_v);
    cudaGetSymbolAddress((void**)&att,  g_att);
    cudaGetSymbolAddress((void**)&ret,  g_ret);
    cudaGetSymbolAddress((void**)&sims, g_sims);
    cudaGetSymbolAddress((void**)&wt,   g_wt);
    cudaGetSymbolAddress((void**)&ai,   g_ai);

    cudaFuncSetAttribute(gemm_qkv,  cudaFuncAttributeMaxDynamicSharedMemorySize, GSMEM_BYTES);
    cudaFuncSetAttribute(gemm_o,    cudaFuncAttributeMaxDynamicSharedMemorySize, GSMEM_BYTES);
    cudaFuncSetAttribute(flash_mma, cudaFuncAttributeMaxDynamicSharedMemorySize, FSMEM_BYTES);

    prep_a<<<(Bq * Sq * DM) / (256 * 4), 256>>>(inputs, ai);
    transpose_w<<<dim3(32, 32, 4), 256>>>(Wq, Wk, Wv, Wo, wt);

    gemm_qkv<<<dim3(8, 32, 3), 256, GSMEM_BYTES>>>(ai, wt, q, k, v);

    retrieve_sims<<<dim3(125, Bq), 256>>>(k, events, sims);
    topk_gather<<<Bq, 256>>>(sims, events, ret);

    flash_mma<<<dim3(Sq / 128, Hh, Bq), 256, FSMEM_BYTES>>>(amask, q, k, v, ret, att);

    gemm_o<<<dim3(8, 32), 256, GSMEM_BYTES>>>(att, wt + 3 * (size_t)DM * DM, out);
}

// round 8
// speedup vs baseline: 1.9920x; 1.0354x over previous
#include <cuda_runtime.h>
#include <math.h>
#include <stdint.h>

// Problem constants
#define Bq   2
#define Sq   2048
#define DM   1024
#define Hh   16
#define HD   64
#define MEMN 1000
#define KTOT 10

// ---------------- device scratch ----------------
__device__ float g_q[Bq * Hh * Sq * HD];
__device__ float g_k[Bq * Hh * Sq * HD];
__device__ float g_v[Bq * Hh * Sq * HD];
__device__ float g_att[Bq * Sq * DM];
__device__ float g_ret[Bq * KTOT * DM];
__device__ float g_sims[Bq * MEMN];
__device__ float g_wt[4 * DM * DM];    // transposed + tf32-rounded weights
__device__ float g_ai[Bq * Sq * DM];   // tf32-rounded inputs
__device__ float g_klast[Bq * DM];     // UNROUNDED last-token key (retrieval)

// ---------------- helpers ----------------
__device__ __forceinline__ uint32_t smem_u32(const void* p) {
    uint32_t a;
    asm("{ .reg .u64 t; cvta.to.shared.u64 t, %1; cvt.u32.u64 %0, t; }" : "=r"(a) : "l"(p));
    return a;
}
__device__ __forceinline__ float cf_tf32(float x) {
    uint32_t u;
    asm("cvt.rna.tf32.f32 %0, %1;" : "=r"(u) : "f"(x));
    return __uint_as_float(u);
}
__device__ __forceinline__ void mma8(float* c, const uint32_t* a, const uint32_t* b) {
    asm("mma.sync.aligned.m16n8k8.row.col.f32.tf32.tf32.f32 "
        "{%0,%1,%2,%3},{%4,%5,%6,%7},{%8,%9},{%0,%1,%2,%3};"
        : "+f"(c[0]), "+f"(c[1]), "+f"(c[2]), "+f"(c[3])
        : "r"(a[0]), "r"(a[1]), "r"(a[2]), "r"(a[3]), "r"(b[0]), "r"(b[1]));
}
__device__ __forceinline__ void cpa16(uint32_t d, const void* g) {
    asm volatile("cp.async.cg.shared.global [%0], [%1], 16;" :: "r"(d), "l"(g) : "memory");
}
#define CP_COMMIT() asm volatile("cp.async.commit_group;" ::: "memory")
#define CP_WAIT0()  asm volatile("cp.async.wait_group 0;" ::: "memory")

// ---------------- prep: round inputs to tf32 in global ---------------------
__global__ __launch_bounds__(256) void prep_a(const float* __restrict__ A,
                                              float* __restrict__ D)
{
    size_t i = ((size_t)blockIdx.x * 256 + threadIdx.x) * 4;
    float4 t = *(const float4*)(A + i);
    *(float4*)(D + i) = make_float4(cf_tf32(t.x), cf_tf32(t.y), cf_tf32(t.z), cf_tf32(t.w));
}

// ---------------- weight transpose + tf32 round ----------------------------
__global__ __launch_bounds__(256) void transpose_w(const float* __restrict__ W0,
                                                   const float* __restrict__ W1,
                                                   const float* __restrict__ W2,
                                                   const float* __restrict__ W3,
                                                   float* __restrict__ WT)
{
    __shared__ float t[32][33];
    int z = blockIdx.z;
    const float* W = (z == 0) ? W0 : (z == 1) ? W1 : (z == 2) ? W2 : W3;
    float* D = WT + (size_t)z * DM * DM;
    int x = blockIdx.x * 32, y = blockIdx.y * 32;
    int tx = threadIdx.x & 31, ty = threadIdx.x >> 5;
    for (int r = ty; r < 32; r += 8)
        t[r][tx] = W[(size_t)(y + r) * DM + x + tx];
    __syncthreads();
    for (int r = ty; r < 32; r += 8)
        D[(size_t)(x + r) * DM + y + tx] = cf_tf32(t[tx][r]);
}

// ---------------- cp.async-pipelined tf32 mma.sync GEMM -------------------
#define GP      20
#define STGF    (128 * GP * 2)
#define NSTAGE  3
#define NIT     (DM / 16)
#define GSMEM_BYTES (NSTAGE * STGF * 4)

__device__ __forceinline__ void gemm_body(const float* __restrict__ A,
                                          const float* __restrict__ WT,
                                          float* __restrict__ C,
                                          int headwrite, float* klast, float* dsm)
{
    uint32_t sbase = smem_u32(dsm);
    int tid = threadIdx.x, lane = tid & 31, wid = tid >> 5;
    int wm = wid & 3, wn = wid >> 2;
    int m0 = blockIdx.y * 128, n0 = blockIdx.x * 128;
    int r = lane >> 2, c = lane & 3;

    int srow = tid >> 1, shalf = tid & 1;
    const float* gA = A  + (size_t)(m0 + srow) * DM + shalf * 8;
    const float* gB = WT + (size_t)(n0 + srow) * DM + shalf * 8;
    uint32_t dA = sbase + (uint32_t)(srow * GP + shalf * 8) * 4u;
    uint32_t dB = dA + (uint32_t)(128 * GP) * 4u;

    float acc[2][8][4];
#pragma unroll
    for (int i = 0; i < 2; i++)
#pragma unroll
        for (int j = 0; j < 8; j++)
#pragma unroll
            for (int t = 0; t < 4; t++) acc[i][j][t] = 0.f;

#pragma unroll
    for (int s = 0; s < NSTAGE - 1; s++) {
        uint32_t so = (uint32_t)(s * STGF) * 4u;
        cpa16(dA + so,      gA + s * 16);
        cpa16(dA + so + 16, gA + s * 16 + 4);
        cpa16(dB + so,      gB + s * 16);
        cpa16(dB + so + 16, gB + s * 16 + 4);
        CP_COMMIT();
    }

    for (int it = 0; it < NIT; ++it) {
        if (it + NSTAGE - 1 < NIT) {
            int s = it + NSTAGE - 1;
            uint32_t so = (uint32_t)((s % NSTAGE) * STGF) * 4u;
            cpa16(dA + so,      gA + s * 16);
            cpa16(dA + so + 16, gA + s * 16 + 4);
            cpa16(dB + so,      gB + s * 16);
            cpa16(dB + so + 16, gB + s * 16 + 4);
            CP_COMMIT();
        }
        if (it <= NIT - 3)      asm volatile("cp.async.wait_group 2;" ::: "memory");
        else if (it == NIT - 2) asm volatile("cp.async.wait_group 1;" ::: "memory");
        else                    asm volatile("cp.async.wait_group 0;" ::: "memory");
        __syncthreads();

        const float* As = dsm + (it % NSTAGE) * STGF;
        const float* Bs = As + 128 * GP;

#pragma unroll
        for (int ks = 0; ks < 16; ks += 8) {
            uint32_t af[2][4];
#pragma unroll
            for (int i = 0; i < 2; i++) {
                int row = wm * 32 + i * 16 + r;
                af[i][0] = __float_as_uint(As[row * GP + ks + c]);
                af[i][1] = __float_as_uint(As[(row + 8) * GP + ks + c]);
                af[i][2] = __float_as_uint(As[row * GP + ks + c + 4]);
                af[i][3] = __float_as_uint(As[(row + 8) * GP + ks + c + 4]);
            }
            uint32_t bf[8][2];
#pragma unroll
            for (int j = 0; j < 8; j++) {
                int nr = wn * 64 + j * 8 + r;
                bf[j][0] = __float_as_uint(Bs[nr * GP + ks + c]);
                bf[j][1] = __float_as_uint(Bs[nr * GP + ks + c + 4]);
            }
#pragma unroll
            for (int i = 0; i < 2; i++)
#pragma unroll
                for (int j = 0; j < 8; j++) mma8(acc[i][j], af[i], bf[j]);
        }
        __syncthreads();
    }

    int c2 = (lane & 3) * 2;
#pragma unroll
    for (int i = 0; i < 2; i++) {
#pragma unroll
        for (int j = 0; j < 8; j++) {
            int row0 = m0 + wm * 32 + i * 16 + r;
            int col  = n0 + wn * 64 + j * 8 + c2;
            if (headwrite) {
                // q/k/v are consumed as tf32 downstream: store rounded
                float2 lo = make_float2(cf_tf32(acc[i][j][0]), cf_tf32(acc[i][j][1]));
                float2 hi = make_float2(cf_tf32(acc[i][j][2]), cf_tf32(acc[i][j][3]));
                int b = row0 >> 11, h = col >> 6, hd = col & 63;
                int s0 = row0 & 2047;
                float* base = C + (((size_t)(b * Hh + h)) * Sq) * HD + hd;
                *(float2*)(base + (size_t)s0 * HD)       = lo;
                *(float2*)(base + (size_t)(s0 + 8) * HD) = hi;
                // keep an UNROUNDED copy of the last-token key for retrieval
                if (klast && s0 + 8 == Sq - 1)
                    *(float2*)&klast[b * DM + col] = make_float2(acc[i][j][2], acc[i][j][3]);
            } else {
                *(float2*)&C[(size_t)row0 * DM + col] =
                    make_float2(acc[i][j][0], acc[i][j][1]);
                *(float2*)&C[(size_t)(row0 + 8) * DM + col] =
                    make_float2(acc[i][j][2], acc[i][j][3]);
            }
        }
    }
}

__global__ void __launch_bounds__(256, 2) gemm_qkv(const float* __restrict__ A,
                                                   const float* __restrict__ WT,
                                                   float* q, float* k, float* v,
                                                   float* klast)
{
    extern __shared__ float dsm[];
    int z = blockIdx.z;
    float* C = (z == 0) ? q : (z == 1) ? k : v;
    gemm_body(A, WT + (size_t)z * DM * DM, C, 1, (z == 1) ? klast : (float*)0, dsm);
}

__global__ void __launch_bounds__(256, 2) gemm_o(const float* __restrict__ A,
                                                 const float* __restrict__ WT,
                                                 float* __restrict__ C)
{
    extern __shared__ float dsm[];
    gemm_body(A, WT, C, 0, (float*)0, dsm);
}

// ---------------- retrieval: sims (warp per event) ------------------------
__global__ __launch_bounds__(256) void retrieve_sims(const float* __restrict__ klast,
                                                     const float* __restrict__ events,
                                                     float* __restrict__ sims)
{
    int b = blockIdx.y;
    int tid = threadIdx.x;
    int lane = tid & 31, wid = tid >> 5;
    __shared__ float qs[DM];
    __shared__ float qn_s;

    for (int d = tid; d < DM; d += 256) qs[d] = klast[b * DM + d];
    __syncthreads();
    if (wid == 0) {
        float ps = 0.f;
        for (int d = lane * 4; d < DM; d += 128) {
            float4 t = *(const float4*)&qs[d];
            ps += t.x * t.x + t.y * t.y + t.z * t.z + t.w * t.w;
        }
#pragma unroll
        for (int off = 16; off > 0; off >>= 1) ps += __shfl_down_sync(0xffffffffu, ps, off);
        if (lane == 0) qn_s = sqrtf(ps) + 1e-8f;
    }
    __syncthreads();
    float qnorm = qn_s;

    int e = blockIdx.x * 8 + wid;
    if (e >= MEMN) return;
    const float* ep = events + (size_t)e * DM;
    float dot = 0.f, nn = 0.f;
    for (int d = lane * 4; d < DM; d += 128) {
        float4 ev = *(const float4*)(ep + d);
        float4 qv = *(const float4*)&qs[d];
        dot += qv.x * ev.x + qv.y * ev.y + qv.z * ev.z + qv.w * ev.w;
        nn  += ev.x * ev.x + ev.y * ev.y + ev.z * ev.z + ev.w * ev.w;
    }
#pragma unroll
    for (int off = 16; off > 0; off >>= 1) {
        dot += __shfl_down_sync(0xffffffffu, dot, off);
        nn  += __shfl_down_sync(0xffffffffu, nn, off);
    }
    if (lane == 0) sims[b * MEMN + e] = dot / (qnorm * (sqrtf(nn) + 1e-8f));
}

// ---------------- retrieval: parallel top-k + gather (tf32-rounded) --------
__global__ __launch_bounds__(256) void topk_gather(const float* __restrict__ sims,
                                                   const float* __restrict__ events,
                                                   float* __restrict__ ret)
{
    int b = blockIdx.x;
    int tid = threadIdx.x;
    int lane = tid & 31, wid = tid >> 5;
    __shared__ float sv[MEMN];
    __shared__ float wmax[8];
    __shared__ int   widx[8];
    __shared__ int   tidx[KTOT];

    for (int e = tid; e < MEMN; e += 256) sv[e] = sims[b * MEMN + e];
    __syncthreads();

    for (int kk = 0; kk < KTOT; kk++) {
        float bm = -1e30f; int bi = MEMN;
        for (int e = tid; e < MEMN; e += 256) {
            float v = sv[e];
            if (v > bm || (v == bm && e < bi)) { bm = v; bi = e; }
        }
#pragma unroll
        for (int off = 16; off > 0; off >>= 1) {
            float om = __shfl_down_sync(0xffffffffu, bm, off);
            int   oi = __shfl_down_sync(0xffffffffu, bi, off);
            if (om > bm || (om == bm && oi < bi)) { bm = om; bi = oi; }
        }
        if (lane == 0) { wmax[wid] = bm; widx[wid] = bi; }
        __syncthreads();
        if (tid == 0) {
            float gm = wmax[0]; int gi = widx[0];
            for (int w = 1; w < 8; w++) {
                if (wmax[w] > gm || (wmax[w] == gm && widx[w] < gi)) { gm = wmax[w]; gi = widx[w]; }
            }
            tidx[kk] = gi;
            sv[gi] = -1e30f;
        }
        __syncthreads();
    }

    for (int kk = 0; kk < KTOT; kk++) {
        int src = tidx[kk];
        for (int d = tid; d < DM; d += 256)
            ret[((size_t)b * KTOT + kk) * DM + d] = cf_tf32(events[(size_t)src * DM + d]);
    }
}

// ---------------- flash attention v5: cp.async staging, no V transpose -----
// 256 threads / 8 warps, 128 q-rows per CTA, key tiles of 64.
// All tensors pre-rounded tf32 in global -> staging is raw cp.async.
#define FST    68
#define VST    72
#define OFF_SQ 0
#define OFF_SP (128 * FST)
#define OFF_KS (OFF_SP + 128 * FST)
#define OFF_VS (OFF_KS + 64 * FST)
#define OFF_MK (OFF_VS + 64 * VST)
#define FSMEM_FLOATS (OFF_MK + 64)
#define FSMEM_BYTES  (FSMEM_FLOATS * 4)

__global__ void __launch_bounds__(256, 2) flash_mma(const float* __restrict__ amask,
                                                    const float* __restrict__ qbuf,
                                                    const float* __restrict__ kbuf,
                                                    const float* __restrict__ vbuf,
                                                    const float* __restrict__ ret,
                                                    float* __restrict__ att)
{
    extern __shared__ float fsm[];
    float* SQ = fsm + OFF_SQ;     // Q (tf32) — persistent
    float* SP = fsm + OFF_SP;     // P (tf32)
    float* Ks = fsm + OFF_KS;     // K tile [key][dim], stride 68
    float* Vs = fsm + OFF_VS;     // V tile [key][dim], stride 72 (conflict-free B loads)
    float* mk = fsm + OFF_MK;
    uint32_t sbase = smem_u32(fsm);

    int qt = gridDim.x - 1 - blockIdx.x;   // heavy tiles first
    int h = blockIdx.y, b = blockIdx.z;
    int tid = threadIdx.x;
    int lane = tid & 31, w = tid >> 5;
    int r = lane >> 2, cc = lane & 3;
    int i0 = qt * 128;
    const float scale = 0.125f;
    float slope = exp2f(-0.5f * (float)(h + 1));

    const float* qbase = qbuf + ((size_t)(b * Hh + h)) * Sq * HD;
    const float* kbase = kbuf + ((size_t)(b * Hh + h)) * Sq * HD;
    const float* vbase = vbuf + ((size_t)(b * Hh + h)) * Sq * HD;

    // ---- stage Q via cp.async (already tf32) ----
    {
        int row = tid >> 1, h32 = (tid & 1) * 32;
        const float* qp = qbase + (size_t)(i0 + row) * HD + h32;
        uint32_t dst = sbase + (uint32_t)(OFF_SQ + row * FST + h32) * 4u;
#pragma unroll
        for (int i = 0; i < 8; i++) cpa16(dst + i * 16, qp + i * 4);
        CP_COMMIT();
    }

    int row_lo = w * 16 + r, row_hi = row_lo + 8;
    int ig_lo = i0 + row_lo, ig_hi = i0 + row_hi;

    float of[8][4];
#pragma unroll
    for (int f = 0; f < 8; f++)
#pragma unroll
        for (int e = 0; e < 4; e++) of[f][e] = 0.f;

    float m_lo = -1e30f, m_hi = -1e30f, l_lo = 0.f, l_hi = 0.f;

    int kk_s = tid >> 2, part_s = (tid & 3) * 16;
    uint32_t dK = sbase + (uint32_t)(OFF_KS + kk_s * FST + part_s) * 4u;
    uint32_t dV = sbase + (uint32_t)(OFF_VS + kk_s * VST + part_s) * 4u;

    int ntiles = 2 * qt + 3;
    for (int t = 0; t < ntiles; ++t) {
        int j0 = t * 64 - 10;
        // ---- stage K/V via cp.async ----
        {
            const float *kp, *vp;
            if (t == 0 && kk_s < KTOT) {
                kp = ret + ((size_t)b * KTOT + kk_s) * DM + h * HD + part_s;
                vp = kp;
            } else {
                int jg = j0 + kk_s;
                if (jg > Sq - 1) jg = Sq - 1;
                kp = kbase + (size_t)jg * HD + part_s;
                vp = vbase + (size_t)jg * HD + part_s;
            }
#pragma unroll
            for (int i = 0; i < 4; i++) {
                cpa16(dK + i * 16, kp + i * 4);
                cpa16(dV + i * 16, vp + i * 4);
            }
            CP_COMMIT();
            if (tid < 64) {
                int jg = j0 + tid;
                if (jg < 0) jg = 0;
                if (jg > Sq - 1) jg = Sq - 1;
                mk[tid] = (t == 0 && tid < KTOT) ? 1.0f : amask[b * Sq + jg];
            }
        }
        CP_WAIT0();
        __syncthreads();

        // ---- S = Q K^T via mma.sync ----
        float sc[8][4];
#pragma unroll
        for (int f = 0; f < 8; f++)
#pragma unroll
            for (int e = 0; e < 4; e++) sc[f][e] = 0.f;
#pragma unroll
        for (int ks = 0; ks < 8; ks++) {
            uint32_t aq[4];
            aq[0] = __float_as_uint(SQ[row_lo * FST + ks * 8 + cc]);
            aq[1] = __float_as_uint(SQ[row_hi * FST + ks * 8 + cc]);
            aq[2] = __float_as_uint(SQ[row_lo * FST + ks * 8 + cc + 4]);
            aq[3] = __float_as_uint(SQ[row_hi * FST + ks * 8 + cc + 4]);
#pragma unroll
            for (int f = 0; f < 8; f++) {
                uint32_t bb[2];
                bb[0] = __float_as_uint(Ks[(f * 8 + r) * FST + ks * 8 + cc]);
                bb[1] = __float_as_uint(Ks[(f * 8 + r) * FST + ks * 8 + cc + 4]);
                mma8(sc[f], aq, bb);
            }
        }

        // ---- bias + causal + mask, tile max ----
        float tmax_lo = m_lo, tmax_hi = m_hi;
#pragma unroll
        for (int f = 0; f < 8; f++) {
            int col0 = f * 8 + 2 * cc;
            int col1 = col0 + 1;
            int jg0 = j0 + col0, jg1 = j0 + col1;
            bool mem0 = (t == 0) && (col0 < KTOT);
            bool mem1 = (t == 0) && (col1 < KTOT);
            float pen0 = (1.0f - mk[col0]) * (-1e9f);
            float pen1 = (1.0f - mk[col1]) * (-1e9f);
            float s;
            s = sc[f][0] * scale + (mem0 ? 0.f : slope * (float)(ig_lo - jg0) + pen0);
            if (!mem0 && jg0 > ig_lo) s = -1e30f;
            sc[f][0] = s; tmax_lo = fmaxf(tmax_lo, s);
            s = sc[f][1] * scale + (mem1 ? 0.f : slope * (float)(ig_lo - jg1) + pen1);
            if (!mem1 && jg1 > ig_lo) s = -1e30f;
            sc[f][1] = s; tmax_lo = fmaxf(tmax_lo, s);
            s = sc[f][2] * scale + (mem0 ? 0.f : slope * (float)(ig_hi - jg0) + pen0);
            if (!mem0 && jg0 > ig_hi) s = -1e30f;
            sc[f][2] = s; tmax_hi = fmaxf(tmax_hi, s);
            s = sc[f][3] * scale + (mem1 ? 0.f : slope * (float)(ig_hi - jg1) + pen1);
            if (!mem1 && jg1 > ig_hi) s = -1e30f;
            sc[f][3] = s; tmax_hi = fmaxf(tmax_hi, s);
        }
        tmax_lo = fmaxf(tmax_lo, __shfl_xor_sync(0xffffffffu, tmax_lo, 1));
        tmax_lo = fmaxf(tmax_lo, __shfl_xor_sync(0xffffffffu, tmax_lo, 2));
        tmax_hi = fmaxf(tmax_hi, __shfl_xor_sync(0xffffffffu, tmax_hi, 1));
        tmax_hi = fmaxf(tmax_hi, __shfl_xor_sync(0xffffffffu, tmax_hi, 2));

        float corr_lo = __expf(m_lo - tmax_lo);
        float corr_hi = __expf(m_hi - tmax_hi);
        l_lo *= corr_lo; l_hi *= corr_hi;
        m_lo = tmax_lo;  m_hi = tmax_hi;

        float sl = 0.f, sh = 0.f;
#pragma unroll
        for (int f = 0; f < 8; f++) {
            sc[f][0] = __expf(sc[f][0] - m_lo); sl += sc[f][0];
            sc[f][1] = __expf(sc[f][1] - m_lo); sl += sc[f][1];
            sc[f][2] = __expf(sc[f][2] - m_hi); sh += sc[f][2];
            sc[f][3] = __expf(sc[f][3] - m_hi); sh += sc[f][3];
        }
        sl += __shfl_xor_sync(0xffffffffu, sl, 1);
        sl += __shfl_xor_sync(0xffffffffu, sl, 2);
        sh += __shfl_xor_sync(0xffffffffu, sh, 1);
        sh += __shfl_xor_sync(0xffffffffu, sh, 2);
        l_lo += sl; l_hi += sh;

#pragma unroll
        for (int f = 0; f < 8; f++) {
            of[f][0] *= corr_lo; of[f][1] *= corr_lo;
            of[f][2] *= corr_hi; of[f][3] *= corr_hi;
        }

        // ---- write P (tf32) to warp-exclusive SP rows ----
#pragma unroll
        for (int f = 0; f < 8; f++) {
            int col0 = f * 8 + 2 * cc;
            *(float2*)&SP[row_lo * FST + col0] = make_float2(cf_tf32(sc[f][0]), cf_tf32(sc[f][1]));
            *(float2*)&SP[row_hi * FST + col0] = make_float2(cf_tf32(sc[f][2]), cf_tf32(sc[f][3]));
        }
        __syncwarp();

        // ---- O += P V via mma.sync (B direct from row-major Vs) ----
#pragma unroll
        for (int ks = 0; ks < 8; ks++) {
            uint32_t ap[4];
            ap[0] = __float_as_uint(SP[row_lo * FST + ks * 8 + cc]);
            ap[1] = __float_as_uint(SP[row_hi * FST + ks * 8 + cc]);
            ap[2] = __float_as_uint(SP[row_lo * FST + ks * 8 + cc + 4]);
            ap[3] = __float_as_uint(SP[row_hi * FST + ks * 8 + cc + 4]);
#pragma unroll
            for (int f = 0; f < 8; f++) {
                uint32_t bv[2];
                bv[0] = __float_as_uint(Vs[(ks * 8 + cc) * VST + f * 8 + r]);
                bv[1] = __float_as_uint(Vs[(ks * 8 + cc + 4) * VST + f * 8 + r]);
                mma8(of[f], ap, bv);
            }
        }
        __syncthreads();
    }

    // ---- finalize: divide by l, tf32-round (next GEMM input), store ----
    float inv_lo = 1.0f / l_lo, inv_hi = 1.0f / l_hi;
    float* olo = att + ((size_t)(b * Sq + ig_lo)) * DM + h * HD;
    float* ohi = att + ((size_t)(b * Sq + ig_hi)) * DM + h * HD;
#pragma unroll
    for (int f = 0; f < 8; f++) {
        int col0 = f * 8 + 2 * cc;
        *(float2*)(olo + col0) = make_float2(cf_tf32(of[f][0] * inv_lo), cf_tf32(of[f][1] * inv_lo));
        *(float2*)(ohi + col0) = make_float2(cf_tf32(of[f][2] * inv_hi), cf_tf32(of[f][3] * inv_hi));
    }
}

// ---------------- launcher ----------------
extern "C" void kernel_launch(void* const* d_in, const int* in_sizes, int n_in,
                              void* d_out, int out_size)
{
    const float* inputs = (const float*)d_in[0];
    const float* amask  = (const float*)d_in[1];
    const float* Wq     = (const float*)d_in[2];
    const float* Wk     = (const float*)d_in[3];
    const float* Wv     = (const float*)d_in[4];
    const float* Wo     = (const float*)d_in[5];
    const float* events = (const float*)d_in[6];
    float* out = (float*)d_out;

    float *q, *k, *v, *att, *ret, *sims, *wt, *ai, *klast;
    cudaGetSymbolAddress((void**)&q,     g_q);
    cudaGetSymbolAddress((void**)&k,     g_k);
    cudaGetSymbolAddress((void**)&v,     g_v);
    cudaGetSymbolAddress((void**)&att,   g_att);
    cudaGetSymbolAddress((void**)&ret,   g_ret);
    cudaGetSymbolAddress((void**)&sims,  g_sims);
    cudaGetSymbolAddress((void**)&wt,    g_wt);
    cudaGetSymbolAddress((void**)&ai,    g_ai);
    cudaGetSymbolAddress((void**)&klast, g_klast);

    cudaFuncSetAttribute(gemm_qkv,  cudaFuncAttributeMaxDynamicSharedMemorySize, GSMEM_BYTES);
    cudaFuncSetAttribute(gemm_o,    cudaFuncAttributeMaxDynamicSharedMemorySize, GSMEM_BYTES);
    cudaFuncSetAttribute(flash_mma, cudaFuncAttributeMaxDynamicSharedMemorySize, FSMEM_BYTES);

    prep_a<<<(Bq * Sq * DM) / (256 * 4), 256>>>(inputs, ai);
    transpose_w<<<dim3(32, 32, 4), 256>>>(Wq, Wk, Wv, Wo, wt);

    gemm_qkv<<<dim3(8, 32, 3), 256, GSMEM_BYTES>>>(ai, wt, q, k, v, klast);

    retrieve_sims<<<dim3(125, Bq), 256>>>(klast, events, sims);
    topk_gather<<<Bq, 256>>>(sims, events, ret);

    flash_mma<<<dim3(Sq / 128, Hh, Bq), 256, FSMEM_BYTES>>>(amask, q, k, v, ret, att);

    gemm_o<<<dim3(8, 32), 256, GSMEM_BYTES>>>(att, wt + 3 * (size_t)DM * DM, out);
}

// round 9
// speedup vs baseline: 2.3517x; 1.1806x over previous
#include <cuda_runtime.h>
#include <math.h>
#include <stdint.h>

// Problem constants
#define Bq   2
#define Sq   2048
#define DM   1024
#define Hh   16
#define HD   64
#define MEMN 1000
#define KTOT 10

// ---------------- device scratch ----------------
__device__ float g_q[Bq * Hh * Sq * HD];
__device__ float g_k[Bq * Hh * Sq * HD];
__device__ float g_v[Bq * Hh * Sq * HD];
__device__ float g_att[Bq * Sq * DM];   // FRAG-MAJOR (written by flash, read by gemm_o)
__device__ float g_ret[Bq * KTOT * DM];
__device__ float g_sims[Bq * MEMN];
__device__ float g_wt[4 * DM * DM];     // FRAG-MAJOR tf32 weights (B operand)
__device__ float g_ai[Bq * Sq * DM];    // FRAG-MAJOR tf32 inputs (A operand)
__device__ float g_klast[Bq * DM];      // UNROUNDED last-token key (retrieval)

// ---------------- helpers ----------------
__device__ __forceinline__ uint32_t smem_u32(const void* p) {
    uint32_t a;
    asm("{ .reg .u64 t; cvta.to.shared.u64 t, %1; cvt.u32.u64 %0, t; }" : "=r"(a) : "l"(p));
    return a;
}
__device__ __forceinline__ float cf_tf32(float x) {
    uint32_t u;
    asm("cvt.rna.tf32.f32 %0, %1;" : "=r"(u) : "f"(x));
    return __uint_as_float(u);
}
__device__ __forceinline__ void mma8(float* c, const uint32_t* a, const uint32_t* b) {
    asm("mma.sync.aligned.m16n8k8.row.col.f32.tf32.tf32.f32 "
        "{%0,%1,%2,%3},{%4,%5,%6,%7},{%8,%9},{%0,%1,%2,%3};"
        : "+f"(c[0]), "+f"(c[1]), "+f"(c[2]), "+f"(c[3])
        : "r"(a[0]), "r"(a[1]), "r"(a[2]), "r"(a[3]), "r"(b[0]), "r"(b[1]));
}
__device__ __forceinline__ void cpa16(uint32_t d, const void* g) {
    asm volatile("cp.async.cg.shared.global [%0], [%1], 16;" :: "r"(d), "l"(g) : "memory");
}
#define CP_COMMIT() asm volatile("cp.async.commit_group;" ::: "memory")
#define CP_WAIT0()  asm volatile("cp.async.wait_group 0;" ::: "memory")

// A-operand frag-major index: tile (m/16, k/8), lane (m%8)*4+(k%4), elem (m/8)%2 + 2*((k/4)%2)
__device__ __forceinline__ size_t fragidxA(int m, int k) {
    return ((((size_t)(m >> 4)) * (DM / 8) + (k >> 3)) * 32 + ((m & 7) * 4 + (k & 3))) * 4
           + ((m >> 3) & 1) + 2 * ((k >> 2) & 1);
}

// ---------------- prep: inputs -> frag-major tf32 --------------------------
__global__ __launch_bounds__(256) void prep_a(const float* __restrict__ A,
                                              float* __restrict__ D)
{
    int gt = blockIdx.x * 256 + threadIdx.x;     // one thread per (tile, lane)
    int tile = gt >> 5, lane = gt & 31;
    int mt = tile >> 7, kt = tile & 127;
    int m = mt * 16 + (lane >> 2), k = kt * 8 + (lane & 3);
    float4 o;
    o.x = cf_tf32(A[(size_t)m * DM + k]);
    o.y = cf_tf32(A[(size_t)(m + 8) * DM + k]);
    o.z = cf_tf32(A[(size_t)m * DM + k + 4]);
    o.w = cf_tf32(A[(size_t)(m + 8) * DM + k + 4]);
    ((float4*)D)[gt] = o;
}

// ---------------- weights -> frag-major tf32 B operand ---------------------
// B frag for col-major mma operand: tile (n/8, k/8), lane (n%8)*4+(k%4), elem (k/4)%2
__global__ __launch_bounds__(256) void transpose_w(const float* __restrict__ W0,
                                                   const float* __restrict__ W1,
                                                   const float* __restrict__ W2,
                                                   const float* __restrict__ W3,
                                                   float* __restrict__ WT)
{
    __shared__ float t[32][33];
    int z = blockIdx.z;
    const float* W = (z == 0) ? W0 : (z == 1) ? W1 : (z == 2) ? W2 : W3;
    float* D = WT + (size_t)z * DM * DM;
    int x = blockIdx.x * 32, y = blockIdx.y * 32;   // x = n0, y = k0
    int tid = threadIdx.x;
    int tx = tid & 31, ty = tid >> 5;
    for (int r = ty; r < 32; r += 8)
        t[r][tx] = W[(size_t)(y + r) * DM + x + tx];   // t[k_local][n_local]
    __syncthreads();
    for (int p = tid; p < 512; p += 256) {
        int ttile = p >> 5, lane = p & 31;
        int nt_l = ttile >> 2, kt_l = ttile & 3;
        int n_l = nt_l * 8 + (lane >> 2), k_l = kt_l * 8 + (lane & 3);
        float2 o = make_float2(cf_tf32(t[k_l][n_l]), cf_tf32(t[k_l + 4][n_l]));
        ((float2*)D)[((size_t)((x >> 3) + nt_l) * (DM / 8) + (y >> 3) + kt_l) * 32 + lane] = o;
    }
}

// ---------------- frag-major cp.async tf32 mma.sync GEMM -------------------
// CTA 128x128x16/iter, 3 stages, stage = 16 KB (A 8KB blocks of 512B, B 8KB blocks of 256B)
#define NSTAGE  3
#define NIT     (DM / 16)
#define STG_B   16384
#define GSMEM_BYTES (NSTAGE * STG_B)

__device__ __forceinline__ void gemm_body(const float* __restrict__ A,
                                          const float* __restrict__ WT,
                                          float* __restrict__ C,
                                          int headwrite, float* klast, float* dsm)
{
    uint32_t sbase = smem_u32(dsm);
    int tid = threadIdx.x, lane = tid & 31, wid = tid >> 5;
    int wm = wid & 3, wn = wid >> 2;
    int m0 = blockIdx.y * 128, n0 = blockIdx.x * 128;
    int r = lane >> 2;

    // staging map: A = 16 blocks x 512B, B = 32 blocks x 256B
    int bia = tid >> 4, offa = (tid & 15) * 16;     // A: thread -> block, 2x16B (offa, offa+256)
    int bib = tid >> 3, offb = (tid & 7) * 32;      // B: thread -> block, 2x16B (offb, offb+16)
    int amt = bia >> 1, akt = bia & 1;
    int bnt = bib >> 1, bkt = bib & 1;

    const float* gA = A  + ((size_t)((m0 >> 4) + amt) * 128 + akt) * 128 + (offa >> 2);
    const float* gB = WT + ((size_t)((n0 >> 3) + bnt) * 128 + bkt) * 64  + (offb >> 2);
    uint32_t dA = sbase + (uint32_t)(bia * 512 + offa);
    uint32_t dB = sbase + 8192u + (uint32_t)(bib * 256 + offb);

    float acc[2][8][4];
#pragma unroll
    for (int i = 0; i < 2; i++)
#pragma unroll
        for (int j = 0; j < 8; j++)
#pragma unroll
            for (int t = 0; t < 4; t++) acc[i][j][t] = 0.f;

#pragma unroll
    for (int s = 0; s < NSTAGE - 1; s++) {
        uint32_t so = (uint32_t)s * STG_B;
        cpa16(dA + so,       gA + (size_t)s * 256);
        cpa16(dA + so + 256, gA + (size_t)s * 256 + 64);
        cpa16(dB + so,       gB + (size_t)s * 128);
        cpa16(dB + so + 16,  gB + (size_t)s * 128 + 4);
        CP_COMMIT();
    }

    for (int it = 0; it < NIT; ++it) {
        if (it + NSTAGE - 1 < NIT) {
            int s = it + NSTAGE - 1;
            uint32_t so = (uint32_t)(s % NSTAGE) * STG_B;
            cpa16(dA + so,       gA + (size_t)s * 256);
            cpa16(dA + so + 256, gA + (size_t)s * 256 + 64);
            cpa16(dB + so,       gB + (size_t)s * 128);
            cpa16(dB + so + 16,  gB + (size_t)s * 128 + 4);
            CP_COMMIT();
        }
        if (it <= NIT - 3)      asm volatile("cp.async.wait_group 2;" ::: "memory");
        else if (it == NIT - 2) asm volatile("cp.async.wait_group 1;" ::: "memory");
        else                    asm volatile("cp.async.wait_group 0;" ::: "memory");
        __syncthreads();

        const uint4* As4 = (const uint4*)(dsm + (it % NSTAGE) * (STG_B / 4));
        const uint2* Bs2 = (const uint2*)(dsm + (it % NSTAGE) * (STG_B / 4) + 2048);

#pragma unroll
        for (int ks8 = 0; ks8 < 2; ks8++) {
            uint4 af[2];
#pragma unroll
            for (int i = 0; i < 2; i++)
                af[i] = As4[((wm * 2 + i) * 2 + ks8) * 32 + lane];
            uint2 bf[8];
#pragma unroll
            for (int j = 0; j < 8; j++)
                bf[j] = Bs2[((wn * 8 + j) * 2 + ks8) * 32 + lane];
#pragma unroll
            for (int i = 0; i < 2; i++)
#pragma unroll
                for (int j = 0; j < 8; j++)
                    mma8(acc[i][j], (const uint32_t*)&af[i], (const uint32_t*)&bf[j]);
        }
        __syncthreads();
    }

    int c2 = (lane & 3) * 2;
#pragma unroll
    for (int i = 0; i < 2; i++) {
#pragma unroll
        for (int j = 0; j < 8; j++) {
            int row0 = m0 + wm * 32 + i * 16 + r;
            int col  = n0 + wn * 64 + j * 8 + c2;
            if (headwrite) {
                float2 lo = make_float2(cf_tf32(acc[i][j][0]), cf_tf32(acc[i][j][1]));
                float2 hi = make_float2(cf_tf32(acc[i][j][2]), cf_tf32(acc[i][j][3]));
                int b = row0 >> 11, h = col >> 6, hd = col & 63;
                int s0 = row0 & 2047;
                float* base = C + (((size_t)(b * Hh + h)) * Sq) * HD + hd;
                *(float2*)(base + (size_t)s0 * HD)       = lo;
                *(float2*)(base + (size_t)(s0 + 8) * HD) = hi;
                if (klast && s0 + 8 == Sq - 1)
                    *(float2*)&klast[b * DM + col] = make_float2(acc[i][j][2], acc[i][j][3]);
            } else {
                *(float2*)&C[(size_t)row0 * DM + col] =
                    make_float2(acc[i][j][0], acc[i][j][1]);
                *(float2*)&C[(size_t)(row0 + 8) * DM + col] =
                    make_float2(acc[i][j][2], acc[i][j][3]);
            }
        }
    }
}

__global__ void __launch_bounds__(256, 2) gemm_qkv(const float* __restrict__ A,
                                                   const float* __restrict__ WT,
                                                   float* q, float* k, float* v,
                                                   float* klast)
{
    extern __shared__ float dsm[];
    int z = blockIdx.z;
    float* C = (z == 0) ? q : (z == 1) ? k : v;
    gemm_body(A, WT + (size_t)z * DM * DM, C, 1, (z == 1) ? klast : (float*)0, dsm);
}

__global__ void __launch_bounds__(256, 2) gemm_o(const float* __restrict__ A,
                                                 const float* __restrict__ WT,
                                                 float* __restrict__ C)
{
    extern __shared__ float dsm[];
    gemm_body(A, WT, C, 0, (float*)0, dsm);
}

// ---------------- retrieval: sims (warp per event) ------------------------
__global__ __launch_bounds__(256) void retrieve_sims(const float* __restrict__ klast,
                                                     const float* __restrict__ events,
                                                     float* __restrict__ sims)
{
    int b = blockIdx.y;
    int tid = threadIdx.x;
    int lane = tid & 31, wid = tid >> 5;
    __shared__ float qs[DM];
    __shared__ float qn_s;

    for (int d = tid; d < DM; d += 256) qs[d] = klast[b * DM + d];
    __syncthreads();
    if (wid == 0) {
        float ps = 0.f;
        for (int d = lane * 4; d < DM; d += 128) {
            float4 t = *(const float4*)&qs[d];
            ps += t.x * t.x + t.y * t.y + t.z * t.z + t.w * t.w;
        }
#pragma unroll
        for (int off = 16; off > 0; off >>= 1) ps += __shfl_down_sync(0xffffffffu, ps, off);
        if (lane == 0) qn_s = sqrtf(ps) + 1e-8f;
    }
    __syncthreads();
    float qnorm = qn_s;

    int e = blockIdx.x * 8 + wid;
    if (e >= MEMN) return;
    const float* ep = events + (size_t)e * DM;
    float dot = 0.f, nn = 0.f;
    for (int d = lane * 4; d < DM; d += 128) {
        float4 ev = *(const float4*)(ep + d);
        float4 qv = *(const float4*)&qs[d];
        dot += qv.x * ev.x + qv.y * ev.y + qv.z * ev.z + qv.w * ev.w;
        nn  += ev.x * ev.x + ev.y * ev.y + ev.z * ev.z + ev.w * ev.w;
    }
#pragma unroll
    for (int off = 16; off > 0; off >>= 1) {
        dot += __shfl_down_sync(0xffffffffu, dot, off);
        nn  += __shfl_down_sync(0xffffffffu, nn, off);
    }
    if (lane == 0) sims[b * MEMN + e] = dot / (qnorm * (sqrtf(nn) + 1e-8f));
}

// ---------------- retrieval: parallel top-k + gather (tf32-rounded) --------
__global__ __launch_bounds__(256) void topk_gather(const float* __restrict__ sims,
                                                   const float* __restrict__ events,
                                                   float* __restrict__ ret)
{
    int b = blockIdx.x;
    int tid = threadIdx.x;
    int lane = tid & 31, wid = tid >> 5;
    __shared__ float sv[MEMN];
    __shared__ float wmax[8];
    __shared__ int   widx[8];
    __shared__ int   tidx[KTOT];

    for (int e = tid; e < MEMN; e += 256) sv[e] = sims[b * MEMN + e];
    __syncthreads();

    for (int kk = 0; kk < KTOT; kk++) {
        float bm = -1e30f; int bi = MEMN;
        for (int e = tid; e < MEMN; e += 256) {
            float v = sv[e];
            if (v > bm || (v == bm && e < bi)) { bm = v; bi = e; }
        }
#pragma unroll
        for (int off = 16; off > 0; off >>= 1) {
            float om = __shfl_down_sync(0xffffffffu, bm, off);
            int   oi = __shfl_down_sync(0xffffffffu, bi, off);
            if (om > bm || (om == bm && oi < bi)) { bm = om; bi = oi; }
        }
        if (lane == 0) { wmax[wid] = bm; widx[wid] = bi; }
        __syncthreads();
        if (tid == 0) {
            float gm = wmax[0]; int gi = widx[0];
            for (int w = 1; w < 8; w++) {
                if (wmax[w] > gm || (wmax[w] == gm && widx[w] < gi)) { gm = wmax[w]; gi = widx[w]; }
            }
            tidx[kk] = gi;
            sv[gi] = -1e30f;
        }
        __syncthreads();
    }

    for (int kk = 0; kk < KTOT; kk++) {
        int src = tidx[kk];
        for (int d = tid; d < DM; d += 256)
            ret[((size_t)b * KTOT + kk) * DM + d] = cf_tf32(events[(size_t)src * DM + d]);
    }
}

// ---------------- flash attention: cp.async staging, MMA QK+PV -------------
#define FST    68
#define VST    72
#define OFF_SQ 0
#define OFF_SP (128 * FST)
#define OFF_KS (OFF_SP + 128 * FST)
#define OFF_VS (OFF_KS + 64 * FST)
#define OFF_MK (OFF_VS + 64 * VST)
#define FSMEM_FLOATS (OFF_MK + 64)
#define FSMEM_BYTES  (FSMEM_FLOATS * 4)

__global__ void __launch_bounds__(256, 2) flash_mma(const float* __restrict__ amask,
                                                    const float* __restrict__ qbuf,
                                                    const float* __restrict__ kbuf,
                                                    const float* __restrict__ vbuf,
                                                    const float* __restrict__ ret,
                                                    float* __restrict__ att)
{
    extern __shared__ float fsm[];
    float* SQ = fsm + OFF_SQ;
    float* SP = fsm + OFF_SP;
    float* Ks = fsm + OFF_KS;
    float* Vs = fsm + OFF_VS;
    float* mk = fsm + OFF_MK;
    uint32_t sbase = smem_u32(fsm);

    int qt = gridDim.x - 1 - blockIdx.x;
    int h = blockIdx.y, b = blockIdx.z;
    int tid = threadIdx.x;
    int lane = tid & 31, w = tid >> 5;
    int r = lane >> 2, cc = lane & 3;
    int i0 = qt * 128;
    const float scale = 0.125f;
    float slope = exp2f(-0.5f * (float)(h + 1));

    const float* qbase = qbuf + ((size_t)(b * Hh + h)) * Sq * HD;
    const float* kbase = kbuf + ((size_t)(b * Hh + h)) * Sq * HD;
    const float* vbase = vbuf + ((size_t)(b * Hh + h)) * Sq * HD;

    {
        int row = tid >> 1, h32 = (tid & 1) * 32;
        const float* qp = qbase + (size_t)(i0 + row) * HD + h32;
        uint32_t dst = sbase + (uint32_t)(OFF_SQ + row * FST + h32) * 4u;
#pragma unroll
        for (int i = 0; i < 8; i++) cpa16(dst + i * 16, qp + i * 4);
        CP_COMMIT();
    }

    int row_lo = w * 16 + r, row_hi = row_lo + 8;
    int ig_lo = i0 + row_lo, ig_hi = i0 + row_hi;

    float of[8][4];
#pragma unroll
    for (int f = 0; f < 8; f++)
#pragma unroll
        for (int e = 0; e < 4; e++) of[f][e] = 0.f;

    float m_lo = -1e30f, m_hi = -1e30f, l_lo = 0.f, l_hi = 0.f;

    int kk_s = tid >> 2, part_s = (tid & 3) * 16;
    uint32_t dK = sbase + (uint32_t)(OFF_KS + kk_s * FST + part_s) * 4u;
    uint32_t dV = sbase + (uint32_t)(OFF_VS + kk_s * VST + part_s) * 4u;

    int ntiles = 2 * qt + 3;
    for (int t = 0; t < ntiles; ++t) {
        int j0 = t * 64 - 10;
        {
            const float *kp, *vp;
            if (t == 0 && kk_s < KTOT) {
                kp = ret + ((size_t)b * KTOT + kk_s) * DM + h * HD + part_s;
                vp = kp;
            } else {
                int jg = j0 + kk_s;
                if (jg > Sq - 1) jg = Sq - 1;
                kp = kbase + (size_t)jg * HD + part_s;
                vp = vbase + (size_t)jg * HD + part_s;
            }
#pragma unroll
            for (int i = 0; i < 4; i++) {
                cpa16(dK + i * 16, kp + i * 4);
                cpa16(dV + i * 16, vp + i * 4);
            }
            CP_COMMIT();
            if (tid < 64) {
                int jg = j0 + tid;
                if (jg < 0) jg = 0;
                if (jg > Sq - 1) jg = Sq - 1;
                mk[tid] = (t == 0 && tid < KTOT) ? 1.0f : amask[b * Sq + jg];
            }
        }
        CP_WAIT0();
        __syncthreads();

        float sc[8][4];
#pragma unroll
        for (int f = 0; f < 8; f++)
#pragma unroll
            for (int e = 0; e < 4; e++) sc[f][e] = 0.f;
#pragma unroll
        for (int ks = 0; ks < 8; ks++) {
            uint32_t aq[4];
            aq[0] = __float_as_uint(SQ[row_lo * FST + ks * 8 + cc]);
            aq[1] = __float_as_uint(SQ[row_hi * FST + ks * 8 + cc]);
            aq[2] = __float_as_uint(SQ[row_lo * FST + ks * 8 + cc + 4]);
            aq[3] = __float_as_uint(SQ[row_hi * FST + ks * 8 + cc + 4]);
#pragma unroll
            for (int f = 0; f < 8; f++) {
                uint32_t bb[2];
                bb[0] = __float_as_uint(Ks[(f * 8 + r) * FST + ks * 8 + cc]);
                bb[1] = __float_as_uint(Ks[(f * 8 + r) * FST + ks * 8 + cc + 4]);
                mma8(sc[f], aq, bb);
            }
        }

        float tmax_lo = m_lo, tmax_hi = m_hi;
#pragma unroll
        for (int f = 0; f < 8; f++) {
            int col0 = f * 8 + 2 * cc;
            int col1 = col0 + 1;
            int jg0 = j0 + col0, jg1 = j0 + col1;
            bool mem0 = (t == 0) && (col0 < KTOT);
            bool mem1 = (t == 0) && (col1 < KTOT);
            float pen0 = (1.0f - mk[col0]) * (-1e9f);
            float pen1 = (1.0f - mk[col1]) * (-1e9f);
            float s;
            s = sc[f][0] * scale + (mem0 ? 0.f : slope * (float)(ig_lo - jg0) + pen0);
            if (!mem0 && jg0 > ig_lo) s = -1e30f;
            sc[f][0] = s; tmax_lo = fmaxf(tmax_lo, s);
            s = sc[f][1] * scale + (mem1 ? 0.f : slope * (float)(ig_lo - jg1) + pen1);
            if (!mem1 && jg1 > ig_lo) s = -1e30f;
            sc[f][1] = s; tmax_lo = fmaxf(tmax_lo, s);
            s = sc[f][2] * scale + (mem0 ? 0.f : slope * (float)(ig_hi - jg0) + pen0);
            if (!mem0 && jg0 > ig_hi) s = -1e30f;
            sc[f][2] = s; tmax_hi = fmaxf(tmax_hi, s);
            s = sc[f][3] * scale + (mem1 ? 0.f : slope * (float)(ig_hi - jg1) + pen1);
            if (!mem1 && jg1 > ig_hi) s = -1e30f;
            sc[f][3] = s; tmax_hi = fmaxf(tmax_hi, s);
        }
        tmax_lo = fmaxf(tmax_lo, __shfl_xor_sync(0xffffffffu, tmax_lo, 1));
        tmax_lo = fmaxf(tmax_lo, __shfl_xor_sync(0xffffffffu, tmax_lo, 2));
        tmax_hi = fmaxf(tmax_hi, __shfl_xor_sync(0xffffffffu, tmax_hi, 1));
        tmax_hi = fmaxf(tmax_hi, __shfl_xor_sync(0xffffffffu, tmax_hi, 2));

        float corr_lo = __expf(m_lo - tmax_lo);
        float corr_hi = __expf(m_hi - tmax_hi);
        l_lo *= corr_lo; l_hi *= corr_hi;
        m_lo = tmax_lo;  m_hi = tmax_hi;

        float sl = 0.f, sh = 0.f;
#pragma unroll
        for (int f = 0; f < 8; f++) {
            sc[f][0] = __expf(sc[f][0] - m_lo); sl += sc[f][0];
            sc[f][1] = __expf(sc[f][1] - m_lo); sl += sc[f][1];
            sc[f][2] = __expf(sc[f][2] - m_hi); sh += sc[f][2];
            sc[f][3] = __expf(sc[f][3] - m_hi); sh += sc[f][3];
        }
        sl += __shfl_xor_sync(0xffffffffu, sl, 1);
        sl += __shfl_xor_sync(0xffffffffu, sl, 2);
        sh += __shfl_xor_sync(0xffffffffu, sh, 1);
        sh += __shfl_xor_sync(0xffffffffu, sh, 2);
        l_lo += sl; l_hi += sh;

#pragma unroll
        for (int f = 0; f < 8; f++) {
            of[f][0] *= corr_lo; of[f][1] *= corr_lo;
            of[f][2] *= corr_hi; of[f][3] *= corr_hi;
        }

#pragma unroll
        for (int f = 0; f < 8; f++) {
            int col0 = f * 8 + 2 * cc;
            *(float2*)&SP[row_lo * FST + col0] = make_float2(cf_tf32(sc[f][0]), cf_tf32(sc[f][1]));
            *(float2*)&SP[row_hi * FST + col0] = make_float2(cf_tf32(sc[f][2]), cf_tf32(sc[f][3]));
        }
        __syncwarp();

#pragma unroll
        for (int ks = 0; ks < 8; ks++) {
            uint32_t ap[4];
            ap[0] = __float_as_uint(SP[row_lo * FST + ks * 8 + cc]);
            ap[1] = __float_as_uint(SP[row_hi * FST + ks * 8 + cc]);
            ap[2] = __float_as_uint(SP[row_lo * FST + ks * 8 + cc + 4]);
            ap[3] = __float_as_uint(SP[row_hi * FST + ks * 8 + cc + 4]);
#pragma unroll
            for (int f = 0; f < 8; f++) {
                uint32_t bv[2];
                bv[0] = __float_as_uint(Vs[(ks * 8 + cc) * VST + f * 8 + r]);
                bv[1] = __float_as_uint(Vs[(ks * 8 + cc + 4) * VST + f * 8 + r]);
                mma8(of[f], ap, bv);
            }
        }
        __syncthreads();
    }

    // ---- finalize: divide by l, tf32-round, store FRAG-MAJOR for gemm_o ----
    float inv_lo = 1.0f / l_lo, inv_hi = 1.0f / l_hi;
    int mlo = b * Sq + ig_lo, mhi = b * Sq + ig_hi;
#pragma unroll
    for (int f = 0; f < 8; f++) {
        int k0 = h * HD + f * 8 + 2 * cc;
        att[fragidxA(mlo, k0)]     = cf_tf32(of[f][0] * inv_lo);
        att[fragidxA(mlo, k0 + 1)] = cf_tf32(of[f][1] * inv_lo);
        att[fragidxA(mhi, k0)]     = cf_tf32(of[f][2] * inv_hi);
        att[fragidxA(mhi, k0 + 1)] = cf_tf32(of[f][3] * inv_hi);
    }
}

// ---------------- launcher ----------------
extern "C" void kernel_launch(void* const* d_in, const int* in_sizes, int n_in,
                              void* d_out, int out_size)
{
    const float* inputs = (const float*)d_in[0];
    const float* amask  = (const float*)d_in[1];
    const float* Wq     = (const float*)d_in[2];
    const float* Wk     = (const float*)d_in[3];
    const float* Wv     = (const float*)d_in[4];
    const float* Wo     = (const float*)d_in[5];
    const float* events = (const float*)d_in[6];
    float* out = (float*)d_out;

    float *q, *k, *v, *att, *ret, *sims, *wt, *ai, *klast;
    cudaGetSymbolAddress((void**)&q,     g_q);
    cudaGetSymbolAddress((void**)&k,     g_k);
    cudaGetSymbolAddress((void**)&v,     g_v);
    cudaGetSymbolAddress((void**)&att,   g_att);
    cudaGetSymbolAddress((void**)&ret,   g_ret);
    cudaGetSymbolAddress((void**)&sims,  g_sims);
    cudaGetSymbolAddress((void**)&wt,    g_wt);
    cudaGetSymbolAddress((void**)&ai,    g_ai);
    cudaGetSymbolAddress((void**)&klast, g_klast);

    cudaFuncSetAttribute(gemm_qkv,  cudaFuncAttributeMaxDynamicSharedMemorySize, GSMEM_BYTES);
    cudaFuncSetAttribute(gemm_o,    cudaFuncAttributeMaxDynamicSharedMemorySize, GSMEM_BYTES);
    cudaFuncSetAttribute(flash_mma, cudaFuncAttributeMaxDynamicSharedMemorySize, FSMEM_BYTES);

    prep_a<<<(Bq * Sq / 16) * (DM / 8) * 32 / 256, 256>>>(inputs, ai);
    transpose_w<<<dim3(32, 32, 4), 256>>>(Wq, Wk, Wv, Wo, wt);

    gemm_qkv<<<dim3(8, 32, 3), 256, GSMEM_BYTES>>>(ai, wt, q, k, v, klast);

    retrieve_sims<<<dim3(125, Bq), 256>>>(klast, events, sims);
    topk_gather<<<Bq, 256>>>(sims, events, ret);

    flash_mma<<<dim3(Sq / 128, Hh, Bq), 256, FSMEM_BYTES>>>(amask, q, k, v, ret, att);

    gemm_o<<<dim3(8, 32), 256, GSMEM_BYTES>>>(att, wt + 3 * (size_t)DM * DM, out);
}

// round 10
// speedup vs baseline: 2.5117x; 1.0680x over previous
#include <cuda_runtime.h>
#include <math.h>
#include <stdint.h>

// Problem constants
#define Bq   2
#define Sq   2048
#define DM   1024
#define Hh   16
#define HD   64
#define MEMN 1000
#define KTOT 10

// ---------------- device scratch ----------------
__device__ float g_q[Bq * Hh * Sq * HD];
__device__ float g_k[Bq * Hh * Sq * HD];
__device__ float g_v[Bq * Hh * Sq * HD];
__device__ float g_att[Bq * Sq * DM];   // FRAG-MAJOR (written by flash, read by gemm_o)
__device__ float g_ret[Bq * KTOT * DM];
__device__ float g_sims[Bq * MEMN];
__device__ float g_wt[4 * DM * DM];     // FRAG-MAJOR tf32 weights (B operand)
__device__ float g_ai[Bq * Sq * DM];    // FRAG-MAJOR tf32 inputs (A operand)
__device__ float g_klast[Bq * DM];      // UNROUNDED last-token key (retrieval)

// ---------------- helpers ----------------
__device__ __forceinline__ uint32_t smem_u32(const void* p) {
    uint32_t a;
    asm("{ .reg .u64 t; cvta.to.shared.u64 t, %1; cvt.u32.u64 %0, t; }" : "=r"(a) : "l"(p));
    return a;
}
__device__ __forceinline__ float cf_tf32(float x) {
    uint32_t u;
    asm("cvt.rna.tf32.f32 %0, %1;" : "=r"(u) : "f"(x));
    return __uint_as_float(u);
}
__device__ __forceinline__ void mma8(float* c, const uint32_t* a, const uint32_t* b) {
    asm("mma.sync.aligned.m16n8k8.row.col.f32.tf32.tf32.f32 "
        "{%0,%1,%2,%3},{%4,%5,%6,%7},{%8,%9},{%0,%1,%2,%3};"
        : "+f"(c[0]), "+f"(c[1]), "+f"(c[2]), "+f"(c[3])
        : "r"(a[0]), "r"(a[1]), "r"(a[2]), "r"(a[3]), "r"(b[0]), "r"(b[1]));
}
__device__ __forceinline__ void cpa16(uint32_t d, const void* g) {
    asm volatile("cp.async.cg.shared.global [%0], [%1], 16;" :: "r"(d), "l"(g) : "memory");
}
#define CP_COMMIT() asm volatile("cp.async.commit_group;" ::: "memory")
#define CP_WAIT0()  asm volatile("cp.async.wait_group 0;" ::: "memory")

// A-operand frag-major index: tile (m/16, k/8), lane (m%8)*4+(k%4), elem (m/8)%2 + 2*((k/4)%2)
__device__ __forceinline__ size_t fragidxA(int m, int k) {
    return ((((size_t)(m >> 4)) * (DM / 8) + (k >> 3)) * 32 + ((m & 7) * 4 + (k & 3))) * 4
           + ((m >> 3) & 1) + 2 * ((k >> 2) & 1);
}

// ---------------- prep: inputs -> frag-major tf32 --------------------------
__global__ __launch_bounds__(256) void prep_a(const float* __restrict__ A,
                                              float* __restrict__ D)
{
    int gt = blockIdx.x * 256 + threadIdx.x;
    int tile = gt >> 5, lane = gt & 31;
    int mt = tile >> 7, kt = tile & 127;
    int m = mt * 16 + (lane >> 2), k = kt * 8 + (lane & 3);
    float4 o;
    o.x = cf_tf32(A[(size_t)m * DM + k]);
    o.y = cf_tf32(A[(size_t)(m + 8) * DM + k]);
    o.z = cf_tf32(A[(size_t)m * DM + k + 4]);
    o.w = cf_tf32(A[(size_t)(m + 8) * DM + k + 4]);
    ((float4*)D)[gt] = o;
}

// ---------------- weights -> frag-major tf32 B operand ---------------------
__global__ __launch_bounds__(256) void transpose_w(const float* __restrict__ W0,
                                                   const float* __restrict__ W1,
                                                   const float* __restrict__ W2,
                                                   const float* __restrict__ W3,
                                                   float* __restrict__ WT)
{
    __shared__ float t[32][33];
    int z = blockIdx.z;
    const float* W = (z == 0) ? W0 : (z == 1) ? W1 : (z == 2) ? W2 : W3;
    float* D = WT + (size_t)z * DM * DM;
    int x = blockIdx.x * 32, y = blockIdx.y * 32;   // x = n0, y = k0
    int tid = threadIdx.x;
    int tx = tid & 31, ty = tid >> 5;
    for (int r = ty; r < 32; r += 8)
        t[r][tx] = W[(size_t)(y + r) * DM + x + tx];
    __syncthreads();
    for (int p = tid; p < 512; p += 256) {
        int ttile = p >> 5, lane = p & 31;
        int nt_l = ttile >> 2, kt_l = ttile & 3;
        int n_l = nt_l * 8 + (lane >> 2), k_l = kt_l * 8 + (lane & 3);
        float2 o = make_float2(cf_tf32(t[k_l][n_l]), cf_tf32(t[k_l + 4][n_l]));
        ((float2*)D)[((size_t)((x >> 3) + nt_l) * (DM / 8) + (y >> 3) + kt_l) * 32 + lane] = o;
    }
}

// ---------------- frag-major cp.async tf32 mma.sync GEMM -------------------
#define NSTAGE  4
#define NIT     (DM / 16)
#define STG_B   16384
#define GSMEM_BYTES (NSTAGE * STG_B)

__device__ __forceinline__ void gemm_body(const float* __restrict__ A,
                                          const float* __restrict__ WT,
                                          float* __restrict__ C,
                                          int headwrite, float* klast, float* dsm)
{
    uint32_t sbase = smem_u32(dsm);
    int tid = threadIdx.x, lane = tid & 31, wid = tid >> 5;
    int wm = wid & 3, wn = wid >> 2;
    int m0 = blockIdx.y * 128, n0 = blockIdx.x * 128;
    int r = lane >> 2;

    int bia = tid >> 4, offa = (tid & 15) * 16;
    int bib = tid >> 3, offb = (tid & 7) * 32;
    int amt = bia >> 1, akt = bia & 1;
    int bnt = bib >> 1, bkt = bib & 1;

    const float* gA = A  + ((size_t)((m0 >> 4) + amt) * 128 + akt) * 128 + (offa >> 2);
    const float* gB = WT + ((size_t)((n0 >> 3) + bnt) * 128 + bkt) * 64  + (offb >> 2);
    uint32_t dA = sbase + (uint32_t)(bia * 512 + offa);
    uint32_t dB = sbase + 8192u + (uint32_t)(bib * 256 + offb);

    float acc[2][8][4];
#pragma unroll
    for (int i = 0; i < 2; i++)
#pragma unroll
        for (int j = 0; j < 8; j++)
#pragma unroll
            for (int t = 0; t < 4; t++) acc[i][j][t] = 0.f;

#pragma unroll
    for (int s = 0; s < NSTAGE - 1; s++) {
        uint32_t so = (uint32_t)s * STG_B;
        cpa16(dA + so,       gA + (size_t)s * 256);
        cpa16(dA + so + 256, gA + (size_t)s * 256 + 64);
        cpa16(dB + so,       gB + (size_t)s * 128);
        cpa16(dB + so + 16,  gB + (size_t)s * 128 + 4);
        CP_COMMIT();
    }

    for (int it = 0; it < NIT; ++it) {
        if (it + NSTAGE - 1 < NIT) {
            int s = it + NSTAGE - 1;
            uint32_t so = (uint32_t)(s % NSTAGE) * STG_B;
            cpa16(dA + so,       gA + (size_t)s * 256);
            cpa16(dA + so + 256, gA + (size_t)s * 256 + 64);
            cpa16(dB + so,       gB + (size_t)s * 128);
            cpa16(dB + so + 16,  gB + (size_t)s * 128 + 4);
            CP_COMMIT();
        }
        if (it + 3 < NIT)      asm volatile("cp.async.wait_group 3;" ::: "memory");
        else if (it + 2 < NIT) asm volatile("cp.async.wait_group 2;" ::: "memory");
        else if (it + 1 < NIT) asm volatile("cp.async.wait_group 1;" ::: "memory");
        else                   asm volatile("cp.async.wait_group 0;" ::: "memory");
        __syncthreads();

        const uint4* As4 = (const uint4*)(dsm + (it % NSTAGE) * (STG_B / 4));
        const uint2* Bs2 = (const uint2*)(dsm + (it % NSTAGE) * (STG_B / 4) + 2048);

#pragma unroll
        for (int ks8 = 0; ks8 < 2; ks8++) {
            uint4 af[2];
#pragma unroll
            for (int i = 0; i < 2; i++)
                af[i] = As4[((wm * 2 + i) * 2 + ks8) * 32 + lane];
            uint2 bf[8];
#pragma unroll
            for (int j = 0; j < 8; j++)
                bf[j] = Bs2[((wn * 8 + j) * 2 + ks8) * 32 + lane];
#pragma unroll
            for (int i = 0; i < 2; i++)
#pragma unroll
                for (int j = 0; j < 8; j++)
                    mma8(acc[i][j], (const uint32_t*)&af[i], (const uint32_t*)&bf[j]);
        }
        __syncthreads();
    }

    int c2 = (lane & 3) * 2;
#pragma unroll
    for (int i = 0; i < 2; i++) {
#pragma unroll
        for (int j = 0; j < 8; j++) {
            int row0 = m0 + wm * 32 + i * 16 + r;
            int col  = n0 + wn * 64 + j * 8 + c2;
            if (headwrite) {
                float2 lo = make_float2(cf_tf32(acc[i][j][0]), cf_tf32(acc[i][j][1]));
                float2 hi = make_float2(cf_tf32(acc[i][j][2]), cf_tf32(acc[i][j][3]));
                int b = row0 >> 11, h = col >> 6, hd = col & 63;
                int s0 = row0 & 2047;
                float* base = C + (((size_t)(b * Hh + h)) * Sq) * HD + hd;
                *(float2*)(base + (size_t)s0 * HD)       = lo;
                *(float2*)(base + (size_t)(s0 + 8) * HD) = hi;
                if (klast && s0 + 8 == Sq - 1)
                    *(float2*)&klast[b * DM + col] = make_float2(acc[i][j][2], acc[i][j][3]);
            } else {
                *(float2*)&C[(size_t)row0 * DM + col] =
                    make_float2(acc[i][j][0], acc[i][j][1]);
                *(float2*)&C[(size_t)(row0 + 8) * DM + col] =
                    make_float2(acc[i][j][2], acc[i][j][3]);
            }
        }
    }
}

__global__ void __launch_bounds__(256, 2) gemm_qkv(const float* __restrict__ A,
                                                   const float* __restrict__ WT,
                                                   float* q, float* k, float* v,
                                                   float* klast)
{
    extern __shared__ float dsm[];
    int z = blockIdx.z;
    float* C = (z == 0) ? q : (z == 1) ? k : v;
    gemm_body(A, WT + (size_t)z * DM * DM, C, 1, (z == 1) ? klast : (float*)0, dsm);
}

__global__ void __launch_bounds__(256, 2) gemm_o(const float* __restrict__ A,
                                                 const float* __restrict__ WT,
                                                 float* __restrict__ C)
{
    extern __shared__ float dsm[];
    gemm_body(A, WT, C, 0, (float*)0, dsm);
}

// ---------------- retrieval: sims (warp per event) ------------------------
__global__ __launch_bounds__(256) void retrieve_sims(const float* __restrict__ klast,
                                                     const float* __restrict__ events,
                                                     float* __restrict__ sims)
{
    int b = blockIdx.y;
    int tid = threadIdx.x;
    int lane = tid & 31, wid = tid >> 5;
    __shared__ float qs[DM];
    __shared__ float qn_s;

    for (int d = tid; d < DM; d += 256) qs[d] = klast[b * DM + d];
    __syncthreads();
    if (wid == 0) {
        float ps = 0.f;
        for (int d = lane * 4; d < DM; d += 128) {
            float4 t = *(const float4*)&qs[d];
            ps += t.x * t.x + t.y * t.y + t.z * t.z + t.w * t.w;
        }
#pragma unroll
        for (int off = 16; off > 0; off >>= 1) ps += __shfl_down_sync(0xffffffffu, ps, off);
        if (lane == 0) qn_s = sqrtf(ps) + 1e-8f;
    }
    __syncthreads();
    float qnorm = qn_s;

    int e = blockIdx.x * 8 + wid;
    if (e >= MEMN) return;
    const float* ep = events + (size_t)e * DM;
    float dot = 0.f, nn = 0.f;
    for (int d = lane * 4; d < DM; d += 128) {
        float4 ev = *(const float4*)(ep + d);
        float4 qv = *(const float4*)&qs[d];
        dot += qv.x * ev.x + qv.y * ev.y + qv.z * ev.z + qv.w * ev.w;
        nn  += ev.x * ev.x + ev.y * ev.y + ev.z * ev.z + ev.w * ev.w;
    }
#pragma unroll
    for (int off = 16; off > 0; off >>= 1) {
        dot += __shfl_down_sync(0xffffffffu, dot, off);
        nn  += __shfl_down_sync(0xffffffffu, nn, off);
    }
    if (lane == 0) sims[b * MEMN + e] = dot / (qnorm * (sqrtf(nn) + 1e-8f));
}

// ---------------- retrieval: parallel top-k + gather (tf32-rounded) --------
__global__ __launch_bounds__(256) void topk_gather(const float* __restrict__ sims,
                                                   const float* __restrict__ events,
                                                   float* __restrict__ ret)
{
    int b = blockIdx.x;
    int tid = threadIdx.x;
    int lane = tid & 31, wid = tid >> 5;
    __shared__ float sv[MEMN];
    __shared__ float wmax[8];
    __shared__ int   widx[8];
    __shared__ int   tidx[KTOT];

    for (int e = tid; e < MEMN; e += 256) sv[e] = sims[b * MEMN + e];
    __syncthreads();

    for (int kk = 0; kk < KTOT; kk++) {
        float bm = -1e30f; int bi = MEMN;
        for (int e = tid; e < MEMN; e += 256) {
            float v = sv[e];
            if (v > bm || (v == bm && e < bi)) { bm = v; bi = e; }
        }
#pragma unroll
        for (int off = 16; off > 0; off >>= 1) {
            float om = __shfl_down_sync(0xffffffffu, bm, off);
            int   oi = __shfl_down_sync(0xffffffffu, bi, off);
            if (om > bm || (om == bm && oi < bi)) { bm = om; bi = oi; }
        }
        if (lane == 0) { wmax[wid] = bm; widx[wid] = bi; }
        __syncthreads();
        if (tid == 0) {
            float gm = wmax[0]; int gi = widx[0];
            for (int w = 1; w < 8; w++) {
                if (wmax[w] > gm || (wmax[w] == gm && widx[w] < gi)) { gm = wmax[w]; gi = widx[w]; }
            }
            tidx[kk] = gi;
            sv[gi] = -1e30f;
        }
        __syncthreads();
    }

    for (int kk = 0; kk < KTOT; kk++) {
        int src = tidx[kk];
        for (int d = tid; d < DM; d += 256)
            ret[((size_t)b * KTOT + kk) * DM + d] = cf_tf32(events[(size_t)src * DM + d]);
    }
}

// ---------------- flash v6: double-buffered 32-key tiles, aligned ----------
#define TKF    32
#define FST    68
#define VST    72
#define OFF_SQ 0
#define OFF_SP (128 * FST)
#define OFF_K2 (OFF_SP + 128 * FST)
#define OFF_V2 (OFF_K2 + 2 * TKF * FST)
#define OFF_CB (OFF_V2 + 2 * TKF * VST)
#define FSMEM_FLOATS (OFF_CB + 2 * TKF)
#define FSMEM_BYTES  (FSMEM_FLOATS * 4)

__global__ void __launch_bounds__(256, 2) flash_mma(const float* __restrict__ amask,
                                                    const float* __restrict__ qbuf,
                                                    const float* __restrict__ kbuf,
                                                    const float* __restrict__ vbuf,
                                                    const float* __restrict__ ret,
                                                    float* __restrict__ att)
{
    extern __shared__ float fsm[];
    float* SQ = fsm + OFF_SQ;
    float* SP = fsm + OFF_SP;
    float* K2 = fsm + OFF_K2;
    float* V2 = fsm + OFF_V2;
    float* CB = fsm + OFF_CB;
    uint32_t sbase = smem_u32(fsm);

    int qt = gridDim.x - 1 - blockIdx.x;   // heavy tiles first
    int h = blockIdx.y, b = blockIdx.z;
    int tid = threadIdx.x;
    int lane = tid & 31, w = tid >> 5;
    int r = lane >> 2, cc = lane & 3;
    int i0 = qt * 128;
    const float scale = 0.125f;
    float slope = exp2f(-0.5f * (float)(h + 1));

    const float* qbase = qbuf + ((size_t)(b * Hh + h)) * Sq * HD;
    const float* kbase = kbuf + ((size_t)(b * Hh + h)) * Sq * HD;
    const float* vbase = vbuf + ((size_t)(b * Hh + h)) * Sq * HD;

    // ---- stage Q (cp.async) ----
    {
        int row = tid >> 1, h32 = (tid & 1) * 32;
        const float* qp = qbase + (size_t)(i0 + row) * HD + h32;
        uint32_t dst = sbase + (uint32_t)(OFF_SQ + row * FST + h32) * 4u;
#pragma unroll
        for (int i = 0; i < 8; i++) cpa16(dst + i * 16, qp + i * 4);
        CP_COMMIT();
    }

    int kk_s = tid >> 3, part_s = (tid & 7) * 8;
    uint32_t dK0 = sbase + (uint32_t)(OFF_K2 + kk_s * FST + part_s) * 4u;
    uint32_t dV0 = sbase + (uint32_t)(OFF_V2 + kk_s * VST + part_s) * 4u;
    const uint32_t KBUF = (uint32_t)(TKF * FST) * 4u;
    const uint32_t VBUF = (uint32_t)(TKF * VST) * 4u;

    // ---- tile 0 into buf0 (cp.async) ----
    {
        const float* kp = kbase + (size_t)kk_s * HD + part_s;
        const float* vp = vbase + (size_t)kk_s * HD + part_s;
        cpa16(dK0, kp);      cpa16(dK0 + 16, kp + 4);
        cpa16(dV0, vp);      cpa16(dV0 + 16, vp + 4);
        CP_COMMIT();
        if (tid < TKF) CB[tid] = (1.0f - amask[b * Sq + tid]) * (-1e9f);
    }
    // ---- mem tile (16 keys, 6 padded) into buf1 (scalar) ----
    if (tid < 128) {
        int kk = tid >> 3, part = (tid & 7) * 8;
        const float* rp = ret + ((size_t)b * KTOT + kk) * DM + h * HD + part;
        float* dk = K2 + TKF * FST + kk * FST + part;
        float* dv = V2 + TKF * VST + kk * VST + part;
#pragma unroll
        for (int i = 0; i < 8; i++) {
            float vv = (kk < KTOT) ? rp[i] : 0.f;
            dk[i] = vv;
            dv[i] = vv;
        }
    }
    if (tid < TKF) CB[TKF + tid] = (tid < KTOT) ? 0.f : -1e30f;

    CP_WAIT0();
    __syncthreads();

    int row_lo = w * 16 + r, row_hi = row_lo + 8;
    int ig_lo = i0 + row_lo, ig_hi = i0 + row_hi;

    float of[8][4];
#pragma unroll
    for (int f = 0; f < 8; f++)
#pragma unroll
        for (int e = 0; e < 4; e++) of[f][e] = 0.f;
    float m_lo = -1e30f, m_hi = -1e30f, l_lo = 0.f, l_hi = 0.f;

    // ================= memory pass (buf1, 16 cols) =================
    {
        const float* Ks = K2 + TKF * FST;
        const float* Vs = V2 + TKF * VST;
        float sc[2][4];
#pragma unroll
        for (int f = 0; f < 2; f++)
#pragma unroll
            for (int e = 0; e < 4; e++) sc[f][e] = 0.f;
#pragma unroll
        for (int ks = 0; ks < 8; ks++) {
            uint32_t aq[4];
            aq[0] = __float_as_uint(SQ[row_lo * FST + ks * 8 + cc]);
            aq[1] = __float_as_uint(SQ[row_hi * FST + ks * 8 + cc]);
            aq[2] = __float_as_uint(SQ[row_lo * FST + ks * 8 + cc + 4]);
            aq[3] = __float_as_uint(SQ[row_hi * FST + ks * 8 + cc + 4]);
#pragma unroll
            for (int f = 0; f < 2; f++) {
                uint32_t bb[2];
                bb[0] = __float_as_uint(Ks[(f * 8 + r) * FST + ks * 8 + cc]);
                bb[1] = __float_as_uint(Ks[(f * 8 + r) * FST + ks * 8 + cc + 4]);
                mma8(sc[f], aq, bb);
            }
        }
        float tl = m_lo, th = m_hi;
#pragma unroll
        for (int f = 0; f < 2; f++) {
            int c0 = f * 8 + 2 * cc;
            float cb0 = CB[TKF + c0], cb1v = CB[TKF + c0 + 1];
            sc[f][0] = fmaf(sc[f][0], scale, cb0);
            sc[f][1] = fmaf(sc[f][1], scale, cb1v);
            sc[f][2] = fmaf(sc[f][2], scale, cb0);
            sc[f][3] = fmaf(sc[f][3], scale, cb1v);
            tl = fmaxf(tl, fmaxf(sc[f][0], sc[f][1]));
            th = fmaxf(th, fmaxf(sc[f][2], sc[f][3]));
        }
        tl = fmaxf(tl, __shfl_xor_sync(0xffffffffu, tl, 1));
        tl = fmaxf(tl, __shfl_xor_sync(0xffffffffu, tl, 2));
        th = fmaxf(th, __shfl_xor_sync(0xffffffffu, th, 1));
        th = fmaxf(th, __shfl_xor_sync(0xffffffffu, th, 2));
        float corr_lo = __expf(m_lo - tl), corr_hi = __expf(m_hi - th);
        l_lo *= corr_lo; l_hi *= corr_hi;
        m_lo = tl; m_hi = th;
        float sl = 0.f, sh = 0.f;
#pragma unroll
        for (int f = 0; f < 2; f++) {
            sc[f][0] = __expf(sc[f][0] - m_lo); sl += sc[f][0];
            sc[f][1] = __expf(sc[f][1] - m_lo); sl += sc[f][1];
            sc[f][2] = __expf(sc[f][2] - m_hi); sh += sc[f][2];
            sc[f][3] = __expf(sc[f][3] - m_hi); sh += sc[f][3];
        }
        sl += __shfl_xor_sync(0xffffffffu, sl, 1);
        sl += __shfl_xor_sync(0xffffffffu, sl, 2);
        sh += __shfl_xor_sync(0xffffffffu, sh, 1);
        sh += __shfl_xor_sync(0xffffffffu, sh, 2);
        l_lo += sl; l_hi += sh;
#pragma unroll
        for (int f = 0; f < 8; f++) {
            of[f][0] *= corr_lo; of[f][1] *= corr_lo;
            of[f][2] *= corr_hi; of[f][3] *= corr_hi;
        }
#pragma unroll
        for (int f = 0; f < 2; f++) {
            int c0 = f * 8 + 2 * cc;
            *(float2*)&SP[row_lo * FST + c0] = make_float2(cf_tf32(sc[f][0]), cf_tf32(sc[f][1]));
            *(float2*)&SP[row_hi * FST + c0] = make_float2(cf_tf32(sc[f][2]), cf_tf32(sc[f][3]));
        }
        __syncwarp();
#pragma unroll
        for (int ks = 0; ks < 2; ks++) {
            uint32_t ap[4];
            ap[0] = __float_as_uint(SP[row_lo * FST + ks * 8 + cc]);
            ap[1] = __float_as_uint(SP[row_hi * FST + ks * 8 + cc]);
            ap[2] = __float_as_uint(SP[row_lo * FST + ks * 8 + cc + 4]);
            ap[3] = __float_as_uint(SP[row_hi * FST + ks * 8 + cc + 4]);
#pragma unroll
            for (int f = 0; f < 8; f++) {
                uint32_t bv[2];
                bv[0] = __float_as_uint(Vs[(ks * 8 + cc) * VST + f * 8 + r]);
                bv[1] = __float_as_uint(Vs[(ks * 8 + cc + 4) * VST + f * 8 + r]);
                mma8(of[f], ap, bv);
            }
        }
    }

    // ================= seq tiles (aligned, double-buffered) =================
    int ntiles = 4 * qt + 4;
    for (int t = 0; t < ntiles; ++t) {
        int buf = t & 1;
        int j0 = t * TKF;
        CP_WAIT0();
        __syncthreads();
        if (t + 1 < ntiles) {
            int j0n = j0 + TKF, bufn = (t + 1) & 1;
            const float* kp = kbase + (size_t)(j0n + kk_s) * HD + part_s;
            const float* vp = vbase + (size_t)(j0n + kk_s) * HD + part_s;
            uint32_t dK = dK0 + bufn * KBUF, dV = dV0 + bufn * VBUF;
            cpa16(dK, kp);      cpa16(dK + 16, kp + 4);
            cpa16(dV, vp);      cpa16(dV + 16, vp + 4);
            CP_COMMIT();
            if (tid < TKF) CB[bufn * TKF + tid] = (1.0f - amask[b * Sq + j0n + tid]) * (-1e9f);
        }
        const float* Ks = K2 + buf * TKF * FST;
        const float* Vs = V2 + buf * TKF * VST;
        const float* cbp = CB + buf * TKF;

        float sc[4][4];
#pragma unroll
        for (int f = 0; f < 4; f++)
#pragma unroll
            for (int e = 0; e < 4; e++) sc[f][e] = 0.f;
#pragma unroll
        for (int ks = 0; ks < 8; ks++) {
            uint32_t aq[4];
            aq[0] = __float_as_uint(SQ[row_lo * FST + ks * 8 + cc]);
            aq[1] = __float_as_uint(SQ[row_hi * FST + ks * 8 + cc]);
            aq[2] = __float_as_uint(SQ[row_lo * FST + ks * 8 + cc + 4]);
            aq[3] = __float_as_uint(SQ[row_hi * FST + ks * 8 + cc + 4]);
#pragma unroll
            for (int f = 0; f < 4; f++) {
                uint32_t bb[2];
                bb[0] = __float_as_uint(Ks[(f * 8 + r) * FST + ks * 8 + cc]);
                bb[1] = __float_as_uint(Ks[(f * 8 + r) * FST + ks * 8 + cc + 4]);
                mma8(sc[f], aq, bb);
            }
        }

        bool causal = (t >= 4 * qt);
        float o0f = (float)(2 * cc);
        float tl = m_lo, th = m_hi;
#pragma unroll
        for (int f = 0; f < 4; f++) {
            int c0 = f * 8 + 2 * cc;
            float cb0 = cbp[c0], cb1v = cbp[c0 + 1];
            float fl = (float)(ig_lo - j0 - f * 8);
            float s00 = fmaf(sc[f][0], scale, fmaf(slope, fl - o0f, cb0));
            float s01 = fmaf(sc[f][1], scale, fmaf(slope, fl - o0f - 1.0f, cb1v));
            float s10 = fmaf(sc[f][2], scale, fmaf(slope, fl + 8.0f - o0f, cb0));
            float s11 = fmaf(sc[f][3], scale, fmaf(slope, fl + 8.0f - o0f - 1.0f, cb1v));
            if (causal) {
                int jg0 = j0 + c0;
                if (jg0 > ig_lo)     s00 = -1e30f;
                if (jg0 + 1 > ig_lo) s01 = -1e30f;
                if (jg0 > ig_hi)     s10 = -1e30f;
                if (jg0 + 1 > ig_hi) s11 = -1e30f;
            }
            sc[f][0] = s00; sc[f][1] = s01; sc[f][2] = s10; sc[f][3] = s11;
            tl = fmaxf(tl, fmaxf(s00, s01));
            th = fmaxf(th, fmaxf(s10, s11));
        }
        tl = fmaxf(tl, __shfl_xor_sync(0xffffffffu, tl, 1));
        tl = fmaxf(tl, __shfl_xor_sync(0xffffffffu, tl, 2));
        th = fmaxf(th, __shfl_xor_sync(0xffffffffu, th, 1));
        th = fmaxf(th, __shfl_xor_sync(0xffffffffu, th, 2));

        float corr_lo = __expf(m_lo - tl), corr_hi = __expf(m_hi - th);
        l_lo *= corr_lo; l_hi *= corr_hi;
        m_lo = tl; m_hi = th;

        float sl = 0.f, sh = 0.f;
#pragma unroll
        for (int f = 0; f < 4; f++) {
            sc[f][0] = __expf(sc[f][0] - m_lo); sl += sc[f][0];
            sc[f][1] = __expf(sc[f][1] - m_lo); sl += sc[f][1];
            sc[f][2] = __expf(sc[f][2] - m_hi); sh += sc[f][2];
            sc[f][3] = __expf(sc[f][3] - m_hi); sh += sc[f][3];
        }
        sl += __shfl_xor_sync(0xffffffffu, sl, 1);
        sl += __shfl_xor_sync(0xffffffffu, sl, 2);
        sh += __shfl_xor_sync(0xffffffffu, sh, 1);
        sh += __shfl_xor_sync(0xffffffffu, sh, 2);
        l_lo += sl; l_hi += sh;

#pragma unroll
        for (int f = 0; f < 8; f++) {
            of[f][0] *= corr_lo; of[f][1] *= corr_lo;
            of[f][2] *= corr_hi; of[f][3] *= corr_hi;
        }

#pragma unroll
        for (int f = 0; f < 4; f++) {
            int c0 = f * 8 + 2 * cc;
            *(float2*)&SP[row_lo * FST + c0] = make_float2(cf_tf32(sc[f][0]), cf_tf32(sc[f][1]));
            *(float2*)&SP[row_hi * FST + c0] = make_float2(cf_tf32(sc[f][2]), cf_tf32(sc[f][3]));
        }
        __syncwarp();

#pragma unroll
        for (int ks = 0; ks < 4; ks++) {
            uint32_t ap[4];
            ap[0] = __float_as_uint(SP[row_lo * FST + ks * 8 + cc]);
            ap[1] = __float_as_uint(SP[row_hi * FST + ks * 8 + cc]);
            ap[2] = __float_as_uint(SP[row_lo * FST + ks * 8 + cc + 4]);
            ap[3] = __float_as_uint(SP[row_hi * FST + ks * 8 + cc + 4]);
#pragma unroll
            for (int f = 0; f < 8; f++) {
                uint32_t bv[2];
                bv[0] = __float_as_uint(Vs[(ks * 8 + cc) * VST + f * 8 + r]);
                bv[1] = __float_as_uint(Vs[(ks * 8 + cc + 4) * VST + f * 8 + r]);
                mma8(of[f], ap, bv);
            }
        }
    }

    // ---- finalize: divide by l, tf32-round, store FRAG-MAJOR for gemm_o ----
    float inv_lo = 1.0f / l_lo, inv_hi = 1.0f / l_hi;
    int mlo = b * Sq + ig_lo, mhi = b * Sq + ig_hi;
#pragma unroll
    for (int f = 0; f < 8; f++) {
        int k0 = h * HD + f * 8 + 2 * cc;
        att[fragidxA(mlo, k0)]     = cf_tf32(of[f][0] * inv_lo);
        att[fragidxA(mlo, k0 + 1)] = cf_tf32(of[f][1] * inv_lo);
        att[fragidxA(mhi, k0)]     = cf_tf32(of[f][2] * inv_hi);
        att[fragidxA(mhi, k0 + 1)] = cf_tf32(of[f][3] * inv_hi);
    }
}

// ---------------- launcher ----------------
extern "C" void kernel_launch(void* const* d_in, const int* in_sizes, int n_in,
                              void* d_out, int out_size)
{
    const float* inputs = (const float*)d_in[0];
    const float* amask  = (const float*)d_in[1];
    const float* Wq     = (const float*)d_in[2];
    const float* Wk     = (const float*)d_in[3];
    const float* Wv     = (const float*)d_in[4];
    const float* Wo     = (const float*)d_in[5];
    const float* events = (const float*)d_in[6];
    float* out = (float*)d_out;

    float *q, *k, *v, *att, *ret, *sims, *wt, *ai, *klast;
    cudaGetSymbolAddress((void**)&q,     g_q);
    cudaGetSymbolAddress((void**)&k,     g_k);
    cudaGetSymbolAddress((void**)&v,     g_v);
    cudaGetSymbolAddress((void**)&att,   g_att);
    cudaGetSymbolAddress((void**)&ret,   g_ret);
    cudaGetSymbolAddress((void**)&sims,  g_sims);
    cudaGetSymbolAddress((void**)&wt,    g_wt);
    cudaGetSymbolAddress((void**)&ai,    g_ai);
    cudaGetSymbolAddress((void**)&klast, g_klast);

    cudaFuncSetAttribute(gemm_qkv,  cudaFuncAttributeMaxDynamicSharedMemorySize, GSMEM_BYTES);
    cudaFuncSetAttribute(gemm_o,    cudaFuncAttributeMaxDynamicSharedMemorySize, GSMEM_BYTES);
    cudaFuncSetAttribute(flash_mma, cudaFuncAttributeMaxDynamicSharedMemorySize, FSMEM_BYTES);

    prep_a<<<(Bq * Sq / 16) * (DM / 8) * 32 / 256, 256>>>(inputs, ai);
    transpose_w<<<dim3(32, 32, 4), 256>>>(Wq, Wk, Wv, Wo, wt);

    gemm_qkv<<<dim3(8, 32, 3), 256, GSMEM_BYTES>>>(ai, wt, q, k, v, klast);

    retrieve_sims<<<dim3(125, Bq), 256>>>(klast, events, sims);
    topk_gather<<<Bq, 256>>>(sims, events, ret);

    flash_mma<<<dim3(Sq / 128, Hh, Bq), 256, FSMEM_BYTES>>>(amask, q, k, v, ret, att);

    gemm_o<<<dim3(8, 32), 256, GSMEM_BYTES>>>(att, wt + 3 * (size_t)DM * DM, out);
}

// round 11
// speedup vs baseline: 2.7300x; 1.0870x over previous
#include <cuda_runtime.h>
#include <math.h>
#include <stdint.h>

// Problem constants
#define Bq   2
#define Sq   2048
#define DM   1024
#define Hh   16
#define HD   64
#define MEMN 1000
#define KTOT 10

// ---------------- device scratch ----------------
__device__ float g_q[Bq * Hh * Sq * HD];    // A-frag-major per (b,h,qtile)
__device__ float g_k[Bq * Hh * Sq * HD];    // QK-B-frag-major per (b,h)
__device__ float g_v[Bq * Hh * Sq * HD];    // PV-B-frag-major per (b,h)
__device__ float g_att[Bq * Sq * DM];       // A-frag-major (flash -> gemm_o)
__device__ float g_ret[Bq * KTOT * DM];
__device__ float g_sims[Bq * MEMN];
__device__ float g_wt[4 * DM * DM];         // frag-major tf32 weights (B operand)
__device__ float g_ai[Bq * Sq * DM];        // frag-major tf32 inputs (A operand)
__device__ float g_klast[Bq * DM];          // UNROUNDED last-token key

// ---------------- helpers ----------------
__device__ __forceinline__ uint32_t smem_u32(const void* p) {
    uint32_t a;
    asm("{ .reg .u64 t; cvta.to.shared.u64 t, %1; cvt.u32.u64 %0, t; }" : "=r"(a) : "l"(p));
    return a;
}
__device__ __forceinline__ float cf_tf32(float x) {
    uint32_t u;
    asm("cvt.rna.tf32.f32 %0, %1;" : "=r"(u) : "f"(x));
    return __uint_as_float(u);
}
__device__ __forceinline__ void mma8(float* c, const uint32_t* a, const uint32_t* b) {
    asm("mma.sync.aligned.m16n8k8.row.col.f32.tf32.tf32.f32 "
        "{%0,%1,%2,%3},{%4,%5,%6,%7},{%8,%9},{%0,%1,%2,%3};"
        : "+f"(c[0]), "+f"(c[1]), "+f"(c[2]), "+f"(c[3])
        : "r"(a[0]), "r"(a[1]), "r"(a[2]), "r"(a[3]), "r"(b[0]), "r"(b[1]));
}
__device__ __forceinline__ void cpa16(uint32_t d, const void* g) {
    asm volatile("cp.async.cg.shared.global [%0], [%1], 16;" :: "r"(d), "l"(g) : "memory");
}
#define CP_COMMIT() asm volatile("cp.async.commit_group;" ::: "memory")
#define CP_WAIT0()  asm volatile("cp.async.wait_group 0;" ::: "memory")

// A-frag-major index within a generic [M, DM] matrix (prep_a / att layout)
__device__ __forceinline__ size_t fragidxA(int m, int k) {
    return ((((size_t)(m >> 4)) * (DM / 8) + (k >> 3)) * 32 + ((m & 7) * 4 + (k & 3))) * 4
           + ((m >> 3) & 1) + 2 * ((k >> 2) & 1);
}
// Q A-frag-major within one (b,h): [qtile][mtile 8][dimtile 8][lane][4]
__device__ __forceinline__ size_t qfrag_off(int s, int hd) {
    int ml = s & 127;
    return (size_t)(s >> 7) * 8192
         + (size_t)(((ml >> 4) * 8 + (hd >> 3)) * 32 + ((ml & 7) * 4 + (hd & 3))) * 4
         + ((ml >> 3) & 1) + 2 * ((hd >> 2) & 1);
}
// K QK-B-frag-major within one (b,h): [keytile 256][dimtile 8][lane][2]
__device__ __forceinline__ size_t kfrag_off(int s, int hd) {
    return ((size_t)((s >> 3) * 8 + (hd >> 3)) * 32 + ((s & 7) * 4 + (hd & 3))) * 2
           + ((hd >> 2) & 1);
}
// V PV-B-frag-major within one (b,h): [keygroup 64][dimtile 8][ktig 4][lane][2]
__device__ __forceinline__ size_t vfrag_off(int s, int hd) {
    return ((size_t)(((s >> 5) * 8 + (hd >> 3)) * 4 + ((s >> 3) & 3)) * 32
            + ((hd & 7) * 4 + (s & 3))) * 2 + ((s >> 2) & 1);
}

// ---------------- prep: inputs -> frag-major tf32 --------------------------
__global__ __launch_bounds__(256) void prep_a(const float* __restrict__ A,
                                              float* __restrict__ D)
{
    int gt = blockIdx.x * 256 + threadIdx.x;
    int tile = gt >> 5, lane = gt & 31;
    int mt = tile >> 7, kt = tile & 127;
    int m = mt * 16 + (lane >> 2), k = kt * 8 + (lane & 3);
    float4 o;
    o.x = cf_tf32(A[(size_t)m * DM + k]);
    o.y = cf_tf32(A[(size_t)(m + 8) * DM + k]);
    o.z = cf_tf32(A[(size_t)m * DM + k + 4]);
    o.w = cf_tf32(A[(size_t)(m + 8) * DM + k + 4]);
    ((float4*)D)[gt] = o;
}

// ---------------- weights -> frag-major tf32 B operand ---------------------
__global__ __launch_bounds__(256) void transpose_w(const float* __restrict__ W0,
                                                   const float* __restrict__ W1,
                                                   const float* __restrict__ W2,
                                                   const float* __restrict__ W3,
                                                   float* __restrict__ WT)
{
    __shared__ float t[32][33];
    int z = blockIdx.z;
    const float* W = (z == 0) ? W0 : (z == 1) ? W1 : (z == 2) ? W2 : W3;
    float* D = WT + (size_t)z * DM * DM;
    int x = blockIdx.x * 32, y = blockIdx.y * 32;   // x = n0, y = k0
    int tid = threadIdx.x;
    int tx = tid & 31, ty = tid >> 5;
    for (int r = ty; r < 32; r += 8)
        t[r][tx] = W[(size_t)(y + r) * DM + x + tx];
    __syncthreads();
    for (int p = tid; p < 512; p += 256) {
        int ttile = p >> 5, lane = p & 31;
        int nt_l = ttile >> 2, kt_l = ttile & 3;
        int n_l = nt_l * 8 + (lane >> 2), k_l = kt_l * 8 + (lane & 3);
        float2 o = make_float2(cf_tf32(t[k_l][n_l]), cf_tf32(t[k_l + 4][n_l]));
        ((float2*)D)[((size_t)((x >> 3) + nt_l) * (DM / 8) + (y >> 3) + kt_l) * 32 + lane] = o;
    }
}

// ---------------- frag-major cp.async tf32 mma.sync GEMM -------------------
#define NSTAGE  4
#define NIT     (DM / 16)
#define STG_B   16384
#define GSMEM_BYTES (NSTAGE * STG_B)

// mode: 0 = plain row-major out (gemm_o), 1 = Q frag, 2 = K frag (+klast), 3 = V frag
__device__ __forceinline__ void gemm_body(const float* __restrict__ A,
                                          const float* __restrict__ WT,
                                          float* __restrict__ C,
                                          int mode, float* klast, float* dsm)
{
    uint32_t sbase = smem_u32(dsm);
    int tid = threadIdx.x, lane = tid & 31, wid = tid >> 5;
    int wm = wid & 3, wn = wid >> 2;
    int m0 = blockIdx.y * 128, n0 = blockIdx.x * 128;
    int r = lane >> 2;

    int bia = tid >> 4, offa = (tid & 15) * 16;
    int bib = tid >> 3, offb = (tid & 7) * 32;
    int amt = bia >> 1, akt = bia & 1;
    int bnt = bib >> 1, bkt = bib & 1;

    const float* gA = A  + ((size_t)((m0 >> 4) + amt) * 128 + akt) * 128 + (offa >> 2);
    const float* gB = WT + ((size_t)((n0 >> 3) + bnt) * 128 + bkt) * 64  + (offb >> 2);
    uint32_t dA = sbase + (uint32_t)(bia * 512 + offa);
    uint32_t dB = sbase + 8192u + (uint32_t)(bib * 256 + offb);

    float acc[2][8][4];
#pragma unroll
    for (int i = 0; i < 2; i++)
#pragma unroll
        for (int j = 0; j < 8; j++)
#pragma unroll
            for (int t = 0; t < 4; t++) acc[i][j][t] = 0.f;

#pragma unroll
    for (int s = 0; s < NSTAGE - 1; s++) {
        uint32_t so = (uint32_t)s * STG_B;
        cpa16(dA + so,       gA + (size_t)s * 256);
        cpa16(dA + so + 256, gA + (size_t)s * 256 + 64);
        cpa16(dB + so,       gB + (size_t)s * 128);
        cpa16(dB + so + 16,  gB + (size_t)s * 128 + 4);
        CP_COMMIT();
    }

    for (int it = 0; it < NIT; ++it) {
        if (it + NSTAGE - 1 < NIT) {
            int s = it + NSTAGE - 1;
            uint32_t so = (uint32_t)(s % NSTAGE) * STG_B;
            cpa16(dA + so,       gA + (size_t)s * 256);
            cpa16(dA + so + 256, gA + (size_t)s * 256 + 64);
            cpa16(dB + so,       gB + (size_t)s * 128);
            cpa16(dB + so + 16,  gB + (size_t)s * 128 + 4);
            CP_COMMIT();
        }
        if (it + 3 < NIT)      asm volatile("cp.async.wait_group 3;" ::: "memory");
        else if (it + 2 < NIT) asm volatile("cp.async.wait_group 2;" ::: "memory");
        else if (it + 1 < NIT) asm volatile("cp.async.wait_group 1;" ::: "memory");
        else                   asm volatile("cp.async.wait_group 0;" ::: "memory");
        __syncthreads();

        const uint4* As4 = (const uint4*)(dsm + (it % NSTAGE) * (STG_B / 4));
        const uint2* Bs2 = (const uint2*)(dsm + (it % NSTAGE) * (STG_B / 4) + 2048);

#pragma unroll
        for (int ks8 = 0; ks8 < 2; ks8++) {
            uint4 af[2];
#pragma unroll
            for (int i = 0; i < 2; i++)
                af[i] = As4[((wm * 2 + i) * 2 + ks8) * 32 + lane];
            uint2 bf[8];
#pragma unroll
            for (int j = 0; j < 8; j++)
                bf[j] = Bs2[((wn * 8 + j) * 2 + ks8) * 32 + lane];
#pragma unroll
            for (int i = 0; i < 2; i++)
#pragma unroll
                for (int j = 0; j < 8; j++)
                    mma8(acc[i][j], (const uint32_t*)&af[i], (const uint32_t*)&bf[j]);
        }
        __syncthreads();
    }

    int c2 = (lane & 3) * 2;
#pragma unroll
    for (int i = 0; i < 2; i++) {
#pragma unroll
        for (int j = 0; j < 8; j++) {
            int row0 = m0 + wm * 32 + i * 16 + r;
            int col  = n0 + wn * 64 + j * 8 + c2;
            if (mode == 0) {
                *(float2*)&C[(size_t)row0 * DM + col] =
                    make_float2(acc[i][j][0], acc[i][j][1]);
                *(float2*)&C[(size_t)(row0 + 8) * DM + col] =
                    make_float2(acc[i][j][2], acc[i][j][3]);
            } else {
                int bx = row0 >> 11, s0 = row0 & 2047;
                int h = col >> 6, hd = col & 63;
                float* base = C + (size_t)(bx * Hh + h) * (Sq * HD);
                if (mode == 1) {
                    base[qfrag_off(s0, hd)]         = cf_tf32(acc[i][j][0]);
                    base[qfrag_off(s0, hd + 1)]     = cf_tf32(acc[i][j][1]);
                    base[qfrag_off(s0 + 8, hd)]     = cf_tf32(acc[i][j][2]);
                    base[qfrag_off(s0 + 8, hd + 1)] = cf_tf32(acc[i][j][3]);
                } else if (mode == 2) {
                    base[kfrag_off(s0, hd)]         = cf_tf32(acc[i][j][0]);
                    base[kfrag_off(s0, hd + 1)]     = cf_tf32(acc[i][j][1]);
                    base[kfrag_off(s0 + 8, hd)]     = cf_tf32(acc[i][j][2]);
                    base[kfrag_off(s0 + 8, hd + 1)] = cf_tf32(acc[i][j][3]);
                    if (s0 + 8 == Sq - 1)
                        *(float2*)&klast[bx * DM + col] = make_float2(acc[i][j][2], acc[i][j][3]);
                } else {
                    base[vfrag_off(s0, hd)]         = cf_tf32(acc[i][j][0]);
                    base[vfrag_off(s0, hd + 1)]     = cf_tf32(acc[i][j][1]);
                    base[vfrag_off(s0 + 8, hd)]     = cf_tf32(acc[i][j][2]);
                    base[vfrag_off(s0 + 8, hd + 1)] = cf_tf32(acc[i][j][3]);
                }
            }
        }
    }
}

__global__ void __launch_bounds__(256, 2) gemm_qkv(const float* __restrict__ A,
                                                   const float* __restrict__ WT,
                                                   float* q, float* k, float* v,
                                                   float* klast)
{
    extern __shared__ float dsm[];
    int z = blockIdx.z;
    float* C = (z == 0) ? q : (z == 1) ? k : v;
    gemm_body(A, WT + (size_t)z * DM * DM, C, z + 1, (z == 1) ? klast : (float*)0, dsm);
}

__global__ void __launch_bounds__(256, 2) gemm_o(const float* __restrict__ A,
                                                 const float* __restrict__ WT,
                                                 float* __restrict__ C)
{
    extern __shared__ float dsm[];
    gemm_body(A, WT, C, 0, (float*)0, dsm);
}

// ---------------- retrieval: sims (warp per event) ------------------------
__global__ __launch_bounds__(256) void retrieve_sims(const float* __restrict__ klast,
                                                     const float* __restrict__ events,
                                                     float* __restrict__ sims)
{
    int b = blockIdx.y;
    int tid = threadIdx.x;
    int lane = tid & 31, wid = tid >> 5;
    __shared__ float qs[DM];
    __shared__ float qn_s;

    for (int d = tid; d < DM; d += 256) qs[d] = klast[b * DM + d];
    __syncthreads();
    if (wid == 0) {
        float ps = 0.f;
        for (int d = lane * 4; d < DM; d += 128) {
            float4 t = *(const float4*)&qs[d];
            ps += t.x * t.x + t.y * t.y + t.z * t.z + t.w * t.w;
        }
#pragma unroll
        for (int off = 16; off > 0; off >>= 1) ps += __shfl_down_sync(0xffffffffu, ps, off);
        if (lane == 0) qn_s = sqrtf(ps) + 1e-8f;
    }
    __syncthreads();
    float qnorm = qn_s;

    int e = blockIdx.x * 8 + wid;
    if (e >= MEMN) return;
    const float* ep = events + (size_t)e * DM;
    float dot = 0.f, nn = 0.f;
    for (int d = lane * 4; d < DM; d += 128) {
        float4 ev = *(const float4*)(ep + d);
        float4 qv = *(const float4*)&qs[d];
        dot += qv.x * ev.x + qv.y * ev.y + qv.z * ev.z + qv.w * ev.w;
        nn  += ev.x * ev.x + ev.y * ev.y + ev.z * ev.z + ev.w * ev.w;
    }
#pragma unroll
    for (int off = 16; off > 0; off >>= 1) {
        dot += __shfl_down_sync(0xffffffffu, dot, off);
        nn  += __shfl_down_sync(0xffffffffu, nn, off);
    }
    if (lane == 0) sims[b * MEMN + e] = dot / (qnorm * (sqrtf(nn) + 1e-8f));
}

// ---------------- retrieval: parallel top-k + gather (tf32-rounded) --------
__global__ __launch_bounds__(256) void topk_gather(const float* __restrict__ sims,
                                                   const float* __restrict__ events,
                                                   float* __restrict__ ret)
{
    int b = blockIdx.x;
    int tid = threadIdx.x;
    int lane = tid & 31, wid = tid >> 5;
    __shared__ float sv[MEMN];
    __shared__ float wmax[8];
    __shared__ int   widx[8];
    __shared__ int   tidx[KTOT];

    for (int e = tid; e < MEMN; e += 256) sv[e] = sims[b * MEMN + e];
    __syncthreads();

    for (int kk = 0; kk < KTOT; kk++) {
        float bm = -1e30f; int bi = MEMN;
        for (int e = tid; e < MEMN; e += 256) {
            float v = sv[e];
            if (v > bm || (v == bm && e < bi)) { bm = v; bi = e; }
        }
#pragma unroll
        for (int off = 16; off > 0; off >>= 1) {
            float om = __shfl_down_sync(0xffffffffu, bm, off);
            int   oi = __shfl_down_sync(0xffffffffu, bi, off);
            if (om > bm || (om == bm && oi < bi)) { bm = om; bi = oi; }
        }
        if (lane == 0) { wmax[wid] = bm; widx[wid] = bi; }
        __syncthreads();
        if (tid == 0) {
            float gm = wmax[0]; int gi = widx[0];
            for (int w = 1; w < 8; w++) {
                if (wmax[w] > gm || (wmax[w] == gm && widx[w] < gi)) { gm = wmax[w]; gi = widx[w]; }
            }
            tidx[kk] = gi;
            sv[gi] = -1e30f;
        }
        __syncthreads();
    }

    for (int kk = 0; kk < KTOT; kk++) {
        int src = tidx[kk];
        for (int d = tid; d < DM; d += 256)
            ret[((size_t)b * KTOT + kk) * DM + d] = cf_tf32(events[(size_t)src * DM + d]);
    }
}

// ---------------- flash v7: frag-major Q/K/V, wide LDS ---------------------
#define TKF    32
#define FST    68
#define OFF_SQ 0                         // 8192 floats (Q frag-major, 1 q-tile)
#define OFF_SP 8192                      // 8704 floats (P, row-major stride 68)
#define OFF_K2 (OFF_SP + 128 * FST)      // 2 x 2048
#define OFF_V2 (OFF_K2 + 2 * 2048)       // 2 x 2048
#define OFF_KM (OFF_V2 + 2 * 2048)       // 1024 (mem K frag)
#define OFF_VM (OFF_KM + 1024)           // 1024 (mem V frag)
#define OFF_CB (OFF_VM + 1024)           // 64
#define FSMEM_FLOATS (OFF_CB + 64)
#define FSMEM_BYTES  (FSMEM_FLOATS * 4)

__global__ void __launch_bounds__(256, 2) flash_mma(const float* __restrict__ amask,
                                                    const float* __restrict__ qbuf,
                                                    const float* __restrict__ kbuf,
                                                    const float* __restrict__ vbuf,
                                                    const float* __restrict__ ret,
                                                    float* __restrict__ att)
{
    extern __shared__ float fsm[];
    float* SP = fsm + OFF_SP;
    float* Km = fsm + OFF_KM;
    float* Vm = fsm + OFF_VM;
    float* CB = fsm + OFF_CB;
    uint32_t sbase = smem_u32(fsm);

    int qt = gridDim.x - 1 - blockIdx.x;   // heavy tiles first
    int h = blockIdx.y, b = blockIdx.z;
    int tid = threadIdx.x;
    int lane = tid & 31, w = tid >> 5;
    int r = lane >> 2, cc = lane & 3;
    int i0 = qt * 128;
    const float scale = 0.125f;
    float slope = exp2f(-0.5f * (float)(h + 1));

    const float* qfb = qbuf + (size_t)(b * Hh + h) * (Sq * HD) + (size_t)qt * 8192;
    const float* kfb = kbuf + (size_t)(b * Hh + h) * (Sq * HD);
    const float* vfb = vbuf + (size_t)(b * Hh + h) * (Sq * HD);

    // ---- stage Q (contiguous frag-major, cp.async) ----
    {
        const float* qp = qfb + tid * 32;
        uint32_t dst = sbase + (uint32_t)tid * 128;
#pragma unroll
        for (int i = 0; i < 8; i++) cpa16(dst + i * 16, qp + i * 4);
        CP_COMMIT();
    }

    // ---- tile 0 K/V (contiguous, cp.async) + memory tile (scalar frag) ----
    uint32_t dK0 = sbase + (uint32_t)(OFF_K2 + tid * 8) * 4u;
    uint32_t dV0 = sbase + (uint32_t)(OFF_V2 + tid * 8) * 4u;
    {
        const float* kp = kfb + tid * 8;
        const float* vp = vfb + tid * 8;
        cpa16(dK0, kp);      cpa16(dK0 + 16, kp + 4);
        cpa16(dV0, vp);      cpa16(dV0 + 16, vp + 4);
        CP_COMMIT();
        if (tid < TKF) CB[tid] = (1.0f - amask[b * Sq + tid]) * (-1e9f);
    }
    if (tid < 128) {
        int kk = tid >> 3, dseg = (tid & 7) * 8;
        const float* rp = ret + ((size_t)b * KTOT + kk) * DM + h * HD + dseg;
        int ktile = kk >> 3, dt = dseg >> 3;
#pragma unroll
        for (int i = 0; i < 8; i++) {
            int d = dseg + i;
            float vv = (kk < KTOT) ? rp[i] : 0.f;
            Km[((ktile * 8 + dt) * 32 + (kk & 7) * 4 + (d & 3)) * 2 + ((d >> 2) & 1)] = vv;
            Vm[((dt * 2 + ktile) * 32 + (d & 7) * 4 + (kk & 3)) * 2 + ((kk >> 2) & 1)] = vv;
        }
    }
    CP_WAIT0();
    __syncthreads();

    int row_lo = w * 16 + r, row_hi = row_lo + 8;
    int ig_lo = i0 + row_lo, ig_hi = i0 + row_hi;

    const uint4* SQ4 = (const uint4*)fsm;
    const uint2* Km2 = (const uint2*)(fsm + OFF_KM);
    const uint2* Vm2 = (const uint2*)(fsm + OFF_VM);

    float of[8][4];
#pragma unroll
    for (int f = 0; f < 8; f++)
#pragma unroll
        for (int e = 0; e < 4; e++) of[f][e] = 0.f;
    float m_lo = -1e30f, m_hi = -1e30f, l_lo = 0.f, l_hi = 0.f;

    // ================= memory pass (16 cols) =================
    {
        float sc[2][4];
#pragma unroll
        for (int f = 0; f < 2; f++)
#pragma unroll
            for (int e = 0; e < 4; e++) sc[f][e] = 0.f;
#pragma unroll
        for (int ks = 0; ks < 8; ks++) {
            uint4 aq = SQ4[(w * 8 + ks) * 32 + lane];
#pragma unroll
            for (int f = 0; f < 2; f++) {
                uint2 bb = Km2[(f * 8 + ks) * 32 + lane];
                mma8(sc[f], (const uint32_t*)&aq, (const uint32_t*)&bb);
            }
        }
        float tl = m_lo, th = m_hi;
#pragma unroll
        for (int f = 0; f < 2; f++) {
            int c0 = f * 8 + 2 * cc;
            float cb0 = CB[0] * 0.f + ((c0 < KTOT) ? 0.f : -1e30f);
            float cb1v = ((c0 + 1) < KTOT) ? 0.f : -1e30f;
            sc[f][0] = fmaf(sc[f][0], scale, cb0);
            sc[f][1] = fmaf(sc[f][1], scale, cb1v);
            sc[f][2] = fmaf(sc[f][2], scale, cb0);
            sc[f][3] = fmaf(sc[f][3], scale, cb1v);
            tl = fmaxf(tl, fmaxf(sc[f][0], sc[f][1]));
            th = fmaxf(th, fmaxf(sc[f][2], sc[f][3]));
        }
        tl = fmaxf(tl, __shfl_xor_sync(0xffffffffu, tl, 1));
        tl = fmaxf(tl, __shfl_xor_sync(0xffffffffu, tl, 2));
        th = fmaxf(th, __shfl_xor_sync(0xffffffffu, th, 1));
        th = fmaxf(th, __shfl_xor_sync(0xffffffffu, th, 2));
        float corr_lo = __expf(m_lo - tl), corr_hi = __expf(m_hi - th);
        l_lo *= corr_lo; l_hi *= corr_hi;
        m_lo = tl; m_hi = th;
        float sl = 0.f, sh = 0.f;
#pragma unroll
        for (int f = 0; f < 2; f++) {
            sc[f][0] = __expf(sc[f][0] - m_lo); sl += sc[f][0];
            sc[f][1] = __expf(sc[f][1] - m_lo); sl += sc[f][1];
            sc[f][2] = __expf(sc[f][2] - m_hi); sh += sc[f][2];
            sc[f][3] = __expf(sc[f][3] - m_hi); sh += sc[f][3];
        }
        sl += __shfl_xor_sync(0xffffffffu, sl, 1);
        sl += __shfl_xor_sync(0xffffffffu, sl, 2);
        sh += __shfl_xor_sync(0xffffffffu, sh, 1);
        sh += __shfl_xor_sync(0xffffffffu, sh, 2);
        l_lo += sl; l_hi += sh;
#pragma unroll
        for (int f = 0; f < 8; f++) {
            of[f][0] *= corr_lo; of[f][1] *= corr_lo;
            of[f][2] *= corr_hi; of[f][3] *= corr_hi;
        }
#pragma unroll
        for (int f = 0; f < 2; f++) {
            int c0 = f * 8 + 2 * cc;
            *(float2*)&SP[row_lo * FST + c0] = make_float2(cf_tf32(sc[f][0]), cf_tf32(sc[f][1]));
            *(float2*)&SP[row_hi * FST + c0] = make_float2(cf_tf32(sc[f][2]), cf_tf32(sc[f][3]));
        }
        __syncwarp();
#pragma unroll
        for (int ks = 0; ks < 2; ks++) {
            uint32_t ap[4];
            ap[0] = __float_as_uint(SP[row_lo * FST + ks * 8 + cc]);
            ap[1] = __float_as_uint(SP[row_hi * FST + ks * 8 + cc]);
            ap[2] = __float_as_uint(SP[row_lo * FST + ks * 8 + cc + 4]);
            ap[3] = __float_as_uint(SP[row_hi * FST + ks * 8 + cc + 4]);
#pragma unroll
            for (int f = 0; f < 8; f++) {
                uint2 bv = Vm2[(f * 2 + ks) * 32 + lane];
                mma8(of[f], ap, (const uint32_t*)&bv);
            }
        }
    }

    // ================= seq tiles (aligned, double-buffered) =================
    int ntiles = 4 * qt + 4;
    for (int t = 0; t < ntiles; ++t) {
        int buf = t & 1;
        int j0 = t * TKF;
        CP_WAIT0();
        __syncthreads();
        if (t + 1 < ntiles) {
            int j0n = j0 + TKF, bufn = (t + 1) & 1;
            const float* kp = kfb + (size_t)j0n * 64 + tid * 8;
            const float* vp = vfb + (size_t)j0n * 64 + tid * 8;
            uint32_t dK = dK0 + (uint32_t)(bufn * 2048) * 4u;
            uint32_t dV = dV0 + (uint32_t)(bufn * 2048) * 4u;
            cpa16(dK, kp);      cpa16(dK + 16, kp + 4);
            cpa16(dV, vp);      cpa16(dV + 16, vp + 4);
            CP_COMMIT();
            if (tid < TKF) CB[32 + (bufn ? 0 : 0)] = CB[32]; // no-op keep
            if (tid < TKF) CB[bufn ? (32 + tid) - 32 + 32 : tid + 32 - 32] =
                (1.0f - amask[b * Sq + j0n + tid]) * (-1e9f);
        }
        const uint2* Ks2 = (const uint2*)(fsm + OFF_K2) + buf * 1024;
        const uint2* Vs2 = (const uint2*)(fsm + OFF_V2) + buf * 1024;
        const float* cbp = CB + (buf ? 32 : 0) - (buf ? 32 : 0); // resolved below

        float sc[4][4];
#pragma unroll
        for (int f = 0; f < 4; f++)
#pragma unroll
            for (int e = 0; e < 4; e++) sc[f][e] = 0.f;
#pragma unroll
        for (int ks = 0; ks < 8; ks++) {
            uint4 aq = SQ4[(w * 8 + ks) * 32 + lane];
#pragma unroll
            for (int f = 0; f < 4; f++) {
                uint2 bb = Ks2[(f * 8 + ks) * 32 + lane];
                mma8(sc[f], (const uint32_t*)&aq, (const uint32_t*)&bb);
            }
        }

        bool causal = (t >= 4 * qt);
        float o0f = (float)(2 * cc);
        float tl = m_lo, th = m_hi;
        const float* cb = CB + buf * 32;
        (void)cbp;
#pragma unroll
        for (int f = 0; f < 4; f++) {
            int c0 = f * 8 + 2 * cc;
            float cb0 = cb[c0 & 31], cb1v = cb[(c0 + 1) & 31];
            float fl = (float)(ig_lo - j0 - f * 8);
            float s00 = fmaf(sc[f][0], scale, fmaf(slope, fl - o0f, cb0));
            float s01 = fmaf(sc[f][1], scale, fmaf(slope, fl - o0f - 1.0f, cb1v));
            float s10 = fmaf(sc[f][2], scale, fmaf(slope, fl + 8.0f - o0f, cb0));
            float s11 = fmaf(sc[f][3], scale, fmaf(slope, fl + 8.0f - o0f - 1.0f, cb1v));
            if (causal) {
                int jg0 = j0 + c0;
                if (jg0 > ig_lo)     s00 = -1e30f;
                if (jg0 + 1 > ig_lo) s01 = -1e30f;
                if (jg0 > ig_hi)     s10 = -1e30f;
                if (jg0 + 1 > ig_hi) s11 = -1e30f;
            }
            sc[f][0] = s00; sc[f][1] = s01; sc[f][2] = s10; sc[f][3] = s11;
            tl = fmaxf(tl, fmaxf(s00, s01));
            th = fmaxf(th, fmaxf(s10, s11));
        }
        tl = fmaxf(tl, __shfl_xor_sync(0xffffffffu, tl, 1));
        tl = fmaxf(tl, __shfl_xor_sync(0xffffffffu, tl, 2));
        th = fmaxf(th, __shfl_xor_sync(0xffffffffu, th, 1));
        th = fmaxf(th, __shfl_xor_sync(0xffffffffu, th, 2));

        float corr_lo = __expf(m_lo - tl), corr_hi = __expf(m_hi - th);
        l_lo *= corr_lo; l_hi *= corr_hi;
        m_lo = tl; m_hi = th;

        float sl = 0.f, sh = 0.f;
#pragma unroll
        for (int f = 0; f < 4; f++) {
            sc[f][0] = __expf(sc[f][0] - m_lo); sl += sc[f][0];
            sc[f][1] = __expf(sc[f][1] - m_lo); sl += sc[f][1];
            sc[f][2] = __expf(sc[f][2] - m_hi); sh += sc[f][2];
            sc[f][3] = __expf(sc[f][3] - m_hi); sh += sc[f][3];
        }
        sl += __shfl_xor_sync(0xffffffffu, sl, 1);
        sl += __shfl_xor_sync(0xffffffffu, sl, 2);
        sh += __shfl_xor_sync(0xffffffffu, sh, 1);
        sh += __shfl_xor_sync(0xffffffffu, sh, 2);
        l_lo += sl; l_hi += sh;

#pragma unroll
        for (int f = 0; f < 8; f++) {
            of[f][0] *= corr_lo; of[f][1] *= corr_lo;
            of[f][2] *= corr_hi; of[f][3] *= corr_hi;
        }

#pragma unroll
        for (int f = 0; f < 4; f++) {
            int c0 = f * 8 + 2 * cc;
            *(float2*)&SP[row_lo * FST + c0] = make_float2(cf_tf32(sc[f][0]), cf_tf32(sc[f][1]));
            *(float2*)&SP[row_hi * FST + c0] = make_float2(cf_tf32(sc[f][2]), cf_tf32(sc[f][3]));
        }
        __syncwarp();

#pragma unroll
        for (int ks = 0; ks < 4; ks++) {
            uint32_t ap[4];
            ap[0] = __float_as_uint(SP[row_lo * FST + ks * 8 + cc]);
            ap[1] = __float_as_uint(SP[row_hi * FST + ks * 8 + cc]);
            ap[2] = __float_as_uint(SP[row_lo * FST + ks * 8 + cc + 4]);
            ap[3] = __float_as_uint(SP[row_hi * FST + ks * 8 + cc + 4]);
#pragma unroll
            for (int f = 0; f < 8; f++) {
                uint2 bv = Vs2[(f * 4 + ks) * 32 + lane];
                mma8(of[f], ap, (const uint32_t*)&bv);
            }
        }
    }

    // ---- finalize: divide by l, tf32-round, store A-frag-major for gemm_o ----
    float inv_lo = 1.0f / l_lo, inv_hi = 1.0f / l_hi;
    int mlo = b * Sq + ig_lo, mhi = b * Sq + ig_hi;
#pragma unroll
    for (int f = 0; f < 8; f++) {
        int k0 = h * HD + f * 8 + 2 * cc;
        att[fragidxA(mlo, k0)]     = cf_tf32(of[f][0] * inv_lo);
        att[fragidxA(mlo, k0 + 1)] = cf_tf32(of[f][1] * inv_lo);
        att[fragidxA(mhi, k0)]     = cf_tf32(of[f][2] * inv_hi);
        att[fragidxA(mhi, k0 + 1)] = cf_tf32(of[f][3] * inv_hi);
    }
}

// ---------------- launcher ----------------
extern "C" void kernel_launch(void* const* d_in, const int* in_sizes, int n_in,
                              void* d_out, int out_size)
{
    const float* inputs = (const float*)d_in[0];
    const float* amask  = (const float*)d_in[1];
    const float* Wq     = (const float*)d_in[2];
    const float* Wk     = (const float*)d_in[3];
    const float* Wv     = (const float*)d_in[4];
    const float* Wo     = (const float*)d_in[5];
    const float* events = (const float*)d_in[6];
    float* out = (float*)d_out;

    float *q, *k, *v, *att, *ret, *sims, *wt, *ai, *klast;
    cudaGetSymbolAddress((void**)&q,     g_q);
    cudaGetSymbolAddress((void**)&k,     g_k);
    cudaGetSymbolAddress((void**)&v,     g_v);
    cudaGetSymbolAddress((void**)&att,   g_att);
    cudaGetSymbolAddress((void**)&ret,   g_ret);
    cudaGetSymbolAddress((void**)&sims,  g_sims);
    cudaGetSymbolAddress((void**)&wt,    g_wt);
    cudaGetSymbolAddress((void**)&ai,    g_ai);
    cudaGetSymbolAddress((void**)&klast, g_klast);

    cudaFuncSetAttribute(gemm_qkv,  cudaFuncAttributeMaxDynamicSharedMemorySize, GSMEM_BYTES);
    cudaFuncSetAttribute(gemm_o,    cudaFuncAttributeMaxDynamicSharedMemorySize, GSMEM_BYTES);
    cudaFuncSetAttribute(flash_mma, cudaFuncAttributeMaxDynamicSharedMemorySize, FSMEM_BYTES);

    prep_a<<<(Bq * Sq / 16) * (DM / 8) * 32 / 256, 256>>>(inputs, ai);
    transpose_w<<<dim3(32, 32, 4), 256>>>(Wq, Wk, Wv, Wo, wt);

    gemm_qkv<<<dim3(8, 32, 3), 256, GSMEM_BYTES>>>(ai, wt, q, k, v, klast);

    retrieve_sims<<<dim3(125, Bq), 256>>>(klast, events, sims);
    topk_gather<<<Bq, 256>>>(sims, events, ret);

    flash_mma<<<dim3(Sq / 128, Hh, Bq), 256, FSMEM_BYTES>>>(amask, q, k, v, ret, att);

    gemm_o<<<dim3(8, 32), 256, GSMEM_BYTES>>>(att, wt + 3 * (size_t)DM * DM, out);
}

// round 12
// speedup vs baseline: 2.7940x; 1.0234x over previous
#include <cuda_runtime.h>
#include <math.h>
#include <stdint.h>

// Problem constants
#define Bq   2
#define Sq   2048
#define DM   1024
#define Hh   16
#define HD   64
#define MEMN 1000
#define KTOT 10

// ---------------- device scratch ----------------
__device__ float g_q[Bq * Hh * Sq * HD];    // A-frag-major per (b,h,qtile)
__device__ float g_k[Bq * Hh * Sq * HD];    // QK-B-frag-major per (b,h)
__device__ float g_v[Bq * Hh * Sq * HD];    // PV-B-frag-major per (b,h)
__device__ float g_att[Bq * Sq * DM];       // A-frag-major (flash -> gemm_o)
__device__ float g_ret[Bq * KTOT * DM];
__device__ float g_sims[Bq * MEMN];
__device__ float g_wt[4 * DM * DM];         // frag-major tf32 weights (B operand)
__device__ float g_ai[Bq * Sq * DM];        // frag-major tf32 inputs (A operand)
__device__ float g_klast[Bq * DM];          // UNROUNDED last-token key

// ---------------- helpers ----------------
__device__ __forceinline__ uint32_t smem_u32(const void* p) {
    uint32_t a;
    asm("{ .reg .u64 t; cvta.to.shared.u64 t, %1; cvt.u32.u64 %0, t; }" : "=r"(a) : "l"(p));
    return a;
}
__device__ __forceinline__ float cf_tf32(float x) {
    uint32_t u;
    asm("cvt.rna.tf32.f32 %0, %1;" : "=r"(u) : "f"(x));
    return __uint_as_float(u);
}
__device__ __forceinline__ void mma8(float* c, const uint32_t* a, const uint32_t* b) {
    asm("mma.sync.aligned.m16n8k8.row.col.f32.tf32.tf32.f32 "
        "{%0,%1,%2,%3},{%4,%5,%6,%7},{%8,%9},{%0,%1,%2,%3};"
        : "+f"(c[0]), "+f"(c[1]), "+f"(c[2]), "+f"(c[3])
        : "r"(a[0]), "r"(a[1]), "r"(a[2]), "r"(a[3]), "r"(b[0]), "r"(b[1]));
}
__device__ __forceinline__ void cpa16(uint32_t d, const void* g) {
    asm volatile("cp.async.cg.shared.global [%0], [%1], 16;" :: "r"(d), "l"(g) : "memory");
}
#define CP_COMMIT() asm volatile("cp.async.commit_group;" ::: "memory")

// A-frag-major index within a generic [M, DM] matrix (prep_a / att layout)
__device__ __forceinline__ size_t fragidxA(int m, int k) {
    return ((((size_t)(m >> 4)) * (DM / 8) + (k >> 3)) * 32 + ((m & 7) * 4 + (k & 3))) * 4
           + ((m >> 3) & 1) + 2 * ((k >> 2) & 1);
}
// Q A-frag-major within one (b,h): [qtile][mtile 8][dimtile 8][lane][4]
__device__ __forceinline__ size_t qfrag_off(int s, int hd) {
    int ml = s & 127;
    return (size_t)(s >> 7) * 8192
         + (size_t)(((ml >> 4) * 8 + (hd >> 3)) * 32 + ((ml & 7) * 4 + (hd & 3))) * 4
         + ((ml >> 3) & 1) + 2 * ((hd >> 2) & 1);
}
// K QK-B-frag-major within one (b,h): [keytile 256][dimtile 8][lane][2]
__device__ __forceinline__ size_t kfrag_off(int s, int hd) {
    return ((size_t)((s >> 3) * 8 + (hd >> 3)) * 32 + ((s & 7) * 4 + (hd & 3))) * 2
           + ((hd >> 2) & 1);
}
// V PV-B-frag-major within one (b,h): [keygroup 64][dimtile 8][ktig 4][lane][2]
__device__ __forceinline__ size_t vfrag_off(int s, int hd) {
    return ((size_t)(((s >> 5) * 8 + (hd >> 3)) * 4 + ((s >> 3) & 3)) * 32
            + ((hd & 7) * 4 + (s & 3))) * 2 + ((s >> 2) & 1);
}

// ---------------- prep: inputs -> frag-major tf32 --------------------------
__global__ __launch_bounds__(256) void prep_a(const float* __restrict__ A,
                                              float* __restrict__ D)
{
    int gt = blockIdx.x * 256 + threadIdx.x;
    int tile = gt >> 5, lane = gt & 31;
    int mt = tile >> 7, kt = tile & 127;
    int m = mt * 16 + (lane >> 2), k = kt * 8 + (lane & 3);
    float4 o;
    o.x = cf_tf32(A[(size_t)m * DM + k]);
    o.y = cf_tf32(A[(size_t)(m + 8) * DM + k]);
    o.z = cf_tf32(A[(size_t)m * DM + k + 4]);
    o.w = cf_tf32(A[(size_t)(m + 8) * DM + k + 4]);
    ((float4*)D)[gt] = o;
}

// ---------------- weights -> frag-major tf32 B operand ---------------------
__global__ __launch_bounds__(256) void transpose_w(const float* __restrict__ W0,
                                                   const float* __restrict__ W1,
                                                   const float* __restrict__ W2,
                                                   const float* __restrict__ W3,
                                                   float* __restrict__ WT)
{
    __shared__ float t[32][33];
    int z = blockIdx.z;
    const float* W = (z == 0) ? W0 : (z == 1) ? W1 : (z == 2) ? W2 : W3;
    float* D = WT + (size_t)z * DM * DM;
    int x = blockIdx.x * 32, y = blockIdx.y * 32;   // x = n0, y = k0
    int tid = threadIdx.x;
    int tx = tid & 31, ty = tid >> 5;
    for (int r = ty; r < 32; r += 8)
        t[r][tx] = W[(size_t)(y + r) * DM + x + tx];
    __syncthreads();
    for (int p = tid; p < 512; p += 256) {
        int ttile = p >> 5, lane = p & 31;
        int nt_l = ttile >> 2, kt_l = ttile & 3;
        int n_l = nt_l * 8 + (lane >> 2), k_l = kt_l * 8 + (lane & 3);
        float2 o = make_float2(cf_tf32(t[k_l][n_l]), cf_tf32(t[k_l + 4][n_l]));
        ((float2*)D)[((size_t)((x >> 3) + nt_l) * (DM / 8) + (y >> 3) + kt_l) * 32 + lane] = o;
    }
}

// ---------------- frag-major cp.async tf32 mma.sync GEMM -------------------
#define NSTAGE  4
#define NIT     (DM / 16)
#define STG_B   16384
#define GSMEM_BYTES (NSTAGE * STG_B)

// mode: 0 = plain row-major out (gemm_o), 1 = Q frag, 2 = K frag (+klast), 3 = V frag
__device__ __forceinline__ void gemm_body(const float* __restrict__ A,
                                          const float* __restrict__ WT,
                                          float* __restrict__ C,
                                          int mode, float* klast, float* dsm)
{
    uint32_t sbase = smem_u32(dsm);
    int tid = threadIdx.x, lane = tid & 31, wid = tid >> 5;
    int wm = wid & 3, wn = wid >> 2;
    int m0 = blockIdx.y * 128, n0 = blockIdx.x * 128;
    int r = lane >> 2;

    int bia = tid >> 4, offa = (tid & 15) * 16;
    int bib = tid >> 3, offb = (tid & 7) * 32;
    int amt = bia >> 1, akt = bia & 1;
    int bnt = bib >> 1, bkt = bib & 1;

    const float* gA = A  + ((size_t)((m0 >> 4) + amt) * 128 + akt) * 128 + (offa >> 2);
    const float* gB = WT + ((size_t)((n0 >> 3) + bnt) * 128 + bkt) * 64  + (offb >> 2);
    uint32_t dA = sbase + (uint32_t)(bia * 512 + offa);
    uint32_t dB = sbase + 8192u + (uint32_t)(bib * 256 + offb);

    float acc[2][8][4];
#pragma unroll
    for (int i = 0; i < 2; i++)
#pragma unroll
        for (int j = 0; j < 8; j++)
#pragma unroll
            for (int t = 0; t < 4; t++) acc[i][j][t] = 0.f;

#pragma unroll
    for (int s = 0; s < NSTAGE - 1; s++) {
        uint32_t so = (uint32_t)s * STG_B;
        cpa16(dA + so,       gA + (size_t)s * 256);
        cpa16(dA + so + 256, gA + (size_t)s * 256 + 64);
        cpa16(dB + so,       gB + (size_t)s * 128);
        cpa16(dB + so + 16,  gB + (size_t)s * 128 + 4);
        CP_COMMIT();
    }

    for (int it = 0; it < NIT; ++it) {
        if (it + NSTAGE - 1 < NIT) {
            int s = it + NSTAGE - 1;
            uint32_t so = (uint32_t)(s % NSTAGE) * STG_B;
            cpa16(dA + so,       gA + (size_t)s * 256);
            cpa16(dA + so + 256, gA + (size_t)s * 256 + 64);
            cpa16(dB + so,       gB + (size_t)s * 128);
            cpa16(dB + so + 16,  gB + (size_t)s * 128 + 4);
            CP_COMMIT();
        }
        if (it + 3 < NIT)      asm volatile("cp.async.wait_group 3;" ::: "memory");
        else if (it + 2 < NIT) asm volatile("cp.async.wait_group 2;" ::: "memory");
        else if (it + 1 < NIT) asm volatile("cp.async.wait_group 1;" ::: "memory");
        else                   asm volatile("cp.async.wait_group 0;" ::: "memory");
        __syncthreads();

        const uint4* As4 = (const uint4*)(dsm + (it % NSTAGE) * (STG_B / 4));
        const uint2* Bs2 = (const uint2*)(dsm + (it % NSTAGE) * (STG_B / 4) + 2048);

#pragma unroll
        for (int ks8 = 0; ks8 < 2; ks8++) {
            uint4 af[2];
#pragma unroll
            for (int i = 0; i < 2; i++)
                af[i] = As4[((wm * 2 + i) * 2 + ks8) * 32 + lane];
            uint2 bf[8];
#pragma unroll
            for (int j = 0; j < 8; j++)
                bf[j] = Bs2[((wn * 8 + j) * 2 + ks8) * 32 + lane];
#pragma unroll
            for (int i = 0; i < 2; i++)
#pragma unroll
                for (int j = 0; j < 8; j++)
                    mma8(acc[i][j], (const uint32_t*)&af[i], (const uint32_t*)&bf[j]);
        }
        __syncthreads();
    }

    int c2 = (lane & 3) * 2;
#pragma unroll
    for (int i = 0; i < 2; i++) {
#pragma unroll
        for (int j = 0; j < 8; j++) {
            int row0 = m0 + wm * 32 + i * 16 + r;
            int col  = n0 + wn * 64 + j * 8 + c2;
            if (mode == 0) {
                *(float2*)&C[(size_t)row0 * DM + col] =
                    make_float2(acc[i][j][0], acc[i][j][1]);
                *(float2*)&C[(size_t)(row0 + 8) * DM + col] =
                    make_float2(acc[i][j][2], acc[i][j][3]);
            } else {
                int bx = row0 >> 11, s0 = row0 & 2047;
                int h = col >> 6, hd = col & 63;
                float* base = C + (size_t)(bx * Hh + h) * (Sq * HD);
                if (mode == 1) {
                    base[qfrag_off(s0, hd)]         = cf_tf32(acc[i][j][0]);
                    base[qfrag_off(s0, hd + 1)]     = cf_tf32(acc[i][j][1]);
                    base[qfrag_off(s0 + 8, hd)]     = cf_tf32(acc[i][j][2]);
                    base[qfrag_off(s0 + 8, hd + 1)] = cf_tf32(acc[i][j][3]);
                } else if (mode == 2) {
                    base[kfrag_off(s0, hd)]         = cf_tf32(acc[i][j][0]);
                    base[kfrag_off(s0, hd + 1)]     = cf_tf32(acc[i][j][1]);
                    base[kfrag_off(s0 + 8, hd)]     = cf_tf32(acc[i][j][2]);
                    base[kfrag_off(s0 + 8, hd + 1)] = cf_tf32(acc[i][j][3]);
                    if (s0 + 8 == Sq - 1)
                        *(float2*)&klast[bx * DM + col] = make_float2(acc[i][j][2], acc[i][j][3]);
                } else {
                    base[vfrag_off(s0, hd)]         = cf_tf32(acc[i][j][0]);
                    base[vfrag_off(s0, hd + 1)]     = cf_tf32(acc[i][j][1]);
                    base[vfrag_off(s0 + 8, hd)]     = cf_tf32(acc[i][j][2]);
                    base[vfrag_off(s0 + 8, hd + 1)] = cf_tf32(acc[i][j][3]);
                }
            }
        }
    }
}

__global__ void __launch_bounds__(256, 2) gemm_qkv(const float* __restrict__ A,
                                                   const float* __restrict__ WT,
                                                   float* q, float* k, float* v,
                                                   float* klast)
{
    extern __shared__ float dsm[];
    int z = blockIdx.z;
    float* C = (z == 0) ? q : (z == 1) ? k : v;
    gemm_body(A, WT + (size_t)z * DM * DM, C, z + 1, (z == 1) ? klast : (float*)0, dsm);
}

__global__ void __launch_bounds__(256, 2) gemm_o(const float* __restrict__ A,
                                                 const float* __restrict__ WT,
                                                 float* __restrict__ C)
{
    extern __shared__ float dsm[];
    gemm_body(A, WT, C, 0, (float*)0, dsm);
}

// ---------------- retrieval: sims (warp per event) ------------------------
__global__ __launch_bounds__(256) void retrieve_sims(const float* __restrict__ klast,
                                                     const float* __restrict__ events,
                                                     float* __restrict__ sims)
{
    int b = blockIdx.y;
    int tid = threadIdx.x;
    int lane = tid & 31, wid = tid >> 5;
    __shared__ float qs[DM];
    __shared__ float qn_s;

    for (int d = tid; d < DM; d += 256) qs[d] = klast[b * DM + d];
    __syncthreads();
    if (wid == 0) {
        float ps = 0.f;
        for (int d = lane * 4; d < DM; d += 128) {
            float4 t = *(const float4*)&qs[d];
            ps += t.x * t.x + t.y * t.y + t.z * t.z + t.w * t.w;
        }
#pragma unroll
        for (int off = 16; off > 0; off >>= 1) ps += __shfl_down_sync(0xffffffffu, ps, off);
        if (lane == 0) qn_s = sqrtf(ps) + 1e-8f;
    }
    __syncthreads();
    float qnorm = qn_s;

    int e = blockIdx.x * 8 + wid;
    if (e >= MEMN) return;
    const float* ep = events + (size_t)e * DM;
    float dot = 0.f, nn = 0.f;
    for (int d = lane * 4; d < DM; d += 128) {
        float4 ev = *(const float4*)(ep + d);
        float4 qv = *(const float4*)&qs[d];
        dot += qv.x * ev.x + qv.y * ev.y + qv.z * ev.z + qv.w * ev.w;
        nn  += ev.x * ev.x + ev.y * ev.y + ev.z * ev.z + ev.w * ev.w;
    }
#pragma unroll
    for (int off = 16; off > 0; off >>= 1) {
        dot += __shfl_down_sync(0xffffffffu, dot, off);
        nn  += __shfl_down_sync(0xffffffffu, nn, off);
    }
    if (lane == 0) sims[b * MEMN + e] = dot / (qnorm * (sqrtf(nn) + 1e-8f));
}

// ---------------- retrieval: parallel top-k + gather (tf32-rounded) --------
__global__ __launch_bounds__(256) void topk_gather(const float* __restrict__ sims,
                                                   const float* __restrict__ events,
                                                   float* __restrict__ ret)
{
    int b = blockIdx.x;
    int tid = threadIdx.x;
    int lane = tid & 31, wid = tid >> 5;
    __shared__ float sv[MEMN];
    __shared__ float wmax[8];
    __shared__ int   widx[8];
    __shared__ int   tidx[KTOT];

    for (int e = tid; e < MEMN; e += 256) sv[e] = sims[b * MEMN + e];
    __syncthreads();

    for (int kk = 0; kk < KTOT; kk++) {
        float bm = -1e30f; int bi = MEMN;
        for (int e = tid; e < MEMN; e += 256) {
            float v = sv[e];
            if (v > bm || (v == bm && e < bi)) { bm = v; bi = e; }
        }
#pragma unroll
        for (int off = 16; off > 0; off >>= 1) {
            float om = __shfl_down_sync(0xffffffffu, bm, off);
            int   oi = __shfl_down_sync(0xffffffffu, bi, off);
            if (om > bm || (om == bm && oi < bi)) { bm = om; bi = oi; }
        }
        if (lane == 0) { wmax[wid] = bm; widx[wid] = bi; }
        __syncthreads();
        if (tid == 0) {
            float gm = wmax[0]; int gi = widx[0];
            for (int w = 1; w < 8; w++) {
                if (wmax[w] > gm || (wmax[w] == gm && widx[w] < gi)) { gm = wmax[w]; gi = widx[w]; }
            }
            tidx[kk] = gi;
            sv[gi] = -1e30f;
        }
        __syncthreads();
    }

    for (int kk = 0; kk < KTOT; kk++) {
        int src = tidx[kk];
        for (int d = tid; d < DM; d += 256)
            ret[((size_t)b * KTOT + kk) * DM + d] = cf_tf32(events[(size_t)src * DM + d]);
    }
}

// ---------------- flash v8: Q in regs, quad-buffered K/V (depth-2 prefetch)
#define TKF    32
#define FST    68
#define OFF_SP 0                          // 8704 floats (P, row-major stride 68)
#define OFF_K2 (128 * FST)                // 4 x 2048
#define OFF_V2 (OFF_K2 + 4 * 2048)        // 4 x 2048
#define OFF_KM (OFF_V2 + 4 * 2048)        // 1024 (mem K frag)
#define OFF_VM (OFF_KM + 1024)            // 1024 (mem V frag)
#define OFF_CB (OFF_VM + 1024)            // 128 (4 x 32 mask bias ring)
#define FSMEM_FLOATS (OFF_CB + 128)
#define FSMEM_BYTES  (FSMEM_FLOATS * 4)

__global__ void __launch_bounds__(256, 2) flash_mma(const float* __restrict__ amask,
                                                    const float* __restrict__ qbuf,
                                                    const float* __restrict__ kbuf,
                                                    const float* __restrict__ vbuf,
                                                    const float* __restrict__ ret,
                                                    float* __restrict__ att)
{
    extern __shared__ float fsm[];
    float* SP = fsm + OFF_SP;
    float* Km = fsm + OFF_KM;
    float* Vm = fsm + OFF_VM;
    float* CB = fsm + OFF_CB;
    uint32_t sbase = smem_u32(fsm);

    int qt = gridDim.x - 1 - blockIdx.x;   // heavy tiles first
    int h = blockIdx.y, b = blockIdx.z;
    int tid = threadIdx.x;
    int lane = tid & 31, w = tid >> 5;
    int r = lane >> 2, cc = lane & 3;
    int i0 = qt * 128;
    const float scale = 0.125f;
    float slope = exp2f(-0.5f * (float)(h + 1));

    const float* qfb = qbuf + (size_t)(b * Hh + h) * (Sq * HD) + (size_t)qt * 8192;
    const float* kfb = kbuf + (size_t)(b * Hh + h) * (Sq * HD);
    const float* vfb = vbuf + (size_t)(b * Hh + h) * (Sq * HD);

    int ntiles = 4 * qt + 4;

    // ---- prologue: stage K/V tiles 0..2 (one commit group each) ----
    uint32_t dK0 = sbase + (uint32_t)(OFF_K2 + tid * 8) * 4u;
    uint32_t dV0 = sbase + (uint32_t)(OFF_V2 + tid * 8) * 4u;
#pragma unroll
    for (int s = 0; s < 3; s++) {
        const float* kp = kfb + s * 2048 + tid * 8;
        const float* vp = vfb + s * 2048 + tid * 8;
        uint32_t dK = dK0 + (uint32_t)(s * 2048) * 4u;
        uint32_t dV = dV0 + (uint32_t)(s * 2048) * 4u;
        cpa16(dK, kp);      cpa16(dK + 16, kp + 4);
        cpa16(dV, vp);      cpa16(dV + 16, vp + 4);
        CP_COMMIT();
    }
    if (tid < 96) CB[tid] = (1.0f - amask[b * Sq + tid]) * (-1e9f);

    // ---- Q fragments into registers (coalesced LDG.128 from frag-major) ----
    uint4 aq[8];
    {
        const uint4* qg = (const uint4*)qfb;
#pragma unroll
        for (int ks = 0; ks < 8; ks++) aq[ks] = qg[(w * 8 + ks) * 32 + lane];
    }

    // ---- memory tile (10 keys + 6 pad) into frag-major side buffers ----
    if (tid < 128) {
        int kk = tid >> 3, dseg = (tid & 7) * 8;
        const float* rp = ret + ((size_t)b * KTOT + kk) * DM + h * HD + dseg;
        int ktile = kk >> 3, dt = dseg >> 3;
#pragma unroll
        for (int i = 0; i < 8; i++) {
            int d = dseg + i;
            float vv = (kk < KTOT) ? rp[i] : 0.f;
            Km[((ktile * 8 + dt) * 32 + (kk & 7) * 4 + (d & 3)) * 2 + ((d >> 2) & 1)] = vv;
            Vm[((dt * 2 + ktile) * 32 + (d & 7) * 4 + (kk & 3)) * 2 + ((kk >> 2) & 1)] = vv;
        }
    }
    __syncthreads();

    int row_lo = w * 16 + r, row_hi = row_lo + 8;
    int ig_lo = i0 + row_lo, ig_hi = i0 + row_hi;

    const uint2* Km2 = (const uint2*)(fsm + OFF_KM);
    const uint2* Vm2 = (const uint2*)(fsm + OFF_VM);

    float of[8][4];
#pragma unroll
    for (int f = 0; f < 8; f++)
#pragma unroll
        for (int e = 0; e < 4; e++) of[f][e] = 0.f;
    float m_lo = -1e30f, m_hi = -1e30f, l_lo = 0.f, l_hi = 0.f;

    // ================= memory pass (16 cols) =================
    {
        float sc[2][4];
#pragma unroll
        for (int f = 0; f < 2; f++)
#pragma unroll
            for (int e = 0; e < 4; e++) sc[f][e] = 0.f;
#pragma unroll
        for (int ks = 0; ks < 8; ks++) {
#pragma unroll
            for (int f = 0; f < 2; f++) {
                uint2 bb = Km2[(f * 8 + ks) * 32 + lane];
                mma8(sc[f], (const uint32_t*)&aq[ks], (const uint32_t*)&bb);
            }
        }
        float tl = m_lo, th = m_hi;
#pragma unroll
        for (int f = 0; f < 2; f++) {
            int c0 = f * 8 + 2 * cc;
            float cb0  = (c0 < KTOT) ? 0.f : -1e30f;
            float cb1v = ((c0 + 1) < KTOT) ? 0.f : -1e30f;
            sc[f][0] = fmaf(sc[f][0], scale, cb0);
            sc[f][1] = fmaf(sc[f][1], scale, cb1v);
            sc[f][2] = fmaf(sc[f][2], scale, cb0);
            sc[f][3] = fmaf(sc[f][3], scale, cb1v);
            tl = fmaxf(tl, fmaxf(sc[f][0], sc[f][1]));
            th = fmaxf(th, fmaxf(sc[f][2], sc[f][3]));
        }
        tl = fmaxf(tl, __shfl_xor_sync(0xffffffffu, tl, 1));
        tl = fmaxf(tl, __shfl_xor_sync(0xffffffffu, tl, 2));
        th = fmaxf(th, __shfl_xor_sync(0xffffffffu, th, 1));
        th = fmaxf(th, __shfl_xor_sync(0xffffffffu, th, 2));
        float corr_lo = __expf(m_lo - tl), corr_hi = __expf(m_hi - th);
        l_lo *= corr_lo; l_hi *= corr_hi;
        m_lo = tl; m_hi = th;
        float sl = 0.f, sh = 0.f;
#pragma unroll
        for (int f = 0; f < 2; f++) {
            sc[f][0] = __expf(sc[f][0] - m_lo); sl += sc[f][0];
            sc[f][1] = __expf(sc[f][1] - m_lo); sl += sc[f][1];
            sc[f][2] = __expf(sc[f][2] - m_hi); sh += sc[f][2];
            sc[f][3] = __expf(sc[f][3] - m_hi); sh += sc[f][3];
        }
        sl += __shfl_xor_sync(0xffffffffu, sl, 1);
        sl += __shfl_xor_sync(0xffffffffu, sl, 2);
        sh += __shfl_xor_sync(0xffffffffu, sh, 1);
        sh += __shfl_xor_sync(0xffffffffu, sh, 2);
        l_lo += sl; l_hi += sh;
#pragma unroll
        for (int f = 0; f < 8; f++) {
            of[f][0] *= corr_lo; of[f][1] *= corr_lo;
            of[f][2] *= corr_hi; of[f][3] *= corr_hi;
        }
#pragma unroll
        for (int f = 0; f < 2; f++) {
            int c0 = f * 8 + 2 * cc;
            *(float2*)&SP[row_lo * FST + c0] = make_float2(cf_tf32(sc[f][0]), cf_tf32(sc[f][1]));
            *(float2*)&SP[row_hi * FST + c0] = make_float2(cf_tf32(sc[f][2]), cf_tf32(sc[f][3]));
        }
        __syncwarp();
#pragma unroll
        for (int ks = 0; ks < 2; ks++) {
            uint32_t ap[4];
            ap[0] = __float_as_uint(SP[row_lo * FST + ks * 8 + cc]);
            ap[1] = __float_as_uint(SP[row_hi * FST + ks * 8 + cc]);
            ap[2] = __float_as_uint(SP[row_lo * FST + ks * 8 + cc + 4]);
            ap[3] = __float_as_uint(SP[row_hi * FST + ks * 8 + cc + 4]);
#pragma unroll
            for (int f = 0; f < 8; f++) {
                uint2 bv = Vm2[(f * 2 + ks) * 32 + lane];
                mma8(of[f], ap, (const uint32_t*)&bv);
            }
        }
    }

    // ================= seq tiles (quad-buffered, prefetch depth 2) ==========
    for (int t = 0; t < ntiles; ++t) {
        int buf = t & 3;
        int j0 = t * TKF;
        asm volatile("cp.async.wait_group 2;" ::: "memory");   // tile t retired
        __syncthreads();
        if (t + 3 < ntiles) {
            int tn = t + 3, bufn = tn & 3;
            const float* kp = kfb + (size_t)tn * 2048 + tid * 8;
            const float* vp = vfb + (size_t)tn * 2048 + tid * 8;
            uint32_t dK = dK0 + (uint32_t)(bufn * 2048) * 4u;
            uint32_t dV = dV0 + (uint32_t)(bufn * 2048) * 4u;
            cpa16(dK, kp);      cpa16(dK + 16, kp + 4);
            cpa16(dV, vp);      cpa16(dV + 16, vp + 4);
            CP_COMMIT();
            if (tid < TKF)
                CB[bufn * 32 + tid] = (1.0f - amask[b * Sq + tn * TKF + tid]) * (-1e9f);
        }
        const uint2* Ks2 = (const uint2*)(fsm + OFF_K2) + buf * 1024;
        const uint2* Vs2 = (const uint2*)(fsm + OFF_V2) + buf * 1024;
        const float* cb = CB + buf * 32;

        float sc[4][4];
#pragma unroll
        for (int f = 0; f < 4; f++)
#pragma unroll
            for (int e = 0; e < 4; e++) sc[f][e] = 0.f;
#pragma unroll
        for (int ks = 0; ks < 8; ks++) {
#pragma unroll
            for (int f = 0; f < 4; f++) {
                uint2 bb = Ks2[(f * 8 + ks) * 32 + lane];
                mma8(sc[f], (const uint32_t*)&aq[ks], (const uint32_t*)&bb);
            }
        }

        bool causal = (t >= 4 * qt);
        float o0f = (float)(2 * cc);
        float tl = m_lo, th = m_hi;
#pragma unroll
        for (int f = 0; f < 4; f++) {
            int c0 = f * 8 + 2 * cc;
            float cb0 = cb[c0], cb1v = cb[c0 + 1];
            float fl = (float)(ig_lo - j0 - f * 8);
            float s00 = fmaf(sc[f][0], scale, fmaf(slope, fl - o0f, cb0));
            float s01 = fmaf(sc[f][1], scale, fmaf(slope, fl - o0f - 1.0f, cb1v));
            float s10 = fmaf(sc[f][2], scale, fmaf(slope, fl + 8.0f - o0f, cb0));
            float s11 = fmaf(sc[f][3], scale, fmaf(slope, fl + 8.0f - o0f - 1.0f, cb1v));
            if (causal) {
                int jg0 = j0 + c0;
                if (jg0 > ig_lo)     s00 = -1e30f;
                if (jg0 + 1 > ig_lo) s01 = -1e30f;
                if (jg0 > ig_hi)     s10 = -1e30f;
                if (jg0 + 1 > ig_hi) s11 = -1e30f;
            }
            sc[f][0] = s00; sc[f][1] = s01; sc[f][2] = s10; sc[f][3] = s11;
            tl = fmaxf(tl, fmaxf(s00, s01));
            th = fmaxf(th, fmaxf(s10, s11));
        }
        tl = fmaxf(tl, __shfl_xor_sync(0xffffffffu, tl, 1));
        tl = fmaxf(tl, __shfl_xor_sync(0xffffffffu, tl, 2));
        th = fmaxf(th, __shfl_xor_sync(0xffffffffu, th, 1));
        th = fmaxf(th, __shfl_xor_sync(0xffffffffu, th, 2));

        float corr_lo = __expf(m_lo - tl), corr_hi = __expf(m_hi - th);
        l_lo *= corr_lo; l_hi *= corr_hi;
        m_lo = tl; m_hi = th;

        float sl = 0.f, sh = 0.f;
#pragma unroll
        for (int f = 0; f < 4; f++) {
            sc[f][0] = __expf(sc[f][0] - m_lo); sl += sc[f][0];
            sc[f][1] = __expf(sc[f][1] - m_lo); sl += sc[f][1];
            sc[f][2] = __expf(sc[f][2] - m_hi); sh += sc[f][2];
            sc[f][3] = __expf(sc[f][3] - m_hi); sh += sc[f][3];
        }
        sl += __shfl_xor_sync(0xffffffffu, sl, 1);
        sl += __shfl_xor_sync(0xffffffffu, sl, 2);
        sh += __shfl_xor_sync(0xffffffffu, sh, 1);
        sh += __shfl_xor_sync(0xffffffffu, sh, 2);
        l_lo += sl; l_hi += sh;

#pragma unroll
        for (int f = 0; f < 8; f++) {
            of[f][0] *= corr_lo; of[f][1] *= corr_lo;
            of[f][2] *= corr_hi; of[f][3] *= corr_hi;
        }

#pragma unroll
        for (int f = 0; f < 4; f++) {
            int c0 = f * 8 + 2 * cc;
            *(float2*)&SP[row_lo * FST + c0] = make_float2(cf_tf32(sc[f][0]), cf_tf32(sc[f][1]));
            *(float2*)&SP[row_hi * FST + c0] = make_float2(cf_tf32(sc[f][2]), cf_tf32(sc[f][3]));
        }
        __syncwarp();

#pragma unroll
        for (int ks = 0; ks < 4; ks++) {
            uint32_t ap[4];
            ap[0] = __float_as_uint(SP[row_lo * FST + ks * 8 + cc]);
            ap[1] = __float_as_uint(SP[row_hi * FST + ks * 8 + cc]);
            ap[2] = __float_as_uint(SP[row_lo * FST + ks * 8 + cc + 4]);
            ap[3] = __float_as_uint(SP[row_hi * FST + ks * 8 + cc + 4]);
#pragma unroll
            for (int f = 0; f < 8; f++) {
                uint2 bv = Vs2[(f * 4 + ks) * 32 + lane];
                mma8(of[f], ap, (const uint32_t*)&bv);
            }
        }
    }

    // ---- finalize: divide by l, tf32-round, store A-frag-major for gemm_o ----
    float inv_lo = 1.0f / l_lo, inv_hi = 1.0f / l_hi;
    int mlo = b * Sq + ig_lo, mhi = b * Sq + ig_hi;
#pragma unroll
    for (int f = 0; f < 8; f++) {
        int k0 = h * HD + f * 8 + 2 * cc;
        att[fragidxA(mlo, k0)]     = cf_tf32(of[f][0] * inv_lo);
        att[fragidxA(mlo, k0 + 1)] = cf_tf32(of[f][1] * inv_lo);
        att[fragidxA(mhi, k0)]     = cf_tf32(of[f][2] * inv_hi);
        att[fragidxA(mhi, k0 + 1)] = cf_tf32(of[f][3] * inv_hi);
    }
}

// ---------------- launcher ----------------
extern "C" void kernel_launch(void* const* d_in, const int* in_sizes, int n_in,
                              void* d_out, int out_size)
{
    const float* inputs = (const float*)d_in[0];
    const float* amask  = (const float*)d_in[1];
    const float* Wq     = (const float*)d_in[2];
    const float* Wk     = (const float*)d_in[3];
    const float* Wv     = (const float*)d_in[4];
    const float* Wo     = (const float*)d_in[5];
    const float* events = (const float*)d_in[6];
    float* out = (float*)d_out;

    float *q, *k, *v, *att, *ret, *sims, *wt, *ai, *klast;
    cudaGetSymbolAddress((void**)&q,     g_q);
    cudaGetSymbolAddress((void**)&k,     g_k);
    cudaGetSymbolAddress((void**)&v,     g_v);
    cudaGetSymbolAddress((void**)&att,   g_att);
    cudaGetSymbolAddress((void**)&ret,   g_ret);
    cudaGetSymbolAddress((void**)&sims,  g_sims);
    cudaGetSymbolAddress((void**)&wt,    g_wt);
    cudaGetSymbolAddress((void**)&ai,    g_ai);
    cudaGetSymbolAddress((void**)&klast, g_klast);

    cudaFuncSetAttribute(gemm_qkv,  cudaFuncAttributeMaxDynamicSharedMemorySize, GSMEM_BYTES);
    cudaFuncSetAttribute(gemm_o,    cudaFuncAttributeMaxDynamicSharedMemorySize, GSMEM_BYTES);
    cudaFuncSetAttribute(flash_mma, cudaFuncAttributeMaxDynamicSharedMemorySize, FSMEM_BYTES);

    prep_a<<<(Bq * Sq / 16) * (DM / 8) * 32 / 256, 256>>>(inputs, ai);
    transpose_w<<<dim3(32, 32, 4), 256>>>(Wq, Wk, Wv, Wo, wt);

    gemm_qkv<<<dim3(8, 32, 3), 256, GSMEM_BYTES>>>(ai, wt, q, k, v, klast);

    retrieve_sims<<<dim3(125, Bq), 256>>>(klast, events, sims);
    topk_gather<<<Bq, 256>>>(sims, events, ret);

    flash_mma<<<dim3(Sq / 128, Hh, Bq), 256, FSMEM_BYTES>>>(amask, q, k, v, ret, att);

    gemm_o<<<dim3(8, 32), 256, GSMEM_BYTES>>>(att, wt + 3 * (size_t)DM * DM, out);
}

// round 13
// speedup vs baseline: 2.9163x; 1.0438x over previous
#include <cuda_runtime.h>
#include <math.h>
#include <stdint.h>

// Problem constants
#define Bq   2
#define Sq   2048
#define DM   1024
#define Hh   16
#define HD   64
#define MEMN 1000
#define KTOT 10

// ---------------- device scratch ----------------
__device__ float g_q[Bq * Hh * Sq * HD];    // A-frag-major per (b,h,qtile)
__device__ float g_k[Bq * Hh * Sq * HD];    // QK-B-frag-major per (b,h)
__device__ float g_v[Bq * Hh * Sq * HD];    // PV-B-frag-major per (b,h)
__device__ float g_att[Bq * Sq * DM];       // A-frag-major (flash -> gemm_o)
__device__ float g_ret[Bq * KTOT * DM];
__device__ float g_sims[Bq * MEMN];
__device__ float g_wt[4 * DM * DM];         // frag-major tf32 weights (B operand)
__device__ float g_ai[Bq * Sq * DM];        // frag-major tf32 inputs (A operand)
__device__ float g_klast[Bq * DM];          // UNROUNDED last-token key

// ---------------- helpers ----------------
__device__ __forceinline__ uint32_t smem_u32(const void* p) {
    uint32_t a;
    asm("{ .reg .u64 t; cvta.to.shared.u64 t, %1; cvt.u32.u64 %0, t; }" : "=r"(a) : "l"(p));
    return a;
}
__device__ __forceinline__ float cf_tf32(float x) {
    uint32_t u;
    asm("cvt.rna.tf32.f32 %0, %1;" : "=r"(u) : "f"(x));
    return __uint_as_float(u);
}
__device__ __forceinline__ void mma8(float* c, const uint32_t* a, const uint32_t* b) {
    asm("mma.sync.aligned.m16n8k8.row.col.f32.tf32.tf32.f32 "
        "{%0,%1,%2,%3},{%4,%5,%6,%7},{%8,%9},{%0,%1,%2,%3};"
        : "+f"(c[0]), "+f"(c[1]), "+f"(c[2]), "+f"(c[3])
        : "r"(a[0]), "r"(a[1]), "r"(a[2]), "r"(a[3]), "r"(b[0]), "r"(b[1]));
}
__device__ __forceinline__ void cpa16(uint32_t d, const void* g) {
    asm volatile("cp.async.cg.shared.global [%0], [%1], 16;" :: "r"(d), "l"(g) : "memory");
}
#define CP_COMMIT() asm volatile("cp.async.commit_group;" ::: "memory")

// A-frag-major index within a generic [M, DM] matrix (prep_a / att layout)
__device__ __forceinline__ size_t fragidxA(int m, int k) {
    return ((((size_t)(m >> 4)) * (DM / 8) + (k >> 3)) * 32 + ((m & 7) * 4 + (k & 3))) * 4
           + ((m >> 3) & 1) + 2 * ((k >> 2) & 1);
}
// Q A-frag-major within one (b,h): [qtile][mtile 8][dimtile 8][lane][4]
__device__ __forceinline__ size_t qfrag_off(int s, int hd) {
    int ml = s & 127;
    return (size_t)(s >> 7) * 8192
         + (size_t)(((ml >> 4) * 8 + (hd >> 3)) * 32 + ((ml & 7) * 4 + (hd & 3))) * 4
         + ((ml >> 3) & 1) + 2 * ((hd >> 2) & 1);
}
// K QK-B-frag-major within one (b,h): [keytile 256][dimtile 8][lane][2]
__device__ __forceinline__ size_t kfrag_off(int s, int hd) {
    return ((size_t)((s >> 3) * 8 + (hd >> 3)) * 32 + ((s & 7) * 4 + (hd & 3))) * 2
           + ((hd >> 2) & 1);
}
// V PV-B-frag-major within one (b,h): [keygroup 64][dimtile 8][ktig 4][lane][2]
__device__ __forceinline__ size_t vfrag_off(int s, int hd) {
    return ((size_t)(((s >> 5) * 8 + (hd >> 3)) * 4 + ((s >> 3) & 3)) * 32
            + ((hd & 7) * 4 + (s & 3))) * 2 + ((s >> 2) & 1);
}

// ---------------- prep: inputs -> frag-major tf32 --------------------------
__global__ __launch_bounds__(256) void prep_a(const float* __restrict__ A,
                                              float* __restrict__ D)
{
    int gt = blockIdx.x * 256 + threadIdx.x;
    int tile = gt >> 5, lane = gt & 31;
    int mt = tile >> 7, kt = tile & 127;
    int m = mt * 16 + (lane >> 2), k = kt * 8 + (lane & 3);
    float4 o;
    o.x = cf_tf32(A[(size_t)m * DM + k]);
    o.y = cf_tf32(A[(size_t)(m + 8) * DM + k]);
    o.z = cf_tf32(A[(size_t)m * DM + k + 4]);
    o.w = cf_tf32(A[(size_t)(m + 8) * DM + k + 4]);
    ((float4*)D)[gt] = o;
}

// ---------------- weights -> frag-major tf32 B operand ---------------------
__global__ __launch_bounds__(256) void transpose_w(const float* __restrict__ W0,
                                                   const float* __restrict__ W1,
                                                   const float* __restrict__ W2,
                                                   const float* __restrict__ W3,
                                                   float* __restrict__ WT)
{
    __shared__ float t[32][33];
    int z = blockIdx.z;
    const float* W = (z == 0) ? W0 : (z == 1) ? W1 : (z == 2) ? W2 : W3;
    float* D = WT + (size_t)z * DM * DM;
    int x = blockIdx.x * 32, y = blockIdx.y * 32;   // x = n0, y = k0
    int tid = threadIdx.x;
    int tx = tid & 31, ty = tid >> 5;
    for (int r = ty; r < 32; r += 8)
        t[r][tx] = W[(size_t)(y + r) * DM + x + tx];
    __syncthreads();
    for (int p = tid; p < 512; p += 256) {
        int ttile = p >> 5, lane = p & 31;
        int nt_l = ttile >> 2, kt_l = ttile & 3;
        int n_l = nt_l * 8 + (lane >> 2), k_l = kt_l * 8 + (lane & 3);
        float2 o = make_float2(cf_tf32(t[k_l][n_l]), cf_tf32(t[k_l + 4][n_l]));
        ((float2*)D)[((size_t)((x >> 3) + nt_l) * (DM / 8) + (y >> 3) + kt_l) * 32 + lane] = o;
    }
}

// ---------------- frag-major cp.async tf32 mma.sync GEMM, K-slab 32 --------
#define GNIT   (DM / 32)          // 32 iterations
#define GSTG_B 32768              // 16KB A + 16KB B per stage
#define GSMEM_BYTES (3 * GSTG_B)

// mode: 0 = plain row-major out (gemm_o), 1 = Q frag, 2 = K frag (+klast), 3 = V frag
__device__ __forceinline__ void gemm_body(const float* __restrict__ A,
                                          const float* __restrict__ WT,
                                          float* __restrict__ C,
                                          int mode, float* klast, float* dsm)
{
    uint32_t sbase = smem_u32(dsm);
    int tid = threadIdx.x, lane = tid & 31, wid = tid >> 5;
    int wm = wid & 3, wn = wid >> 2;
    int m0 = blockIdx.y * 128, n0 = blockIdx.x * 128;
    int r = lane >> 2;

    // staging map: A = 8 chunks of 2KB (one mtile, 4 ktiles); B = 16 chunks of 1KB
    int ca = tid >> 5, ua = tid & 31;
    int cb = tid >> 4, ub = tid & 15;
    const float* gA = A  + (size_t)((m0 >> 4) + ca) * 16384 + ua * 4;
    const float* gB = WT + (size_t)((n0 >> 3) + cb) * 8192  + ub * 4;
    uint32_t dA = sbase + (uint32_t)(ca * 2048 + ua * 16);
    uint32_t dB = sbase + 16384u + (uint32_t)(cb * 1024 + ub * 16);

    float acc[2][8][4];
#pragma unroll
    for (int i = 0; i < 2; i++)
#pragma unroll
        for (int j = 0; j < 8; j++)
#pragma unroll
            for (int t = 0; t < 4; t++) acc[i][j][t] = 0.f;

    // prologue: stages 0, 1
#pragma unroll
    for (int s = 0; s < 2; s++) {
        uint32_t so = (uint32_t)s * GSTG_B;
#pragma unroll
        for (int j = 0; j < 4; j++) {
            cpa16(dA + so + j * 512, gA + s * 512 + j * 128);
            cpa16(dB + so + j * 256, gB + s * 256 + j * 64);
        }
        CP_COMMIT();
    }

    for (int it = 0; it < GNIT; ++it) {
        if (it + 1 < GNIT) asm volatile("cp.async.wait_group 1;" ::: "memory");
        else               asm volatile("cp.async.wait_group 0;" ::: "memory");
        __syncthreads();                 // visibility for stage it; all done with it-1
        if (it + 2 < GNIT) {
            int s = it + 2;
            uint32_t so = (uint32_t)(s % 3) * GSTG_B;
#pragma unroll
            for (int j = 0; j < 4; j++) {
                cpa16(dA + so + j * 512, gA + (size_t)s * 512 + j * 128);
                cpa16(dB + so + j * 256, gB + (size_t)s * 256 + j * 64);
            }
            CP_COMMIT();
        }

        const uint4* As4 = (const uint4*)(dsm + (it % 3) * (GSTG_B / 4));
        const uint2* Bs2 = (const uint2*)(dsm + (it % 3) * (GSTG_B / 4) + 4096);

#pragma unroll
        for (int kt = 0; kt < 4; kt++) {
            uint4 af[2];
#pragma unroll
            for (int i = 0; i < 2; i++)
                af[i] = As4[((wm * 2 + i) * 4 + kt) * 32 + lane];
            uint2 bf[8];
#pragma unroll
            for (int j = 0; j < 8; j++)
                bf[j] = Bs2[((wn * 8 + j) * 4 + kt) * 32 + lane];
#pragma unroll
            for (int i = 0; i < 2; i++)
#pragma unroll
                for (int j = 0; j < 8; j++)
                    mma8(acc[i][j], (const uint32_t*)&af[i], (const uint32_t*)&bf[j]);
        }
    }

    int c2 = (lane & 3) * 2;
#pragma unroll
    for (int i = 0; i < 2; i++) {
#pragma unroll
        for (int j = 0; j < 8; j++) {
            int row0 = m0 + wm * 32 + i * 16 + r;
            int col  = n0 + wn * 64 + j * 8 + c2;
            if (mode == 0) {
                *(float2*)&C[(size_t)row0 * DM + col] =
                    make_float2(acc[i][j][0], acc[i][j][1]);
                *(float2*)&C[(size_t)(row0 + 8) * DM + col] =
                    make_float2(acc[i][j][2], acc[i][j][3]);
            } else {
                int bx = row0 >> 11, s0 = row0 & 2047;
                int h = col >> 6, hd = col & 63;
                float* base = C + (size_t)(bx * Hh + h) * (Sq * HD);
                if (mode == 1) {
                    base[qfrag_off(s0, hd)]         = cf_tf32(acc[i][j][0]);
                    base[qfrag_off(s0, hd + 1)]     = cf_tf32(acc[i][j][1]);
                    base[qfrag_off(s0 + 8, hd)]     = cf_tf32(acc[i][j][2]);
                    base[qfrag_off(s0 + 8, hd + 1)] = cf_tf32(acc[i][j][3]);
                } else if (mode == 2) {
                    base[kfrag_off(s0, hd)]         = cf_tf32(acc[i][j][0]);
                    base[kfrag_off(s0, hd + 1)]     = cf_tf32(acc[i][j][1]);
                    base[kfrag_off(s0 + 8, hd)]     = cf_tf32(acc[i][j][2]);
                    base[kfrag_off(s0 + 8, hd + 1)] = cf_tf32(acc[i][j][3]);
                    if (s0 + 8 == Sq - 1)
                        *(float2*)&klast[bx * DM + col] = make_float2(acc[i][j][2], acc[i][j][3]);
                } else {
                    base[vfrag_off(s0, hd)]         = cf_tf32(acc[i][j][0]);
                    base[vfrag_off(s0, hd + 1)]     = cf_tf32(acc[i][j][1]);
                    base[vfrag_off(s0 + 8, hd)]     = cf_tf32(acc[i][j][2]);
                    base[vfrag_off(s0 + 8, hd + 1)] = cf_tf32(acc[i][j][3]);
                }
            }
        }
    }
}

__global__ void __launch_bounds__(256, 2) gemm_qkv(const float* __restrict__ A,
                                                   const float* __restrict__ WT,
                                                   float* q, float* k, float* v,
                                                   float* klast)
{
    extern __shared__ float dsm[];
    int z = blockIdx.z;
    float* C = (z == 0) ? q : (z == 1) ? k : v;
    gemm_body(A, WT + (size_t)z * DM * DM, C, z + 1, (z == 1) ? klast : (float*)0, dsm);
}

__global__ void __launch_bounds__(256, 2) gemm_o(const float* __restrict__ A,
                                                 const float* __restrict__ WT,
                                                 float* __restrict__ C)
{
    extern __shared__ float dsm[];
    gemm_body(A, WT, C, 0, (float*)0, dsm);
}

// ---------------- retrieval: sims (warp per event) ------------------------
__global__ __launch_bounds__(256) void retrieve_sims(const float* __restrict__ klast,
                                                     const float* __restrict__ events,
                                                     float* __restrict__ sims)
{
    int b = blockIdx.y;
    int tid = threadIdx.x;
    int lane = tid & 31, wid = tid >> 5;
    __shared__ float qs[DM];
    __shared__ float qn_s;

    for (int d = tid; d < DM; d += 256) qs[d] = klast[b * DM + d];
    __syncthreads();
    if (wid == 0) {
        float ps = 0.f;
        for (int d = lane * 4; d < DM; d += 128) {
            float4 t = *(const float4*)&qs[d];
            ps += t.x * t.x + t.y * t.y + t.z * t.z + t.w * t.w;
        }
#pragma unroll
        for (int off = 16; off > 0; off >>= 1) ps += __shfl_down_sync(0xffffffffu, ps, off);
        if (lane == 0) qn_s = sqrtf(ps) + 1e-8f;
    }
    __syncthreads();
    float qnorm = qn_s;

    int e = blockIdx.x * 8 + wid;
    if (e >= MEMN) return;
    const float* ep = events + (size_t)e * DM;
    float dot = 0.f, nn = 0.f;
    for (int d = lane * 4; d < DM; d += 128) {
        float4 ev = *(const float4*)(ep + d);
        float4 qv = *(const float4*)&qs[d];
        dot += qv.x * ev.x + qv.y * ev.y + qv.z * ev.z + qv.w * ev.w;
        nn  += ev.x * ev.x + ev.y * ev.y + ev.z * ev.z + ev.w * ev.w;
    }
#pragma unroll
    for (int off = 16; off > 0; off >>= 1) {
        dot += __shfl_down_sync(0xffffffffu, dot, off);
        nn  += __shfl_down_sync(0xffffffffu, nn, off);
    }
    if (lane == 0) sims[b * MEMN + e] = dot / (qnorm * (sqrtf(nn) + 1e-8f));
}

// ---------------- retrieval: parallel top-k + gather (tf32-rounded) --------
__global__ __launch_bounds__(256) void topk_gather(const float* __restrict__ sims,
                                                   const float* __restrict__ events,
                                                   float* __restrict__ ret)
{
    int b = blockIdx.x;
    int tid = threadIdx.x;
    int lane = tid & 31, wid = tid >> 5;
    __shared__ float sv[MEMN];
    __shared__ float wmax[8];
    __shared__ int   widx[8];
    __shared__ int   tidx[KTOT];

    for (int e = tid; e < MEMN; e += 256) sv[e] = sims[b * MEMN + e];
    __syncthreads();

    for (int kk = 0; kk < KTOT; kk++) {
        float bm = -1e30f; int bi = MEMN;
        for (int e = tid; e < MEMN; e += 256) {
            float v = sv[e];
            if (v > bm || (v == bm && e < bi)) { bm = v; bi = e; }
        }
#pragma unroll
        for (int off = 16; off > 0; off >>= 1) {
            float om = __shfl_down_sync(0xffffffffu, bm, off);
            int   oi = __shfl_down_sync(0xffffffffu, bi, off);
            if (om > bm || (om == bm && oi < bi)) { bm = om; bi = oi; }
        }
        if (lane == 0) { wmax[wid] = bm; widx[wid] = bi; }
        __syncthreads();
        if (tid == 0) {
            float gm = wmax[0]; int gi = widx[0];
            for (int w = 1; w < 8; w++) {
                if (wmax[w] > gm || (wmax[w] == gm && widx[w] < gi)) { gm = wmax[w]; gi = widx[w]; }
            }
            tidx[kk] = gi;
            sv[gi] = -1e30f;
        }
        __syncthreads();
    }

    for (int kk = 0; kk < KTOT; kk++) {
        int src = tidx[kk];
        for (int d = tid; d < DM; d += 256)
            ret[((size_t)b * KTOT + kk) * DM + d] = cf_tf32(events[(size_t)src * DM + d]);
    }
}

// ---------------- flash v9: shfl P-transpose, no P smem --------------------
#define TKF    32
#define OFF_K2 0                          // 4 x 2048 floats
#define OFF_V2 8192                       // 4 x 2048
#define OFF_KM 16384                      // 1024 (mem K frag)
#define OFF_VM 17408                      // 1024 (mem V frag)
#define OFF_CB 18432                      // 128 (4 x 32 mask bias ring)
#define FSMEM_FLOATS (OFF_CB + 128)
#define FSMEM_BYTES  (FSMEM_FLOATS * 4)

// transpose exp'd P from C-fragment layout to A-fragment layout via shfl
#define P_TRANSPOSE(ap, p0, p1, p2, p3, lane, cc) do {                        \
    int _srcA = ((lane) & ~3) | ((cc) >> 1);                                  \
    float _v00 = __shfl_sync(0xffffffffu, (p0), _srcA);                       \
    float _v01 = __shfl_sync(0xffffffffu, (p1), _srcA);                       \
    float _v10 = __shfl_sync(0xffffffffu, (p2), _srcA);                       \
    float _v11 = __shfl_sync(0xffffffffu, (p3), _srcA);                       \
    float _w00 = __shfl_sync(0xffffffffu, (p0), _srcA + 2);                   \
    float _w01 = __shfl_sync(0xffffffffu, (p1), _srcA + 2);                   \
    float _w10 = __shfl_sync(0xffffffffu, (p2), _srcA + 2);                   \
    float _w11 = __shfl_sync(0xffffffffu, (p3), _srcA + 2);                   \
    int _odd = (cc) & 1;                                                      \
    (ap)[0] = __float_as_uint(_odd ? _v01 : _v00);                            \
    (ap)[1] = __float_as_uint(_odd ? _v11 : _v10);                            \
    (ap)[2] = __float_as_uint(_odd ? _w01 : _w00);                            \
    (ap)[3] = __float_as_uint(_odd ? _w11 : _w10);                            \
} while (0)

__global__ void __launch_bounds__(256, 2) flash_mma(const float* __restrict__ amask,
                                                    const float* __restrict__ qbuf,
                                                    const float* __restrict__ kbuf,
                                                    const float* __restrict__ vbuf,
                                                    const float* __restrict__ ret,
                                                    float* __restrict__ att)
{
    extern __shared__ float fsm[];
    float* Km = fsm + OFF_KM;
    float* Vm = fsm + OFF_VM;
    float* CB = fsm + OFF_CB;
    uint32_t sbase = smem_u32(fsm);

    int qt = gridDim.x - 1 - blockIdx.x;   // heavy tiles first
    int h = blockIdx.y, b = blockIdx.z;
    int tid = threadIdx.x;
    int lane = tid & 31, w = tid >> 5;
    int r = lane >> 2, cc = lane & 3;
    int i0 = qt * 128;
    const float scale = 0.125f;
    float slope = exp2f(-0.5f * (float)(h + 1));

    const float* qfb = qbuf + (size_t)(b * Hh + h) * (Sq * HD) + (size_t)qt * 8192;
    const float* kfb = kbuf + (size_t)(b * Hh + h) * (Sq * HD);
    const float* vfb = vbuf + (size_t)(b * Hh + h) * (Sq * HD);

    int ntiles = 4 * qt + 4;

    // ---- prologue: stage K/V tiles 0..2 ----
    uint32_t dK0 = sbase + (uint32_t)(OFF_K2 + tid * 8) * 4u;
    uint32_t dV0 = sbase + (uint32_t)(OFF_V2 + tid * 8) * 4u;
#pragma unroll
    for (int s = 0; s < 3; s++) {
        const float* kp = kfb + s * 2048 + tid * 8;
        const float* vp = vfb + s * 2048 + tid * 8;
        uint32_t dK = dK0 + (uint32_t)(s * 2048) * 4u;
        uint32_t dV = dV0 + (uint32_t)(s * 2048) * 4u;
        cpa16(dK, kp);      cpa16(dK + 16, kp + 4);
        cpa16(dV, vp);      cpa16(dV + 16, vp + 4);
        CP_COMMIT();
    }
    if (tid < 96) CB[tid] = (1.0f - amask[b * Sq + tid]) * (-1e9f);

    // ---- Q fragments into registers ----
    uint4 aq[8];
    {
        const uint4* qg = (const uint4*)qfb;
#pragma unroll
        for (int ks = 0; ks < 8; ks++) aq[ks] = qg[(w * 8 + ks) * 32 + lane];
    }

    // ---- memory tile (10 keys + 6 pad) into frag-major side buffers ----
    if (tid < 128) {
        int kk = tid >> 3, dseg = (tid & 7) * 8;
        const float* rp = ret + ((size_t)b * KTOT + kk) * DM + h * HD + dseg;
        int ktile = kk >> 3, dt = dseg >> 3;
#pragma unroll
        for (int i = 0; i < 8; i++) {
            int d = dseg + i;
            float vv = (kk < KTOT) ? rp[i] : 0.f;
            Km[((ktile * 8 + dt) * 32 + (kk & 7) * 4 + (d & 3)) * 2 + ((d >> 2) & 1)] = vv;
            Vm[((dt * 2 + ktile) * 32 + (d & 7) * 4 + (kk & 3)) * 2 + ((kk >> 2) & 1)] = vv;
        }
    }
    __syncthreads();

    int row_lo = w * 16 + r;
    int ig_lo = i0 + row_lo, ig_hi = ig_lo + 8;

    const uint2* Km2 = (const uint2*)(fsm + OFF_KM);
    const uint2* Vm2 = (const uint2*)(fsm + OFF_VM);

    float of[8][4];
#pragma unroll
    for (int f = 0; f < 8; f++)
#pragma unroll
        for (int e = 0; e < 4; e++) of[f][e] = 0.f;
    float m_lo = -1e30f, m_hi = -1e30f, l_lo = 0.f, l_hi = 0.f;

    // ================= memory pass (16 cols) =================
    {
        float sc[2][4];
#pragma unroll
        for (int f = 0; f < 2; f++)
#pragma unroll
            for (int e = 0; e < 4; e++) sc[f][e] = 0.f;
#pragma unroll
        for (int ks = 0; ks < 8; ks++) {
#pragma unroll
            for (int f = 0; f < 2; f++) {
                uint2 bb = Km2[(f * 8 + ks) * 32 + lane];
                mma8(sc[f], (const uint32_t*)&aq[ks], (const uint32_t*)&bb);
            }
        }
        float tl = m_lo, th = m_hi;
#pragma unroll
        for (int f = 0; f < 2; f++) {
            int c0 = f * 8 + 2 * cc;
            float cb0  = (c0 < KTOT) ? 0.f : -1e30f;
            float cb1v = ((c0 + 1) < KTOT) ? 0.f : -1e30f;
            sc[f][0] = fmaf(sc[f][0], scale, cb0);
            sc[f][1] = fmaf(sc[f][1], scale, cb1v);
            sc[f][2] = fmaf(sc[f][2], scale, cb0);
            sc[f][3] = fmaf(sc[f][3], scale, cb1v);
            tl = fmaxf(tl, fmaxf(sc[f][0], sc[f][1]));
            th = fmaxf(th, fmaxf(sc[f][2], sc[f][3]));
        }
        tl = fmaxf(tl, __shfl_xor_sync(0xffffffffu, tl, 1));
        tl = fmaxf(tl, __shfl_xor_sync(0xffffffffu, tl, 2));
        th = fmaxf(th, __shfl_xor_sync(0xffffffffu, th, 1));
        th = fmaxf(th, __shfl_xor_sync(0xffffffffu, th, 2));
        float corr_lo = __expf(m_lo - tl), corr_hi = __expf(m_hi - th);
        l_lo *= corr_lo; l_hi *= corr_hi;
        m_lo = tl; m_hi = th;
        float sl = 0.f, sh = 0.f;
#pragma unroll
        for (int f = 0; f < 2; f++) {
            sc[f][0] = __expf(sc[f][0] - m_lo); sl += sc[f][0];
            sc[f][1] = __expf(sc[f][1] - m_lo); sl += sc[f][1];
            sc[f][2] = __expf(sc[f][2] - m_hi); sh += sc[f][2];
            sc[f][3] = __expf(sc[f][3] - m_hi); sh += sc[f][3];
        }
        sl += __shfl_xor_sync(0xffffffffu, sl, 1);
        sl += __shfl_xor_sync(0xffffffffu, sl, 2);
        sh += __shfl_xor_sync(0xffffffffu, sh, 1);
        sh += __shfl_xor_sync(0xffffffffu, sh, 2);
        l_lo += sl; l_hi += sh;
#pragma unroll
        for (int f = 0; f < 8; f++) {
            of[f][0] *= corr_lo; of[f][1] *= corr_lo;
            of[f][2] *= corr_hi; of[f][3] *= corr_hi;
        }
#pragma unroll
        for (int ks = 0; ks < 2; ks++) {
            float p0 = cf_tf32(sc[ks][0]), p1 = cf_tf32(sc[ks][1]);
            float p2 = cf_tf32(sc[ks][2]), p3 = cf_tf32(sc[ks][3]);
            uint32_t ap[4];
            P_TRANSPOSE(ap, p0, p1, p2, p3, lane, cc);
#pragma unroll
            for (int f = 0; f < 8; f++) {
                uint2 bv = Vm2[(f * 2 + ks) * 32 + lane];
                mma8(of[f], ap, (const uint32_t*)&bv);
            }
        }
    }

    // ================= seq tiles (quad-buffered, prefetch depth 2) ==========
    for (int t = 0; t < ntiles; ++t) {
        int buf = t & 3;
        int j0 = t * TKF;
        asm volatile("cp.async.wait_group 2;" ::: "memory");
        __syncthreads();
        if (t + 3 < ntiles) {
            int tn = t + 3, bufn = tn & 3;
            const float* kp = kfb + (size_t)tn * 2048 + tid * 8;
            const float* vp = vfb + (size_t)tn * 2048 + tid * 8;
            uint32_t dK = dK0 + (uint32_t)(bufn * 2048) * 4u;
            uint32_t dV = dV0 + (uint32_t)(bufn * 2048) * 4u;
            cpa16(dK, kp);      cpa16(dK + 16, kp + 4);
            cpa16(dV, vp);      cpa16(dV + 16, vp + 4);
            CP_COMMIT();
            if (tid < TKF)
                CB[bufn * 32 + tid] = (1.0f - amask[b * Sq + tn * TKF + tid]) * (-1e9f);
        }
        const uint2* Ks2 = (const uint2*)(fsm + OFF_K2) + buf * 1024;
        const uint2* Vs2 = (const uint2*)(fsm + OFF_V2) + buf * 1024;
        const float* cb = CB + buf * 32;

        float sc[4][4];
#pragma unroll
        for (int f = 0; f < 4; f++)
#pragma unroll
            for (int e = 0; e < 4; e++) sc[f][e] = 0.f;
#pragma unroll
        for (int ks = 0; ks < 8; ks++) {
#pragma unroll
            for (int f = 0; f < 4; f++) {
                uint2 bb = Ks2[(f * 8 + ks) * 32 + lane];
                mma8(sc[f], (const uint32_t*)&aq[ks], (const uint32_t*)&bb);
            }
        }

        bool causal = (t >= 4 * qt);
        float o0f = (float)(2 * cc);
        float tl = m_lo, th = m_hi;
#pragma unroll
        for (int f = 0; f < 4; f++) {
            int c0 = f * 8 + 2 * cc;
            float cb0 = cb[c0], cb1v = cb[c0 + 1];
            float fl = (float)(ig_lo - j0 - f * 8);
            float s00 = fmaf(sc[f][0], scale, fmaf(slope, fl - o0f, cb0));
            float s01 = fmaf(sc[f][1], scale, fmaf(slope, fl - o0f - 1.0f, cb1v));
            float s10 = fmaf(sc[f][2], scale, fmaf(slope, fl + 8.0f - o0f, cb0));
            float s11 = fmaf(sc[f][3], scale, fmaf(slope, fl + 8.0f - o0f - 1.0f, cb1v));
            if (causal) {
                int jg0 = j0 + c0;
                if (jg0 > ig_lo)     s00 = -1e30f;
                if (jg0 + 1 > ig_lo) s01 = -1e30f;
                if (jg0 > ig_hi)     s10 = -1e30f;
                if (jg0 + 1 > ig_hi) s11 = -1e30f;
            }
            sc[f][0] = s00; sc[f][1] = s01; sc[f][2] = s10; sc[f][3] = s11;
            tl = fmaxf(tl, fmaxf(s00, s01));
            th = fmaxf(th, fmaxf(s10, s11));
        }
        tl = fmaxf(tl, __shfl_xor_sync(0xffffffffu, tl, 1));
        tl = fmaxf(tl, __shfl_xor_sync(0xffffffffu, tl, 2));
        th = fmaxf(th, __shfl_xor_sync(0xffffffffu, th, 1));
        th = fmaxf(th, __shfl_xor_sync(0xffffffffu, th, 2));

        float corr_lo = __expf(m_lo - tl), corr_hi = __expf(m_hi - th);
        l_lo *= corr_lo; l_hi *= corr_hi;
        m_lo = tl; m_hi = th;

        float sl = 0.f, sh = 0.f;
#pragma unroll
        for (int f = 0; f < 4; f++) {
            sc[f][0] = __expf(sc[f][0] - m_lo); sl += sc[f][0];
            sc[f][1] = __expf(sc[f][1] - m_lo); sl += sc[f][1];
            sc[f][2] = __expf(sc[f][2] - m_hi); sh += sc[f][2];
            sc[f][3] = __expf(sc[f][3] - m_hi); sh += sc[f][3];
        }
        sl += __shfl_xor_sync(0xffffffffu, sl, 1);
        sl += __shfl_xor_sync(0xffffffffu, sl, 2);
        sh += __shfl_xor_sync(0xffffffffu, sh, 1);
        sh += __shfl_xor_sync(0xffffffffu, sh, 2);
        l_lo += sl; l_hi += sh;

#pragma unroll
        for (int f = 0; f < 8; f++) {
            of[f][0] *= corr_lo; of[f][1] *= corr_lo;
            of[f][2] *= corr_hi; of[f][3] *= corr_hi;
        }

#pragma unroll
        for (int ks = 0; ks < 4; ks++) {
            float p0 = cf_tf32(sc[ks][0]), p1 = cf_tf32(sc[ks][1]);
            float p2 = cf_tf32(sc[ks][2]), p3 = cf_tf32(sc[ks][3]);
            uint32_t ap[4];
            P_TRANSPOSE(ap, p0, p1, p2, p3, lane, cc);
#pragma unroll
            for (int f = 0; f < 8; f++) {
                uint2 bv = Vs2[(f * 4 + ks) * 32 + lane];
                mma8(of[f], ap, (const uint32_t*)&bv);
            }
        }
    }

    // ---- finalize: divide by l, tf32-round, store A-frag-major for gemm_o ----
    float inv_lo = 1.0f / l_lo, inv_hi = 1.0f / l_hi;
    int mlo = b * Sq + ig_lo, mhi = b * Sq + ig_hi;
#pragma unroll
    for (int f = 0; f < 8; f++) {
        int k0 = h * HD + f * 8 + 2 * cc;
        att[fragidxA(mlo, k0)]     = cf_tf32(of[f][0] * inv_lo);
        att[fragidxA(mlo, k0 + 1)] = cf_tf32(of[f][1] * inv_lo);
        att[fragidxA(mhi, k0)]     = cf_tf32(of[f][2] * inv_hi);
        att[fragidxA(mhi, k0 + 1)] = cf_tf32(of[f][3] * inv_hi);
    }
}

// ---------------- launcher ----------------
extern "C" void kernel_launch(void* const* d_in, const int* in_sizes, int n_in,
                              void* d_out, int out_size)
{
    const float* inputs = (const float*)d_in[0];
    const float* amask  = (const float*)d_in[1];
    const float* Wq     = (const float*)d_in[2];
    const float* Wk     = (const float*)d_in[3];
    const float* Wv     = (const float*)d_in[4];
    const float* Wo     = (const float*)d_in[5];
    const float* events = (const float*)d_in[6];
    float* out = (float*)d_out;

    float *q, *k, *v, *att, *ret, *sims, *wt, *ai, *klast;
    cudaGetSymbolAddress((void**)&q,     g_q);
    cudaGetSymbolAddress((void**)&k,     g_k);
    cudaGetSymbolAddress((void**)&v,     g_v);
    cudaGetSymbolAddress((void**)&att,   g_att);
    cudaGetSymbolAddress((void**)&ret,   g_ret);
    cudaGetSymbolAddress((void**)&sims,  g_sims);
    cudaGetSymbolAddress((void**)&wt,    g_wt);
    cudaGetSymbolAddress((void**)&ai,    g_ai);
    cudaGetSymbolAddress((void**)&klast, g_klast);

    cudaFuncSetAttribute(gemm_qkv,  cudaFuncAttributeMaxDynamicSharedMemorySize, GSMEM_BYTES);
    cudaFuncSetAttribute(gemm_o,    cudaFuncAttributeMaxDynamicSharedMemorySize, GSMEM_BYTES);
    cudaFuncSetAttribute(flash_mma, cudaFuncAttributeMaxDynamicSharedMemorySize, FSMEM_BYTES);

    prep_a<<<(Bq * Sq / 16) * (DM / 8) * 32 / 256, 256>>>(inputs, ai);
    transpose_w<<<dim3(32, 32, 4), 256>>>(Wq, Wk, Wv, Wo, wt);

    gemm_qkv<<<dim3(8, 32, 3), 256, GSMEM_BYTES>>>(ai, wt, q, k, v, klast);

    retrieve_sims<<<dim3(125, Bq), 256>>>(klast, events, sims);
    topk_gather<<<Bq, 256>>>(sims, events, ret);

    flash_mma<<<dim3(Sq / 128, Hh, Bq), 256, FSMEM_BYTES>>>(amask, q, k, v, ret, att);

    gemm_o<<<dim3(8, 32), 256, GSMEM_BYTES>>>(att, wt + 3 * (size_t)DM * DM, out);
}

// round 14
// speedup vs baseline: 4.7187x; 1.6181x over previous
#include <cuda_runtime.h>
#include <cuda_fp16.h>
#include <math.h>
#include <stdint.h>

// Problem constants
#define Bq   2
#define Sq   2048
#define DM   1024
#define Hh   16
#define HD   64
#define MEMN 1000
#define KTOT 10

// ---------------- device scratch (fp16 frag-major operands) ----------------
__device__ unsigned short g_q[Bq * Hh * Sq * HD];    // A-frag fp16 per (b,h,qtile)
__device__ unsigned short g_k[Bq * Hh * Sq * HD];    // QK B-frag fp16 per (b,h)
__device__ unsigned short g_v[Bq * Hh * Sq * HD];    // PV B-frag fp16 per (b,h)
__device__ unsigned short g_att[Bq * Sq * DM];       // A-frag fp16 (flash -> gemm_o)
__device__ unsigned short g_wt[4 * DM * DM];         // B-frag fp16 weights
__device__ unsigned short g_ai[Bq * Sq * DM];        // A-frag fp16 inputs
__device__ float g_ret[Bq * KTOT * DM];
__device__ float g_sims[Bq * MEMN];
__device__ float g_klast[Bq * DM];                   // UNROUNDED last-token key

// ---------------- helpers ----------------
__device__ __forceinline__ uint32_t smem_u32(const void* p) {
    uint32_t a;
    asm("{ .reg .u64 t; cvta.to.shared.u64 t, %1; cvt.u32.u64 %0, t; }" : "=r"(a) : "l"(p));
    return a;
}
__device__ __forceinline__ uint32_t pkh2(float lo, float hi) {
    __half2 h = __floats2half2_rn(lo, hi);
    return *(uint32_t*)&h;
}
__device__ __forceinline__ void mma16(float* c, const uint32_t* a, const uint32_t* b) {
    asm("mma.sync.aligned.m16n8k16.row.col.f32.f16.f16.f32 "
        "{%0,%1,%2,%3},{%4,%5,%6,%7},{%8,%9},{%0,%1,%2,%3};"
        : "+f"(c[0]), "+f"(c[1]), "+f"(c[2]), "+f"(c[3])
        : "r"(a[0]), "r"(a[1]), "r"(a[2]), "r"(a[3]), "r"(b[0]), "r"(b[1]));
}
__device__ __forceinline__ void cpa16(uint32_t d, const void* g) {
    asm volatile("cp.async.cg.shared.global [%0], [%1], 16;" :: "r"(d), "l"(g) : "memory");
}
#define CP_COMMIT() asm volatile("cp.async.commit_group;" ::: "memory")

// V PV-B-frag half index for (key s, dim d) within one (b,h)
__device__ __forceinline__ size_t vfrag16(int s, int d) {
    return ((((size_t)(s >> 4) * 8 + (d >> 3)) * 32 + (d & 7) * 4 + ((s & 7) >> 1)) * 2
            + ((s >> 3) & 1)) * 2 + (s & 1);
}

// ---------------- prep: fp32 inputs -> fp16 A-frag-major -------------------
__global__ __launch_bounds__(256) void prep_a(const float* __restrict__ A,
                                              unsigned short* __restrict__ D)
{
    int gt = blockIdx.x * 256 + threadIdx.x;      // (tile, lane)
    int tile = gt >> 5, lane = gt & 31;
    int mt = tile >> 6, kt = tile & 63;
    int m = mt * 16 + (lane >> 2), k = kt * 16 + (lane & 3) * 2;
    float2 a0 = *(const float2*)&A[(size_t)m * DM + k];
    float2 a1 = *(const float2*)&A[(size_t)(m + 8) * DM + k];
    float2 a2 = *(const float2*)&A[(size_t)m * DM + k + 8];
    float2 a3 = *(const float2*)&A[(size_t)(m + 8) * DM + k + 8];
    uint4 o;
    o.x = pkh2(a0.x, a0.y);
    o.y = pkh2(a1.x, a1.y);
    o.z = pkh2(a2.x, a2.y);
    o.w = pkh2(a3.x, a3.y);
    ((uint4*)D)[gt] = o;
}

// ---------------- weights -> fp16 B-frag-major -----------------------------
__global__ __launch_bounds__(256) void transpose_w(const float* __restrict__ W0,
                                                   const float* __restrict__ W1,
                                                   const float* __restrict__ W2,
                                                   const float* __restrict__ W3,
                                                   unsigned short* __restrict__ WT)
{
    __shared__ float t[32][33];
    int z = blockIdx.z;
    const float* W = (z == 0) ? W0 : (z == 1) ? W1 : (z == 2) ? W2 : W3;
    unsigned short* D = WT + (size_t)z * DM * DM;
    int x = blockIdx.x * 32, y = blockIdx.y * 32;   // x = n0, y = k0
    int tid = threadIdx.x;
    int tx = tid & 31, ty = tid >> 5;
    for (int rr = ty; rr < 32; rr += 8)
        t[rr][tx] = W[(size_t)(y + rr) * DM + x + tx];   // t[k_local][n_local]
    __syncthreads();
    int nt_l = tid >> 6, kt_l = (tid >> 5) & 1, lane = tid & 31;
    int r = lane >> 2, cc = lane & 3;
    int n_l = nt_l * 8 + r;
    int kb = kt_l * 16 + 2 * cc;
    uint2 o;
    o.x = pkh2(t[kb][n_l],     t[kb + 1][n_l]);
    o.y = pkh2(t[kb + 8][n_l], t[kb + 9][n_l]);
    ((uint2*)D)[(((size_t)(x >> 3) + nt_l) * 64 + (y >> 4) + kt_l) * 32 + lane] = o;
}

// ---------------- fp16 frag-major cp.async mma.sync GEMM -------------------
// tile 128x128, K-slab 32 (2 k-instructions), 3 stages x 16KB
#define GNIT   (DM / 32)          // 32
#define GSTG_B 16384
#define GSMEM_BYTES (3 * GSTG_B)

// mode: 0 = fp32 row-major out (gemm_o), 1 = Q frag, 2 = K frag (+klast), 3 = V frag
__device__ __forceinline__ void gemm_body(const unsigned short* __restrict__ A16,
                                          const unsigned short* __restrict__ W16,
                                          void* __restrict__ Cout,
                                          int mode, float* klast, float* dsm)
{
    uint32_t sbase = smem_u32(dsm);
    int tid = threadIdx.x, lane = tid & 31, wid = tid >> 5;
    int wm = wid & 3, wn = wid >> 2;
    int m0 = blockIdx.y * 128, n0 = blockIdx.x * 128;
    int r = lane >> 2;

    int ca = tid >> 5, ua = tid & 31;
    int cbk = tid >> 4, ub = tid & 15;
    const char* gA = (const char*)A16 + ((size_t)((m0 >> 4) + ca) * 64) * 512 + (size_t)ua * 32;
    const char* gB = (const char*)W16 + ((size_t)((n0 >> 3) + cbk) * 64) * 256 + (size_t)ub * 32;
    uint32_t dA = sbase + (uint32_t)(ca * 1024 + ua * 32);
    uint32_t dB = sbase + 8192u + (uint32_t)(cbk * 512 + ub * 32);

    float acc[2][8][4];
#pragma unroll
    for (int i = 0; i < 2; i++)
#pragma unroll
        for (int j = 0; j < 8; j++)
#pragma unroll
            for (int t = 0; t < 4; t++) acc[i][j][t] = 0.f;

#pragma unroll
    for (int s = 0; s < 2; s++) {
        uint32_t so = (uint32_t)s * GSTG_B;
        cpa16(dA + so,      gA + (size_t)s * 1024);
        cpa16(dA + so + 16, gA + (size_t)s * 1024 + 16);
        cpa16(dB + so,      gB + (size_t)s * 512);
        cpa16(dB + so + 16, gB + (size_t)s * 512 + 16);
        CP_COMMIT();
    }

    for (int it = 0; it < GNIT; ++it) {
        if (it + 1 < GNIT) asm volatile("cp.async.wait_group 1;" ::: "memory");
        else               asm volatile("cp.async.wait_group 0;" ::: "memory");
        __syncthreads();
        if (it + 2 < GNIT) {
            int s = it + 2;
            uint32_t so = (uint32_t)(s % 3) * GSTG_B;
            cpa16(dA + so,      gA + (size_t)s * 1024);
            cpa16(dA + so + 16, gA + (size_t)s * 1024 + 16);
            cpa16(dB + so,      gB + (size_t)s * 512);
            cpa16(dB + so + 16, gB + (size_t)s * 512 + 16);
            CP_COMMIT();
        }

        const uint4* As4 = (const uint4*)((char*)dsm + (it % 3) * GSTG_B);
        const uint2* Bs2 = (const uint2*)((char*)dsm + (it % 3) * GSTG_B + 8192);

#pragma unroll
        for (int ktl = 0; ktl < 2; ktl++) {
            uint4 af[2];
#pragma unroll
            for (int i = 0; i < 2; i++)
                af[i] = As4[((wm * 2 + i) * 2 + ktl) * 32 + lane];
            uint2 bf[8];
#pragma unroll
            for (int j = 0; j < 8; j++)
                bf[j] = Bs2[((wn * 8 + j) * 2 + ktl) * 32 + lane];
#pragma unroll
            for (int i = 0; i < 2; i++)
#pragma unroll
                for (int j = 0; j < 8; j++)
                    mma16(acc[i][j], (const uint32_t*)&af[i], (const uint32_t*)&bf[j]);
        }
    }

    int c2 = (lane & 3) * 2;
#pragma unroll
    for (int i = 0; i < 2; i++) {
#pragma unroll
        for (int j = 0; j < 8; j++) {
            int row0 = m0 + wm * 32 + i * 16 + r;
            int col  = n0 + wn * 64 + j * 8 + c2;
            float a0 = acc[i][j][0], a1 = acc[i][j][1];
            float a2 = acc[i][j][2], a3 = acc[i][j][3];
            if (mode == 0) {
                float* C = (float*)Cout;
                *(float2*)&C[(size_t)row0 * DM + col]       = make_float2(a0, a1);
                *(float2*)&C[(size_t)(row0 + 8) * DM + col] = make_float2(a2, a3);
            } else {
                int bx = row0 >> 11, s0 = row0 & 2047;
                int h = col >> 6, hd = col & 63;
                unsigned short* base = (unsigned short*)Cout + (size_t)(bx * Hh + h) * (Sq * HD);
                if (mode == 1) {
                    uint32_t* qh = (uint32_t*)base;
                    size_t qi = (((size_t)(s0 >> 4) * 4 + (hd >> 4)) * 32 + lane) * 4
                              + ((hd >> 3) & 1) * 2;
                    qh[qi]     = pkh2(a0, a1);
                    qh[qi + 1] = pkh2(a2, a3);
                } else if (mode == 2) {
                    uint32_t* kh = (uint32_t*)base;
                    int e = (hd >> 3) & 1;
                    kh[(((size_t)(s0 >> 3) * 4 + (hd >> 4)) * 32 + lane) * 2 + e] = pkh2(a0, a1);
                    kh[((((size_t)(s0 >> 3) + 1) * 4 + (hd >> 4)) * 32 + lane) * 2 + e] = pkh2(a2, a3);
                    if (klast && s0 + 8 == Sq - 1)
                        *(float2*)&klast[bx * DM + col] = make_float2(a2, a3);
                } else {
                    base[vfrag16(s0, col & 63)]         = __half_as_ushort(__float2half_rn(a0));
                    base[vfrag16(s0, (col & 63) + 1)]   = __half_as_ushort(__float2half_rn(a1));
                    base[vfrag16(s0 + 8, col & 63)]     = __half_as_ushort(__float2half_rn(a2));
                    base[vfrag16(s0 + 8, (col & 63) + 1)] = __half_as_ushort(__float2half_rn(a3));
                }
            }
        }
    }
}

__global__ void __launch_bounds__(256, 2) gemm_qkv(const unsigned short* __restrict__ A,
                                                   const unsigned short* __restrict__ WT,
                                                   unsigned short* q, unsigned short* k,
                                                   unsigned short* v, float* klast)
{
    extern __shared__ float dsm[];
    int z = blockIdx.z;
    unsigned short* C = (z == 0) ? q : (z == 1) ? k : v;
    gemm_body(A, WT + (size_t)z * DM * DM, C, z + 1, (z == 1) ? klast : (float*)0, dsm);
}

__global__ void __launch_bounds__(256, 2) gemm_o(const unsigned short* __restrict__ A,
                                                 const unsigned short* __restrict__ WT,
                                                 float* __restrict__ C)
{
    extern __shared__ float dsm[];
    gemm_body(A, WT, C, 0, (float*)0, dsm);
}

// ---------------- retrieval: sims (warp per event) ------------------------
__global__ __launch_bounds__(256) void retrieve_sims(const float* __restrict__ klast,
                                                     const float* __restrict__ events,
                                                     float* __restrict__ sims)
{
    int b = blockIdx.y;
    int tid = threadIdx.x;
    int lane = tid & 31, wid = tid >> 5;
    __shared__ float qs[DM];
    __shared__ float qn_s;

    for (int d = tid; d < DM; d += 256) qs[d] = klast[b * DM + d];
    __syncthreads();
    if (wid == 0) {
        float ps = 0.f;
        for (int d = lane * 4; d < DM; d += 128) {
            float4 t = *(const float4*)&qs[d];
            ps += t.x * t.x + t.y * t.y + t.z * t.z + t.w * t.w;
        }
#pragma unroll
        for (int off = 16; off > 0; off >>= 1) ps += __shfl_down_sync(0xffffffffu, ps, off);
        if (lane == 0) qn_s = sqrtf(ps) + 1e-8f;
    }
    __syncthreads();
    float qnorm = qn_s;

    int e = blockIdx.x * 8 + wid;
    if (e >= MEMN) return;
    const float* ep = events + (size_t)e * DM;
    float dot = 0.f, nn = 0.f;
    for (int d = lane * 4; d < DM; d += 128) {
        float4 ev = *(const float4*)(ep + d);
        float4 qv = *(const float4*)&qs[d];
        dot += qv.x * ev.x + qv.y * ev.y + qv.z * ev.z + qv.w * ev.w;
        nn  += ev.x * ev.x + ev.y * ev.y + ev.z * ev.z + ev.w * ev.w;
    }
#pragma unroll
    for (int off = 16; off > 0; off >>= 1) {
        dot += __shfl_down_sync(0xffffffffu, dot, off);
        nn  += __shfl_down_sync(0xffffffffu, nn, off);
    }
    if (lane == 0) sims[b * MEMN + e] = dot / (qnorm * (sqrtf(nn) + 1e-8f));
}

// ---------------- retrieval: parallel top-k + gather (raw fp32) ------------
__global__ __launch_bounds__(256) void topk_gather(const float* __restrict__ sims,
                                                   const float* __restrict__ events,
                                                   float* __restrict__ ret)
{
    int b = blockIdx.x;
    int tid = threadIdx.x;
    int lane = tid & 31, wid = tid >> 5;
    __shared__ float sv[MEMN];
    __shared__ float wmax[8];
    __shared__ int   widx[8];
    __shared__ int   tidx[KTOT];

    for (int e = tid; e < MEMN; e += 256) sv[e] = sims[b * MEMN + e];
    __syncthreads();

    for (int kk = 0; kk < KTOT; kk++) {
        float bm = -1e30f; int bi = MEMN;
        for (int e = tid; e < MEMN; e += 256) {
            float v = sv[e];
            if (v > bm || (v == bm && e < bi)) { bm = v; bi = e; }
        }
#pragma unroll
        for (int off = 16; off > 0; off >>= 1) {
            float om = __shfl_down_sync(0xffffffffu, bm, off);
            int   oi = __shfl_down_sync(0xffffffffu, bi, off);
            if (om > bm || (om == bm && oi < bi)) { bm = om; bi = oi; }
        }
        if (lane == 0) { wmax[wid] = bm; widx[wid] = bi; }
        __syncthreads();
        if (tid == 0) {
            float gm = wmax[0]; int gi = widx[0];
            for (int w = 1; w < 8; w++) {
                if (wmax[w] > gm || (wmax[w] == gm && widx[w] < gi)) { gm = wmax[w]; gi = widx[w]; }
            }
            tidx[kk] = gi;
            sv[gi] = -1e30f;
        }
        __syncthreads();
    }

    for (int kk = 0; kk < KTOT; kk++) {
        int src = tidx[kk];
        for (int d = tid; d < DM; d += 256)
            ret[((size_t)b * KTOT + kk) * DM + d] = events[(size_t)src * DM + d];
    }
}

// ---------------- flash v10: fp16 mma, no-shuffle P reuse ------------------
#define TKF 32
// smem (bytes): K2 4x4KB | V2 4x4KB | Km 2KB | Vm 2KB | CB 512B
#define OFFB_K2 0
#define OFFB_V2 16384
#define OFFB_KM 32768
#define OFFB_VM 34816
#define OFFB_CB 36864
#define FSMEM_BYTES (OFFB_CB + 512)

__global__ void __launch_bounds__(256, 2) flash_mma(const float* __restrict__ amask,
                                                    const unsigned short* __restrict__ qh,
                                                    const unsigned short* __restrict__ kh,
                                                    const unsigned short* __restrict__ vh,
                                                    const float* __restrict__ ret,
                                                    unsigned short* __restrict__ att)
{
    extern __shared__ float fsm[];
    unsigned short* KmH = (unsigned short*)((char*)fsm + OFFB_KM);
    unsigned short* VmH = (unsigned short*)((char*)fsm + OFFB_VM);
    float* CB = (float*)((char*)fsm + OFFB_CB);
    uint32_t sbase = smem_u32(fsm);

    int qt = gridDim.x - 1 - blockIdx.x;   // heavy tiles first
    int h = blockIdx.y, b = blockIdx.z;
    int tid = threadIdx.x;
    int lane = tid & 31, w = tid >> 5;
    int r = lane >> 2, cc = lane & 3;
    int i0 = qt * 128;
    const float scale = 0.125f;
    float slope = exp2f(-0.5f * (float)(h + 1));

    const char* kbc = (const char*)(kh + (size_t)(b * Hh + h) * (Sq * HD));
    const char* vbc = (const char*)(vh + (size_t)(b * Hh + h) * (Sq * HD));

    int ntiles = 4 * qt + 4;

    // ---- prologue: stage K/V tiles 0..2 (4KB each, 1 cpa16/thread) ----
    uint32_t dK0 = sbase + OFFB_K2 + (uint32_t)tid * 16;
    uint32_t dV0 = sbase + OFFB_V2 + (uint32_t)tid * 16;
#pragma unroll
    for (int s = 0; s < 3; s++) {
        cpa16(dK0 + s * 4096, kbc + (size_t)s * 4096 + tid * 16);
        cpa16(dV0 + s * 4096, vbc + (size_t)s * 4096 + tid * 16);
        CP_COMMIT();
    }
    if (tid < 96) CB[tid] = (1.0f - amask[b * Sq + tid]) * (-1e9f);

    // ---- Q fragments into registers (coalesced from frag-major) ----
    uint4 aq[4];
    {
        const uint4* qg = (const uint4*)(qh + (size_t)(b * Hh + h) * (Sq * HD)
                                         + (size_t)qt * 8192);
#pragma unroll
        for (int kt = 0; kt < 4; kt++) aq[kt] = qg[(w * 4 + kt) * 32 + lane];
    }

    // ---- memory tile (10 keys + 6 pad) into fp16 frag side buffers ----
    if (tid < 128) {
        int kk = tid >> 3, dseg = (tid & 7) * 8;
        const float* rp = ret + ((size_t)b * KTOT + kk) * DM + h * HD + dseg;
#pragma unroll
        for (int i = 0; i < 8; i++) {
            int d = dseg + i;
            float vv = (kk < KTOT) ? rp[i] : 0.f;
            unsigned short hv = __half_as_ushort(__float2half_rn(vv));
            KmH[((((kk >> 3) * 4 + (d >> 4)) * 32 + (kk & 7) * 4 + ((d & 7) >> 1)) * 2
                 + ((d >> 3) & 1)) * 2 + (d & 1)] = hv;
            VmH[(((d >> 3) * 32 + (d & 7) * 4 + ((kk & 7) >> 1)) * 2
                 + ((kk >> 3) & 1)) * 2 + (kk & 1)] = hv;
        }
    }
    __syncthreads();

    int row_lo = w * 16 + r;
    int ig_lo = i0 + row_lo, ig_hi = ig_lo + 8;

    const uint2* Km2 = (const uint2*)((char*)fsm + OFFB_KM);
    const uint2* Vm2 = (const uint2*)((char*)fsm + OFFB_VM);

    float of[8][4];
#pragma unroll
    for (int f = 0; f < 8; f++)
#pragma unroll
        for (int e = 0; e < 4; e++) of[f][e] = 0.f;
    float m_lo = -1e30f, m_hi = -1e30f, l_lo = 0.f, l_hi = 0.f;

    // ================= memory pass (16 cols) =================
    {
        float sc[2][4];
#pragma unroll
        for (int f = 0; f < 2; f++)
#pragma unroll
            for (int e = 0; e < 4; e++) sc[f][e] = 0.f;
#pragma unroll
        for (int kt = 0; kt < 4; kt++) {
#pragma unroll
            for (int f = 0; f < 2; f++) {
                uint2 bb = Km2[(f * 4 + kt) * 32 + lane];
                mma16(sc[f], (const uint32_t*)&aq[kt], (const uint32_t*)&bb);
            }
        }
        float tl = m_lo, th = m_hi;
#pragma unroll
        for (int f = 0; f < 2; f++) {
            int c0 = f * 8 + 2 * cc;
            float cb0  = (c0 < KTOT) ? 0.f : -1e30f;
            float cb1v = ((c0 + 1) < KTOT) ? 0.f : -1e30f;
            sc[f][0] = fmaf(sc[f][0], scale, cb0);
            sc[f][1] = fmaf(sc[f][1], scale, cb1v);
            sc[f][2] = fmaf(sc[f][2], scale, cb0);
            sc[f][3] = fmaf(sc[f][3], scale, cb1v);
            tl = fmaxf(tl, fmaxf(sc[f][0], sc[f][1]));
            th = fmaxf(th, fmaxf(sc[f][2], sc[f][3]));
        }
        tl = fmaxf(tl, __shfl_xor_sync(0xffffffffu, tl, 1));
        tl = fmaxf(tl, __shfl_xor_sync(0xffffffffu, tl, 2));
        th = fmaxf(th, __shfl_xor_sync(0xffffffffu, th, 1));
        th = fmaxf(th, __shfl_xor_sync(0xffffffffu, th, 2));
        float corr_lo = __expf(m_lo - tl), corr_hi = __expf(m_hi - th);
        l_lo *= corr_lo; l_hi *= corr_hi;
        m_lo = tl; m_hi = th;
        float sl = 0.f, sh = 0.f;
#pragma unroll
        for (int f = 0; f < 2; f++) {
            sc[f][0] = __expf(sc[f][0] - m_lo); sl += sc[f][0];
            sc[f][1] = __expf(sc[f][1] - m_lo); sl += sc[f][1];
            sc[f][2] = __expf(sc[f][2] - m_hi); sh += sc[f][2];
            sc[f][3] = __expf(sc[f][3] - m_hi); sh += sc[f][3];
        }
        sl += __shfl_xor_sync(0xffffffffu, sl, 1);
        sl += __shfl_xor_sync(0xffffffffu, sl, 2);
        sh += __shfl_xor_sync(0xffffffffu, sh, 1);
        sh += __shfl_xor_sync(0xffffffffu, sh, 2);
        l_lo += sl; l_hi += sh;
#pragma unroll
        for (int f = 0; f < 8; f++) {
            of[f][0] *= corr_lo; of[f][1] *= corr_lo;
            of[f][2] *= corr_hi; of[f][3] *= corr_hi;
        }
        // P reuse: C-frag == A-frag layout in fp16; pack pairs, no shuffle
        uint32_t ap[4];
        ap[0] = pkh2(sc[0][0], sc[0][1]);
        ap[1] = pkh2(sc[0][2], sc[0][3]);
        ap[2] = pkh2(sc[1][0], sc[1][1]);
        ap[3] = pkh2(sc[1][2], sc[1][3]);
#pragma unroll
        for (int f = 0; f < 8; f++) {
            uint2 bv = Vm2[f * 32 + lane];
            mma16(of[f], ap, (const uint32_t*)&bv);
        }
    }

    // ================= seq tiles (quad-buffered, prefetch depth 2) ==========
    for (int t = 0; t < ntiles; ++t) {
        int buf = t & 3;
        int j0 = t * TKF;
        asm volatile("cp.async.wait_group 2;" ::: "memory");
        __syncthreads();
        if (t + 3 < ntiles) {
            int tn = t + 3, bufn = tn & 3;
            cpa16(dK0 + bufn * 4096, kbc + (size_t)tn * 4096 + tid * 16);
            cpa16(dV0 + bufn * 4096, vbc + (size_t)tn * 4096 + tid * 16);
            CP_COMMIT();
            if (tid < TKF)
                CB[bufn * 32 + tid] = (1.0f - amask[b * Sq + tn * TKF + tid]) * (-1e9f);
        }
        const uint2* Ks2 = (const uint2*)((char*)fsm + OFFB_K2 + buf * 4096);
        const uint2* Vs2 = (const uint2*)((char*)fsm + OFFB_V2 + buf * 4096);
        const float* cb = CB + buf * 32;

        float sc[4][4];
#pragma unroll
        for (int f = 0; f < 4; f++)
#pragma unroll
            for (int e = 0; e < 4; e++) sc[f][e] = 0.f;
#pragma unroll
        for (int kt = 0; kt < 4; kt++) {
#pragma unroll
            for (int f = 0; f < 4; f++) {
                uint2 bb = Ks2[(f * 4 + kt) * 32 + lane];
                mma16(sc[f], (const uint32_t*)&aq[kt], (const uint32_t*)&bb);
            }
        }

        bool causal = (t >= 4 * qt);
        float o0f = (float)(2 * cc);
        float tl = m_lo, th = m_hi;
#pragma unroll
        for (int f = 0; f < 4; f++) {
            int c0 = f * 8 + 2 * cc;
            float cb0 = cb[c0], cb1v = cb[c0 + 1];
            float fl = (float)(ig_lo - j0 - f * 8);
            float s00 = fmaf(sc[f][0], scale, fmaf(slope, fl - o0f, cb0));
            float s01 = fmaf(sc[f][1], scale, fmaf(slope, fl - o0f - 1.0f, cb1v));
            float s10 = fmaf(sc[f][2], scale, fmaf(slope, fl + 8.0f - o0f, cb0));
            float s11 = fmaf(sc[f][3], scale, fmaf(slope, fl + 8.0f - o0f - 1.0f, cb1v));
            if (causal) {
                int jg0 = j0 + c0;
                if (jg0 > ig_lo)     s00 = -1e30f;
                if (jg0 + 1 > ig_lo) s01 = -1e30f;
                if (jg0 > ig_hi)     s10 = -1e30f;
                if (jg0 + 1 > ig_hi) s11 = -1e30f;
            }
            sc[f][0] = s00; sc[f][1] = s01; sc[f][2] = s10; sc[f][3] = s11;
            tl = fmaxf(tl, fmaxf(s00, s01));
            th = fmaxf(th, fmaxf(s10, s11));
        }
        tl = fmaxf(tl, __shfl_xor_sync(0xffffffffu, tl, 1));
        tl = fmaxf(tl, __shfl_xor_sync(0xffffffffu, tl, 2));
        th = fmaxf(th, __shfl_xor_sync(0xffffffffu, th, 1));
        th = fmaxf(th, __shfl_xor_sync(0xffffffffu, th, 2));

        float corr_lo = __expf(m_lo - tl), corr_hi = __expf(m_hi - th);
        l_lo *= corr_lo; l_hi *= corr_hi;
        m_lo = tl; m_hi = th;

        float sl = 0.f, sh = 0.f;
#pragma unroll
        for (int f = 0; f < 4; f++) {
            sc[f][0] = __expf(sc[f][0] - m_lo); sl += sc[f][0];
            sc[f][1] = __expf(sc[f][1] - m_lo); sl += sc[f][1];
            sc[f][2] = __expf(sc[f][2] - m_hi); sh += sc[f][2];
            sc[f][3] = __expf(sc[f][3] - m_hi); sh += sc[f][3];
        }
        sl += __shfl_xor_sync(0xffffffffu, sl, 1);
        sl += __shfl_xor_sync(0xffffffffu, sl, 2);
        sh += __shfl_xor_sync(0xffffffffu, sh, 1);
        sh += __shfl_xor_sync(0xffffffffu, sh, 2);
        l_lo += sl; l_hi += sh;

#pragma unroll
        for (int f = 0; f < 8; f++) {
            of[f][0] *= corr_lo; of[f][1] *= corr_lo;
            of[f][2] *= corr_hi; of[f][3] *= corr_hi;
        }

        // P reuse: pack C-frags directly as fp16 A-frags
#pragma unroll
        for (int kt = 0; kt < 2; kt++) {
            uint32_t ap[4];
            ap[0] = pkh2(sc[2 * kt][0],     sc[2 * kt][1]);
            ap[1] = pkh2(sc[2 * kt][2],     sc[2 * kt][3]);
            ap[2] = pkh2(sc[2 * kt + 1][0], sc[2 * kt + 1][1]);
            ap[3] = pkh2(sc[2 * kt + 1][2], sc[2 * kt + 1][3]);
#pragma unroll
            for (int f = 0; f < 8; f++) {
                uint2 bv = Vs2[(kt * 8 + f) * 32 + lane];
                mma16(of[f], ap, (const uint32_t*)&bv);
            }
        }
    }

    // ---- finalize: divide by l, fp16 A-frag store for gemm_o ----
    float inv_lo = 1.0f / l_lo, inv_hi = 1.0f / l_hi;
    int mlo = b * Sq + ig_lo;
    uint32_t* atth = (uint32_t*)att;
#pragma unroll
    for (int f = 0; f < 8; f++) {
        int k0 = h * HD + f * 8 + 2 * cc;
        size_t ai = (((size_t)(mlo >> 4) * 64 + (k0 >> 4)) * 32 + lane) * 4
                  + ((k0 >> 3) & 1) * 2;
        atth[ai]     = pkh2(of[f][0] * inv_lo, of[f][1] * inv_lo);
        atth[ai + 1] = pkh2(of[f][2] * inv_hi, of[f][3] * inv_hi);
    }
}

// ---------------- launcher ----------------
extern "C" void kernel_launch(void* const* d_in, const int* in_sizes, int n_in,
                              void* d_out, int out_size)
{
    const float* inputs = (const float*)d_in[0];
    const float* amask  = (const float*)d_in[1];
    const float* Wq     = (const float*)d_in[2];
    const float* Wk     = (const float*)d_in[3];
    const float* Wv     = (const float*)d_in[4];
    const float* Wo     = (const float*)d_in[5];
    const float* events = (const float*)d_in[6];
    float* out = (float*)d_out;

    unsigned short *q, *k, *v, *att, *wt, *ai;
    float *ret, *sims, *klast;
    cudaGetSymbolAddress((void**)&q,     g_q);
    cudaGetSymbolAddress((void**)&k,     g_k);
    cudaGetSymbolAddress((void**)&v,     g_v);
    cudaGetSymbolAddress((void**)&att,   g_att);
    cudaGetSymbolAddress((void**)&ret,   g_ret);
    cudaGetSymbolAddress((void**)&sims,  g_sims);
    cudaGetSymbolAddress((void**)&wt,    g_wt);
    cudaGetSymbolAddress((void**)&ai,    g_ai);
    cudaGetSymbolAddress((void**)&klast, g_klast);

    cudaFuncSetAttribute(gemm_qkv,  cudaFuncAttributeMaxDynamicSharedMemorySize, GSMEM_BYTES);
    cudaFuncSetAttribute(gemm_o,    cudaFuncAttributeMaxDynamicSharedMemorySize, GSMEM_BYTES);
    cudaFuncSetAttribute(flash_mma, cudaFuncAttributeMaxDynamicSharedMemorySize, FSMEM_BYTES);

    prep_a<<<(Bq * Sq / 16) * (DM / 16) * 32 / 256, 256>>>(inputs, ai);
    transpose_w<<<dim3(32, 32, 4), 256>>>(Wq, Wk, Wv, Wo, wt);

    gemm_qkv<<<dim3(8, 32, 3), 256, GSMEM_BYTES>>>(ai, wt, q, k, v, klast);

    retrieve_sims<<<dim3(125, Bq), 256>>>(klast, events, sims);
    topk_gather<<<Bq, 256>>>(sims, events, ret);

    flash_mma<<<dim3(Sq / 128, Hh, Bq), 256, FSMEM_BYTES>>>(amask, q, k, v, ret, att);

    gemm_o<<<dim3(8, 32), 256, GSMEM_BYTES>>>(att, wt + 3 * (size_t)DM * DM, out);
}